// round 1
// baseline (speedup 1.0000x reference)
#include <cuda_runtime.h>
#include <math.h>

// ---------------- problem constants ----------------
#define DIMN 2048
#define HEADS 16
#define HD 128
#define RANKN 64
#define IMG_SEQ 2048
#define TXT_SEQ 128
#define SEQN 2176          // IMG_SEQ + TXT_SEQ
#define CONDN 1024
#define BLOCKN 1024        // IMG_SEQ - COND
#define SBSN 1152          // SEQ - COND
#define EPSV 1e-5f

// ---------------- device scratch (no allocation allowed) ----------------
__device__ float g_Q[SEQN * DIMN];
__device__ float g_K[SEQN * DIMN];
__device__ float g_V[SEQN * DIMN];
__device__ float g_O[SEQN * DIMN];
__device__ float g_Hi[IMG_SEQ * DIMN];
__device__ float g_Lq[CONDN * RANKN];
__device__ float g_Lk[CONDN * RANKN];
__device__ float g_Lv[CONDN * RANKN];
__device__ float g_Lp[CONDN * RANKN];

// ---------------- SGEMM: C[M,N] (+)= A[M,K] @ W[N,K]^T ----------------
// 128x128x16 tiles, 256 threads, 8x8 micro-tiles, smem stored k-major.
template <bool ACC>
__global__ __launch_bounds__(256) void sgemm_nt(const float* __restrict__ A,
                                                const float* __restrict__ W,
                                                float* __restrict__ C,
                                                int M, int N, int K) {
    constexpr int BM = 128, BN = 128, BK = 16, PADM = 132;
    __shared__ float As[BK][PADM];
    __shared__ float Bs[BK][PADM];

    const int tid = threadIdx.x;
    const int tx = tid & 15;        // 0..15 -> col group
    const int ty = tid >> 4;        // 0..15 -> row group
    const int row0 = blockIdx.y * BM;
    const int col0 = blockIdx.x * BN;

    float acc[8][8];
#pragma unroll
    for (int i = 0; i < 8; i++)
#pragma unroll
        for (int j = 0; j < 8; j++) acc[i][j] = 0.f;

    for (int k0 = 0; k0 < K; k0 += BK) {
        // cooperative load: 512 float4 per tile per operand, 2 per thread
#pragma unroll
        for (int f = 0; f < 2; f++) {
            int id = tid + f * 256;        // 0..511
            int m = id >> 2;               // 0..127
            int k4 = (id & 3) << 2;        // 0,4,8,12
            float4 va = make_float4(0.f, 0.f, 0.f, 0.f);
            int gm = row0 + m;
            if (gm < M) va = *(const float4*)&A[(size_t)gm * K + k0 + k4];
            As[k4 + 0][m] = va.x; As[k4 + 1][m] = va.y;
            As[k4 + 2][m] = va.z; As[k4 + 3][m] = va.w;
            float4 vb = make_float4(0.f, 0.f, 0.f, 0.f);
            int gn = col0 + m;
            if (gn < N) vb = *(const float4*)&W[(size_t)gn * K + k0 + k4];
            Bs[k4 + 0][m] = vb.x; Bs[k4 + 1][m] = vb.y;
            Bs[k4 + 2][m] = vb.z; Bs[k4 + 3][m] = vb.w;
        }
        __syncthreads();
#pragma unroll
        for (int k = 0; k < BK; k++) {
            float a[8], b[8];
            *(float4*)&a[0] = *(const float4*)&As[k][ty * 8];
            *(float4*)&a[4] = *(const float4*)&As[k][ty * 8 + 4];
            *(float4*)&b[0] = *(const float4*)&Bs[k][tx * 8];
            *(float4*)&b[4] = *(const float4*)&Bs[k][tx * 8 + 4];
#pragma unroll
            for (int i = 0; i < 8; i++)
#pragma unroll
                for (int j = 0; j < 8; j++)
                    acc[i][j] = fmaf(a[i], b[j], acc[i][j]);
        }
        __syncthreads();
    }

#pragma unroll
    for (int i = 0; i < 8; i++) {
        int gm = row0 + ty * 8 + i;
        if (gm >= M) continue;
#pragma unroll
        for (int j = 0; j < 8; j++) {
            int gn = col0 + tx * 8 + j;
            if (gn >= N) continue;
            size_t idx = (size_t)gm * N + gn;
            if (ACC) C[idx] += acc[i][j];
            else     C[idx]  = acc[i][j];
        }
    }
}

// ---------------- fused RMS-norm (over DIM) + rope for Q and K ----------------
__global__ __launch_bounds__(256) void rmsrope_kernel(
    float* __restrict__ Q, float* __restrict__ K,
    const float* __restrict__ rope,
    const float* __restrict__ gq, const float* __restrict__ gk,
    const float* __restrict__ gqt, const float* __restrict__ gkt) {
    const int row = blockIdx.x;
    const int tid = threadIdx.x;
    __shared__ float sbuf[18];

    float* qrow = Q + (size_t)row * DIMN;
    float* krow = K + (size_t)row * DIMN;

    float sq = 0.f, sk = 0.f;
    for (int c4 = tid; c4 < DIMN / 4; c4 += 256) {
        float4 q = *(const float4*)&qrow[c4 * 4];
        sq += q.x * q.x + q.y * q.y + q.z * q.z + q.w * q.w;
        float4 kk = *(const float4*)&krow[c4 * 4];
        sk += kk.x * kk.x + kk.y * kk.y + kk.z * kk.z + kk.w * kk.w;
    }
#pragma unroll
    for (int o = 16; o > 0; o >>= 1) {
        sq += __shfl_xor_sync(0xffffffffu, sq, o);
        sk += __shfl_xor_sync(0xffffffffu, sk, o);
    }
    int w = tid >> 5;
    if ((tid & 31) == 0) { sbuf[w] = sq; sbuf[8 + w] = sk; }
    __syncthreads();
    if (tid == 0) {
        float a = 0.f, b = 0.f;
        for (int i = 0; i < 8; i++) { a += sbuf[i]; b += sbuf[8 + i]; }
        sbuf[16] = a; sbuf[17] = b;
    }
    __syncthreads();
    const float invq = rsqrtf(sbuf[16] / (float)DIMN + EPSV);
    const float invk = rsqrtf(sbuf[17] / (float)DIMN + EPSV);
    const float* gQ = (row < IMG_SEQ) ? gq : gqt;
    const float* gK = (row < IMG_SEQ) ? gk : gkt;
    const float* rp = rope + (size_t)row * 256;  // (64 pairs) x 2 x 2

    for (int pi = tid; pi < DIMN / 2; pi += 256) {
        int c0 = pi * 2;
        int j = pi & 63;   // pair index within head
        float4 r = *(const float4*)&rp[j * 4];  // [rot00, rot01, rot10, rot11]
        float x0 = qrow[c0] * invq * gQ[c0];
        float x1 = qrow[c0 + 1] * invq * gQ[c0 + 1];
        qrow[c0]     = r.x * x0 + r.y * x1;
        qrow[c0 + 1] = r.z * x0 + r.w * x1;
        float y0 = krow[c0] * invk * gK[c0];
        float y1 = krow[c0 + 1] * invk * gK[c0 + 1];
        krow[c0]     = r.x * y0 + r.y * y1;
        krow[c0 + 1] = r.z * y0 + r.w * y1;
    }
}

// ---------------- flash attention (fp32, online softmax) ----------------
// grid (34 row-blocks, 16 heads), 256 threads, Br=Bc=64.
// Block mask: rows >= 1152 only attend keys >= 1152 -> start key loop at tile 18.
#define FLASH_SMEM_FLOATS 30208  // Qt 8704 + Kt 8704 + Vs 8448 + Ps 4352
#define FLASH_SMEM_BYTES (FLASH_SMEM_FLOATS * 4)

__global__ __launch_bounds__(256) void flash_kernel(const float* __restrict__ Q,
                                                    const float* __restrict__ K,
                                                    const float* __restrict__ V,
                                                    float* __restrict__ O) {
    extern __shared__ float sm[];
    float* Qt = sm;           // [128][68] k-major
    float* Kt = sm + 8704;    // [128][68] k-major
    float* Vs = sm + 17408;   // [64][132] row-major
    float* Ps = sm + 25856;   // [64][68]

    const int tid = threadIdx.x;
    const int tx = tid & 15;   // S cols group (4 each), O cols group (8 each)
    const int ty = tid >> 4;   // rows group (4 each)
    const int qrow0 = blockIdx.x * 64;
    const int head = blockIdx.y;
    const size_t hoff = (size_t)head * HD;

    // load Q tile transposed: Qt[k][c]
#pragma unroll
    for (int f = 0; f < 8; f++) {
        int id = tid + f * 256;            // 0..2047
        int kblk = id >> 8;                // 0..7
        int rem = id & 255;
        int c = rem >> 2;                  // 0..63
        int k = (((kblk << 2) + (rem & 3)) << 2);
        float4 v = *(const float4*)&Q[(size_t)(qrow0 + c) * DIMN + hoff + k];
        Qt[(k + 0) * 68 + c] = v.x; Qt[(k + 1) * 68 + c] = v.y;
        Qt[(k + 2) * 68 + c] = v.z; Qt[(k + 3) * 68 + c] = v.w;
    }

    float m[4], l[4], o[4][8];
#pragma unroll
    for (int i = 0; i < 4; i++) {
        m[i] = -INFINITY; l[i] = 0.f;
#pragma unroll
        for (int cc = 0; cc < 8; cc++) o[i][cc] = 0.f;
    }
    __syncthreads();

    const int kt0 = (qrow0 >= SBSN) ? (SBSN / 64) : 0;
    const float scale = 0.0883883476483184405f;  // 1/sqrt(128)

    for (int kt = kt0; kt < SEQN / 64; kt++) {
        const int kr0 = kt * 64;
        // load K tile transposed
#pragma unroll
        for (int f = 0; f < 8; f++) {
            int id = tid + f * 256;
            int kblk = id >> 8;
            int rem = id & 255;
            int c = rem >> 2;
            int k = (((kblk << 2) + (rem & 3)) << 2);
            float4 v = *(const float4*)&K[(size_t)(kr0 + c) * DIMN + hoff + k];
            Kt[(k + 0) * 68 + c] = v.x; Kt[(k + 1) * 68 + c] = v.y;
            Kt[(k + 2) * 68 + c] = v.z; Kt[(k + 3) * 68 + c] = v.w;
        }
        // load V tile row-major
#pragma unroll
        for (int f = 0; f < 8; f++) {
            int id = tid + f * 256;
            int j = id >> 5;
            int c4 = (id & 31) << 2;
            *(float4*)&Vs[j * 132 + c4] =
                *(const float4*)&V[(size_t)(kr0 + j) * DIMN + hoff + c4];
        }
        __syncthreads();

        // S = Q @ K^T (4x4 micro-tile)
        float s[4][4];
#pragma unroll
        for (int i = 0; i < 4; i++)
#pragma unroll
            for (int j = 0; j < 4; j++) s[i][j] = 0.f;
        for (int k = 0; k < HD; k++) {
            float4 a4 = *(const float4*)&Qt[k * 68 + (ty << 2)];
            float4 b4 = *(const float4*)&Kt[k * 68 + (tx << 2)];
            float av[4] = {a4.x, a4.y, a4.z, a4.w};
            float bv[4] = {b4.x, b4.y, b4.z, b4.w};
#pragma unroll
            for (int i = 0; i < 4; i++)
#pragma unroll
                for (int j = 0; j < 4; j++)
                    s[i][j] = fmaf(av[i], bv[j], s[i][j]);
        }

        // online softmax per row
#pragma unroll
        for (int i = 0; i < 4; i++) {
            float mt = -INFINITY;
#pragma unroll
            for (int j = 0; j < 4; j++) { s[i][j] *= scale; mt = fmaxf(mt, s[i][j]); }
#pragma unroll
            for (int off = 8; off > 0; off >>= 1)
                mt = fmaxf(mt, __shfl_xor_sync(0xffffffffu, mt, off));
            float mn = fmaxf(m[i], mt);
            float corr = __expf(m[i] - mn);
            float ps = 0.f;
#pragma unroll
            for (int j = 0; j < 4; j++) { s[i][j] = __expf(s[i][j] - mn); ps += s[i][j]; }
#pragma unroll
            for (int off = 8; off > 0; off >>= 1)
                ps += __shfl_xor_sync(0xffffffffu, ps, off);
            l[i] = l[i] * corr + ps;
            m[i] = mn;
#pragma unroll
            for (int cc = 0; cc < 8; cc++) o[i][cc] *= corr;
            int r = (ty << 2) + i;
            *(float4*)&Ps[r * 68 + (tx << 2)] =
                make_float4(s[i][0], s[i][1], s[i][2], s[i][3]);
        }
        __syncthreads();

        // O += P @ V  (4 rows x 8 cols micro-tile)
#pragma unroll 4
        for (int j = 0; j < 64; j++) {
            float4 v0 = *(const float4*)&Vs[j * 132 + (tx << 3)];
            float4 v1 = *(const float4*)&Vs[j * 132 + (tx << 3) + 4];
            float vv[8] = {v0.x, v0.y, v0.z, v0.w, v1.x, v1.y, v1.z, v1.w};
#pragma unroll
            for (int i = 0; i < 4; i++) {
                float p = Ps[((ty << 2) + i) * 68 + j];
#pragma unroll
                for (int cc = 0; cc < 8; cc++)
                    o[i][cc] = fmaf(p, vv[cc], o[i][cc]);
            }
        }
        __syncthreads();
    }

    // epilogue
#pragma unroll
    for (int i = 0; i < 4; i++) {
        float inv = 1.f / l[i];
        int gr = qrow0 + (ty << 2) + i;
        float4 r0 = make_float4(o[i][0] * inv, o[i][1] * inv, o[i][2] * inv, o[i][3] * inv);
        float4 r1 = make_float4(o[i][4] * inv, o[i][5] * inv, o[i][6] * inv, o[i][7] * inv);
        *(float4*)&O[(size_t)gr * DIMN + hoff + (tx << 3)] = r0;
        *(float4*)&O[(size_t)gr * DIMN + hoff + (tx << 3) + 4] = r1;
    }
}

// ---------------- output assembly ----------------
__global__ void copyout_kernel(const float* __restrict__ Hi, float* __restrict__ out) {
    int i = blockIdx.x * blockDim.x + threadIdx.x;
    const int n1 = BLOCKN * DIMN;          // h_img floats
    if (i >= 2 * n1) return;
    if (i < n1) out[i] = Hi[i];                          // h_img
    else        out[i + TXT_SEQ * DIMN] = Hi[i];         // cond_hidden after h_t
}

// ---------------- launch ----------------
extern "C" void kernel_launch(void* const* d_in, const int* in_sizes, int n_in,
                              void* d_out, int out_size) {
    const float* img  = (const float*)d_in[0];
    const float* txt  = (const float*)d_in[1];
    const float* rope = (const float*)d_in[2];
    const float* wq   = (const float*)d_in[3];
    const float* wk   = (const float*)d_in[4];
    const float* wv   = (const float*)d_in[5];
    const float* wo   = (const float*)d_in[6];
    const float* wq_t = (const float*)d_in[7];
    const float* wk_t = (const float*)d_in[8];
    const float* wv_t = (const float*)d_in[9];
    const float* wo_t = (const float*)d_in[10];
    const float* gq   = (const float*)d_in[11];
    const float* gk   = (const float*)d_in[12];
    const float* gqt  = (const float*)d_in[13];
    const float* gkt  = (const float*)d_in[14];
    const float* q_down = (const float*)d_in[15];
    const float* q_up   = (const float*)d_in[16];
    const float* k_down = (const float*)d_in[17];
    const float* k_up   = (const float*)d_in[18];
    const float* v_down = (const float*)d_in[19];
    const float* v_up   = (const float*)d_in[20];
    const float* p_down = (const float*)d_in[21];
    const float* p_up   = (const float*)d_in[22];
    float* out = (float*)d_out;

    float *Q, *K, *V, *O, *Hi, *Lq, *Lk, *Lv, *Lp;
    cudaGetSymbolAddress((void**)&Q,  g_Q);
    cudaGetSymbolAddress((void**)&K,  g_K);
    cudaGetSymbolAddress((void**)&V,  g_V);
    cudaGetSymbolAddress((void**)&O,  g_O);
    cudaGetSymbolAddress((void**)&Hi, g_Hi);
    cudaGetSymbolAddress((void**)&Lq, g_Lq);
    cudaGetSymbolAddress((void**)&Lk, g_Lk);
    cudaGetSymbolAddress((void**)&Lv, g_Lv);
    cudaGetSymbolAddress((void**)&Lp, g_Lp);

    dim3 blk(256);
    auto gemm = [&](const float* A, const float* W, float* C,
                    int M, int N, int Kd, bool acc) {
        dim3 grid((N + 127) / 128, (M + 127) / 128);
        if (acc) sgemm_nt<true><<<grid, blk>>>(A, W, C, M, N, Kd);
        else     sgemm_nt<false><<<grid, blk>>>(A, W, C, M, N, Kd);
    };

    const float* img_cond = img + (size_t)BLOCKN * DIMN;  // rows 1024..2047

    // LoRA down-projections (only cond rows are non-zero under lmask)
    gemm(img_cond, q_down, Lq, CONDN, RANKN, DIMN, false);
    gemm(img_cond, k_down, Lk, CONDN, RANKN, DIMN, false);
    gemm(img_cond, v_down, Lv, CONDN, RANKN, DIMN, false);

    // Q / K / V  (image main + lora-up accumulate + text)
    gemm(img, wq, Q, IMG_SEQ, DIMN, DIMN, false);
    gemm(Lq, q_up, Q + (size_t)BLOCKN * DIMN, CONDN, DIMN, RANKN, true);
    gemm(txt, wq_t, Q + (size_t)IMG_SEQ * DIMN, TXT_SEQ, DIMN, DIMN, false);

    gemm(img, wk, K, IMG_SEQ, DIMN, DIMN, false);
    gemm(Lk, k_up, K + (size_t)BLOCKN * DIMN, CONDN, DIMN, RANKN, true);
    gemm(txt, wk_t, K + (size_t)IMG_SEQ * DIMN, TXT_SEQ, DIMN, DIMN, false);

    gemm(img, wv, V, IMG_SEQ, DIMN, DIMN, false);
    gemm(Lv, v_up, V + (size_t)BLOCKN * DIMN, CONDN, DIMN, RANKN, true);
    gemm(txt, wv_t, V + (size_t)IMG_SEQ * DIMN, TXT_SEQ, DIMN, DIMN, false);

    // RMS + rope on Q and K
    rmsrope_kernel<<<SEQN, 256>>>(Q, K, rope, gq, gk, gqt, gkt);

    // attention
    cudaFuncSetAttribute(flash_kernel, cudaFuncAttributeMaxDynamicSharedMemorySize,
                         FLASH_SMEM_BYTES);
    flash_kernel<<<dim3(SEQN / 64, HEADS), 256, FLASH_SMEM_BYTES>>>(Q, K, V, O);

    // output projections
    gemm(O, wo, Hi, IMG_SEQ, DIMN, DIMN, false);
    gemm(O + (size_t)IMG_SEQ * DIMN, wo_t, out + (size_t)BLOCKN * DIMN,
         TXT_SEQ, DIMN, DIMN, false);

    // post-projection LoRA on h_i (input = Hi pre-addition, cond rows only)
    gemm(Hi + (size_t)BLOCKN * DIMN, p_down, Lp, CONDN, RANKN, DIMN, false);
    gemm(Lp, p_up, Hi + (size_t)BLOCKN * DIMN, CONDN, DIMN, RANKN, true);

    // assemble outputs: [h_img (1024x2048) | h_t (128x2048) | cond (1024x2048)]
    int tot = 2 * BLOCKN * DIMN;
    copyout_kernel<<<(tot + 255) / 256, 256>>>(Hi, out);
}

// round 2
// speedup vs baseline: 1.8668x; 1.8668x over previous
#include <cuda_runtime.h>
#include <math.h>

// ---------------- problem constants ----------------
#define DIMN 2048
#define HEADS 16
#define HD 128
#define RANKN 64
#define IMG_SEQ 2048
#define TXT_SEQ 128
#define SEQN 2176          // IMG_SEQ + TXT_SEQ
#define CONDN 1024
#define BLOCKN 1024        // IMG_SEQ - COND
#define SBSN 1152          // SEQ - COND
#define EPSV 1e-5f

// ---------------- device scratch (no allocation allowed) ----------------
__device__ float g_Q[SEQN * DIMN];
__device__ float g_K[SEQN * DIMN];
__device__ float g_V[SEQN * DIMN];
__device__ float g_O[SEQN * DIMN];
__device__ float g_Hi[IMG_SEQ * DIMN];
__device__ float g_Lq[CONDN * RANKN];
__device__ float g_Lk[CONDN * RANKN];
__device__ float g_Lv[CONDN * RANKN];
__device__ float g_Lp[CONDN * RANKN];

// ---------------- helpers ----------------
__device__ __forceinline__ float to_tf32(float x) {
    unsigned u;
    asm("cvt.rna.tf32.f32 %0, %1;" : "=r"(u) : "f"(x));
    return __uint_as_float(u);
}

__device__ __forceinline__ void mma_tf32(float c[4], const float a[4], const float b[2]) {
    asm volatile(
        "mma.sync.aligned.m16n8k8.row.col.f32.tf32.tf32.f32 "
        "{%0,%1,%2,%3}, {%4,%5,%6,%7}, {%8,%9}, {%0,%1,%2,%3};"
        : "+f"(c[0]), "+f"(c[1]), "+f"(c[2]), "+f"(c[3])
        : "r"(__float_as_uint(a[0])), "r"(__float_as_uint(a[1])),
          "r"(__float_as_uint(a[2])), "r"(__float_as_uint(a[3])),
          "r"(__float_as_uint(b[0])), "r"(__float_as_uint(b[1])));
}

// ---------------- TF32 tensor-core GEMM: C[M,N] (+)= A[M,K] @ W[N,K]^T -------
// 128x128x32 tiles, 256 threads = 8 warps (4 along M x 2 along N),
// warp tile 32x64 = 2x8 m16n8k8 mma tiles.
template <bool ACC>
__global__ __launch_bounds__(256) void mma_gemm_nt(const float* __restrict__ A,
                                                   const float* __restrict__ W,
                                                   float* __restrict__ C,
                                                   int M, int N, int K) {
    constexpr int BK = 32, LD = 36;
    __shared__ float As[128 * LD];
    __shared__ float Bs[128 * LD];

    const int tid = threadIdx.x;
    const int lane = tid & 31;
    const int warp = tid >> 5;
    const int wm = warp & 3;          // 0..3 -> 32-row strip
    const int wn = warp >> 2;         // 0..1 -> 64-col strip
    const int row0 = blockIdx.y * 128;
    const int col0 = blockIdx.x * 128;

    float c[2][8][4];
#pragma unroll
    for (int i = 0; i < 2; i++)
#pragma unroll
        for (int j = 0; j < 8; j++)
#pragma unroll
            for (int r = 0; r < 4; r++) c[i][j][r] = 0.f;

    const int lrow = lane >> 2;       // 0..7
    const int lcol = lane & 3;        // 0..3

    for (int k0 = 0; k0 < K; k0 += BK) {
        // cooperative load + tf32 rounding: 1024 float4 per operand, 4/thread
#pragma unroll
        for (int f = 0; f < 4; f++) {
            int id = tid + f * 256;        // 0..1023
            int r = id >> 3;               // 0..127
            int kq = (id & 7) << 2;        // 0,4,...,28
            float4 va = make_float4(0.f, 0.f, 0.f, 0.f);
            int gm = row0 + r;
            if (gm < M) va = *(const float4*)&A[(size_t)gm * K + k0 + kq];
            float* dst = &As[r * LD + kq];
            dst[0] = to_tf32(va.x); dst[1] = to_tf32(va.y);
            dst[2] = to_tf32(va.z); dst[3] = to_tf32(va.w);
            float4 vb = make_float4(0.f, 0.f, 0.f, 0.f);
            int gn = col0 + r;
            if (gn < N) vb = *(const float4*)&W[(size_t)gn * K + k0 + kq];
            float* dstb = &Bs[r * LD + kq];
            dstb[0] = to_tf32(vb.x); dstb[1] = to_tf32(vb.y);
            dstb[2] = to_tf32(vb.z); dstb[3] = to_tf32(vb.w);
        }
        __syncthreads();

#pragma unroll
        for (int ks = 0; ks < BK / 8; ks++) {
            const int kb = ks * 8;
            float a[2][4];
#pragma unroll
            for (int mi = 0; mi < 2; mi++) {
                int ar = wm * 32 + mi * 16 + lrow;
                a[mi][0] = As[ar * LD + kb + lcol];
                a[mi][1] = As[(ar + 8) * LD + kb + lcol];
                a[mi][2] = As[ar * LD + kb + lcol + 4];
                a[mi][3] = As[(ar + 8) * LD + kb + lcol + 4];
            }
            float b[8][2];
#pragma unroll
            for (int ni = 0; ni < 8; ni++) {
                int br = wn * 64 + ni * 8 + lrow;
                b[ni][0] = Bs[br * LD + kb + lcol];
                b[ni][1] = Bs[br * LD + kb + lcol + 4];
            }
#pragma unroll
            for (int mi = 0; mi < 2; mi++)
#pragma unroll
                for (int ni = 0; ni < 8; ni++)
                    mma_tf32(c[mi][ni], a[mi], b[ni]);
        }
        __syncthreads();
    }

    // epilogue: c regs -> (row=lane/4 [+8], col=2*(lane%4) [+1])
#pragma unroll
    for (int mi = 0; mi < 2; mi++) {
#pragma unroll
        for (int ni = 0; ni < 8; ni++) {
            int gr = row0 + wm * 32 + mi * 16 + lrow;
            int gc = col0 + wn * 64 + ni * 8 + lcol * 2;
            if (gc + 1 < N || gc < N) {
                if (gr < M && gc + 1 < N) {
                    float2* p0 = (float2*)&C[(size_t)gr * N + gc];
                    float2* p1 = (float2*)&C[(size_t)(gr + 8) * N + gc];
                    if (ACC) {
                        float2 o0 = *p0, o1 = *p1;
                        o0.x += c[mi][ni][0]; o0.y += c[mi][ni][1];
                        o1.x += c[mi][ni][2]; o1.y += c[mi][ni][3];
                        *p0 = o0;
                        if (gr + 8 < M) *p1 = o1;
                    } else {
                        *p0 = make_float2(c[mi][ni][0], c[mi][ni][1]);
                        if (gr + 8 < M) *p1 = make_float2(c[mi][ni][2], c[mi][ni][3]);
                    }
                }
            }
        }
    }
}

// ---------------- fused RMS-norm (over DIM) + rope for Q and K ----------------
__global__ __launch_bounds__(256) void rmsrope_kernel(
    float* __restrict__ Q, float* __restrict__ K,
    const float* __restrict__ rope,
    const float* __restrict__ gq, const float* __restrict__ gk,
    const float* __restrict__ gqt, const float* __restrict__ gkt) {
    const int row = blockIdx.x;
    const int tid = threadIdx.x;
    __shared__ float sbuf[18];

    float* qrow = Q + (size_t)row * DIMN;
    float* krow = K + (size_t)row * DIMN;

    float sq = 0.f, sk = 0.f;
    for (int c4 = tid; c4 < DIMN / 4; c4 += 256) {
        float4 q = *(const float4*)&qrow[c4 * 4];
        sq += q.x * q.x + q.y * q.y + q.z * q.z + q.w * q.w;
        float4 kk = *(const float4*)&krow[c4 * 4];
        sk += kk.x * kk.x + kk.y * kk.y + kk.z * kk.z + kk.w * kk.w;
    }
#pragma unroll
    for (int o = 16; o > 0; o >>= 1) {
        sq += __shfl_xor_sync(0xffffffffu, sq, o);
        sk += __shfl_xor_sync(0xffffffffu, sk, o);
    }
    int w = tid >> 5;
    if ((tid & 31) == 0) { sbuf[w] = sq; sbuf[8 + w] = sk; }
    __syncthreads();
    if (tid == 0) {
        float a = 0.f, b = 0.f;
        for (int i = 0; i < 8; i++) { a += sbuf[i]; b += sbuf[8 + i]; }
        sbuf[16] = a; sbuf[17] = b;
    }
    __syncthreads();
    const float invq = rsqrtf(sbuf[16] / (float)DIMN + EPSV);
    const float invk = rsqrtf(sbuf[17] / (float)DIMN + EPSV);
    const float* gQ = (row < IMG_SEQ) ? gq : gqt;
    const float* gK = (row < IMG_SEQ) ? gk : gkt;
    const float* rp = rope + (size_t)row * 256;  // (64 pairs) x 2 x 2

    for (int pi = tid; pi < DIMN / 2; pi += 256) {
        int c0 = pi * 2;
        int j = pi & 63;   // pair index within head
        float4 r = *(const float4*)&rp[j * 4];  // [rot00, rot01, rot10, rot11]
        float x0 = qrow[c0] * invq * gQ[c0];
        float x1 = qrow[c0 + 1] * invq * gQ[c0 + 1];
        qrow[c0]     = r.x * x0 + r.y * x1;
        qrow[c0 + 1] = r.z * x0 + r.w * x1;
        float y0 = krow[c0] * invk * gK[c0];
        float y1 = krow[c0 + 1] * invk * gK[c0 + 1];
        krow[c0]     = r.x * y0 + r.y * y1;
        krow[c0 + 1] = r.z * y0 + r.w * y1;
    }
}

// ---------------- flash attention (fp32, online softmax) ----------------
#define FLASH_SMEM_FLOATS 30208  // Qt 8704 + Kt 8704 + Vs 8448 + Ps 4352
#define FLASH_SMEM_BYTES (FLASH_SMEM_FLOATS * 4)

__global__ __launch_bounds__(256) void flash_kernel(const float* __restrict__ Q,
                                                    const float* __restrict__ K,
                                                    const float* __restrict__ V,
                                                    float* __restrict__ O) {
    extern __shared__ float sm[];
    float* Qt = sm;           // [128][68] k-major
    float* Kt = sm + 8704;    // [128][68] k-major
    float* Vs = sm + 17408;   // [64][132] row-major
    float* Ps = sm + 25856;   // [64][68]

    const int tid = threadIdx.x;
    const int tx = tid & 15;
    const int ty = tid >> 4;
    const int qrow0 = blockIdx.x * 64;
    const int head = blockIdx.y;
    const size_t hoff = (size_t)head * HD;

#pragma unroll
    for (int f = 0; f < 8; f++) {
        int id = tid + f * 256;
        int kblk = id >> 8;
        int rem = id & 255;
        int cc = rem >> 2;
        int k = (((kblk << 2) + (rem & 3)) << 2);
        float4 v = *(const float4*)&Q[(size_t)(qrow0 + cc) * DIMN + hoff + k];
        Qt[(k + 0) * 68 + cc] = v.x; Qt[(k + 1) * 68 + cc] = v.y;
        Qt[(k + 2) * 68 + cc] = v.z; Qt[(k + 3) * 68 + cc] = v.w;
    }

    float m[4], l[4], o[4][8];
#pragma unroll
    for (int i = 0; i < 4; i++) {
        m[i] = -INFINITY; l[i] = 0.f;
#pragma unroll
        for (int cc = 0; cc < 8; cc++) o[i][cc] = 0.f;
    }
    __syncthreads();

    const int kt0 = (qrow0 >= SBSN) ? (SBSN / 64) : 0;
    const float scale = 0.0883883476483184405f;  // 1/sqrt(128)

    for (int kt = kt0; kt < SEQN / 64; kt++) {
        const int kr0 = kt * 64;
#pragma unroll
        for (int f = 0; f < 8; f++) {
            int id = tid + f * 256;
            int kblk = id >> 8;
            int rem = id & 255;
            int cc = rem >> 2;
            int k = (((kblk << 2) + (rem & 3)) << 2);
            float4 v = *(const float4*)&K[(size_t)(kr0 + cc) * DIMN + hoff + k];
            Kt[(k + 0) * 68 + cc] = v.x; Kt[(k + 1) * 68 + cc] = v.y;
            Kt[(k + 2) * 68 + cc] = v.z; Kt[(k + 3) * 68 + cc] = v.w;
        }
#pragma unroll
        for (int f = 0; f < 8; f++) {
            int id = tid + f * 256;
            int j = id >> 5;
            int c4 = (id & 31) << 2;
            *(float4*)&Vs[j * 132 + c4] =
                *(const float4*)&V[(size_t)(kr0 + j) * DIMN + hoff + c4];
        }
        __syncthreads();

        float s[4][4];
#pragma unroll
        for (int i = 0; i < 4; i++)
#pragma unroll
            for (int j = 0; j < 4; j++) s[i][j] = 0.f;
        for (int k = 0; k < HD; k++) {
            float4 a4 = *(const float4*)&Qt[k * 68 + (ty << 2)];
            float4 b4 = *(const float4*)&Kt[k * 68 + (tx << 2)];
            float av[4] = {a4.x, a4.y, a4.z, a4.w};
            float bv[4] = {b4.x, b4.y, b4.z, b4.w};
#pragma unroll
            for (int i = 0; i < 4; i++)
#pragma unroll
                for (int j = 0; j < 4; j++)
                    s[i][j] = fmaf(av[i], bv[j], s[i][j]);
        }

#pragma unroll
        for (int i = 0; i < 4; i++) {
            float mt = -INFINITY;
#pragma unroll
            for (int j = 0; j < 4; j++) { s[i][j] *= scale; mt = fmaxf(mt, s[i][j]); }
#pragma unroll
            for (int off = 8; off > 0; off >>= 1)
                mt = fmaxf(mt, __shfl_xor_sync(0xffffffffu, mt, off));
            float mn = fmaxf(m[i], mt);
            float corr = __expf(m[i] - mn);
            float ps = 0.f;
#pragma unroll
            for (int j = 0; j < 4; j++) { s[i][j] = __expf(s[i][j] - mn); ps += s[i][j]; }
#pragma unroll
            for (int off = 8; off > 0; off >>= 1)
                ps += __shfl_xor_sync(0xffffffffu, ps, off);
            l[i] = l[i] * corr + ps;
            m[i] = mn;
#pragma unroll
            for (int cc = 0; cc < 8; cc++) o[i][cc] *= corr;
            int r = (ty << 2) + i;
            *(float4*)&Ps[r * 68 + (tx << 2)] =
                make_float4(s[i][0], s[i][1], s[i][2], s[i][3]);
        }
        __syncthreads();

#pragma unroll 4
        for (int j = 0; j < 64; j++) {
            float4 v0 = *(const float4*)&Vs[j * 132 + (tx << 3)];
            float4 v1 = *(const float4*)&Vs[j * 132 + (tx << 3) + 4];
            float vv[8] = {v0.x, v0.y, v0.z, v0.w, v1.x, v1.y, v1.z, v1.w};
#pragma unroll
            for (int i = 0; i < 4; i++) {
                float p = Ps[((ty << 2) + i) * 68 + j];
#pragma unroll
                for (int cc = 0; cc < 8; cc++)
                    o[i][cc] = fmaf(p, vv[cc], o[i][cc]);
            }
        }
        __syncthreads();
    }

#pragma unroll
    for (int i = 0; i < 4; i++) {
        float inv = 1.f / l[i];
        int gr = qrow0 + (ty << 2) + i;
        float4 r0 = make_float4(o[i][0] * inv, o[i][1] * inv, o[i][2] * inv, o[i][3] * inv);
        float4 r1 = make_float4(o[i][4] * inv, o[i][5] * inv, o[i][6] * inv, o[i][7] * inv);
        *(float4*)&O[(size_t)gr * DIMN + hoff + (tx << 3)] = r0;
        *(float4*)&O[(size_t)gr * DIMN + hoff + (tx << 3) + 4] = r1;
    }
}

// ---------------- output assembly ----------------
__global__ void copyout_kernel(const float* __restrict__ Hi, float* __restrict__ out) {
    int i = blockIdx.x * blockDim.x + threadIdx.x;
    const int n1 = BLOCKN * DIMN;
    if (i >= 2 * n1) return;
    if (i < n1) out[i] = Hi[i];
    else        out[i + TXT_SEQ * DIMN] = Hi[i];
}

// ---------------- launch ----------------
extern "C" void kernel_launch(void* const* d_in, const int* in_sizes, int n_in,
                              void* d_out, int out_size) {
    const float* img  = (const float*)d_in[0];
    const float* txt  = (const float*)d_in[1];
    const float* rope = (const float*)d_in[2];
    const float* wq   = (const float*)d_in[3];
    const float* wk   = (const float*)d_in[4];
    const float* wv   = (const float*)d_in[5];
    const float* wo   = (const float*)d_in[6];
    const float* wq_t = (const float*)d_in[7];
    const float* wk_t = (const float*)d_in[8];
    const float* wv_t = (const float*)d_in[9];
    const float* wo_t = (const float*)d_in[10];
    const float* gq   = (const float*)d_in[11];
    const float* gk   = (const float*)d_in[12];
    const float* gqt  = (const float*)d_in[13];
    const float* gkt  = (const float*)d_in[14];
    const float* q_down = (const float*)d_in[15];
    const float* q_up   = (const float*)d_in[16];
    const float* k_down = (const float*)d_in[17];
    const float* k_up   = (const float*)d_in[18];
    const float* v_down = (const float*)d_in[19];
    const float* v_up   = (const float*)d_in[20];
    const float* p_down = (const float*)d_in[21];
    const float* p_up   = (const float*)d_in[22];
    float* out = (float*)d_out;

    float *Q, *K, *V, *O, *Hi, *Lq, *Lk, *Lv, *Lp;
    cudaGetSymbolAddress((void**)&Q,  g_Q);
    cudaGetSymbolAddress((void**)&K,  g_K);
    cudaGetSymbolAddress((void**)&V,  g_V);
    cudaGetSymbolAddress((void**)&O,  g_O);
    cudaGetSymbolAddress((void**)&Hi, g_Hi);
    cudaGetSymbolAddress((void**)&Lq, g_Lq);
    cudaGetSymbolAddress((void**)&Lk, g_Lk);
    cudaGetSymbolAddress((void**)&Lv, g_Lv);
    cudaGetSymbolAddress((void**)&Lp, g_Lp);

    dim3 blk(256);
    auto gemm = [&](const float* A, const float* W, float* C,
                    int M, int N, int Kd, bool acc) {
        dim3 grid((N + 127) / 128, (M + 127) / 128);
        if (acc) mma_gemm_nt<true><<<grid, blk>>>(A, W, C, M, N, Kd);
        else     mma_gemm_nt<false><<<grid, blk>>>(A, W, C, M, N, Kd);
    };

    const float* img_cond = img + (size_t)BLOCKN * DIMN;

    // LoRA down-projections (only cond rows are non-zero under lmask)
    gemm(img_cond, q_down, Lq, CONDN, RANKN, DIMN, false);
    gemm(img_cond, k_down, Lk, CONDN, RANKN, DIMN, false);
    gemm(img_cond, v_down, Lv, CONDN, RANKN, DIMN, false);

    // Q / K / V  (image main + lora-up accumulate + text)
    gemm(img, wq, Q, IMG_SEQ, DIMN, DIMN, false);
    gemm(Lq, q_up, Q + (size_t)BLOCKN * DIMN, CONDN, DIMN, RANKN, true);
    gemm(txt, wq_t, Q + (size_t)IMG_SEQ * DIMN, TXT_SEQ, DIMN, DIMN, false);

    gemm(img, wk, K, IMG_SEQ, DIMN, DIMN, false);
    gemm(Lk, k_up, K + (size_t)BLOCKN * DIMN, CONDN, DIMN, RANKN, true);
    gemm(txt, wk_t, K + (size_t)IMG_SEQ * DIMN, TXT_SEQ, DIMN, DIMN, false);

    gemm(img, wv, V, IMG_SEQ, DIMN, DIMN, false);
    gemm(Lv, v_up, V + (size_t)BLOCKN * DIMN, CONDN, DIMN, RANKN, true);
    gemm(txt, wv_t, V + (size_t)IMG_SEQ * DIMN, TXT_SEQ, DIMN, DIMN, false);

    // RMS + rope on Q and K
    rmsrope_kernel<<<SEQN, 256>>>(Q, K, rope, gq, gk, gqt, gkt);

    // attention
    cudaFuncSetAttribute(flash_kernel, cudaFuncAttributeMaxDynamicSharedMemorySize,
                         FLASH_SMEM_BYTES);
    flash_kernel<<<dim3(SEQN / 64, HEADS), 256, FLASH_SMEM_BYTES>>>(Q, K, V, O);

    // output projections
    gemm(O, wo, Hi, IMG_SEQ, DIMN, DIMN, false);
    gemm(O + (size_t)IMG_SEQ * DIMN, wo_t, out + (size_t)BLOCKN * DIMN,
         TXT_SEQ, DIMN, DIMN, false);

    // post-projection LoRA on h_i (cond rows only)
    gemm(Hi + (size_t)BLOCKN * DIMN, p_down, Lp, CONDN, RANKN, DIMN, false);
    gemm(Lp, p_up, Hi + (size_t)BLOCKN * DIMN, CONDN, DIMN, RANKN, true);

    // assemble outputs
    int tot = 2 * BLOCKN * DIMN;
    copyout_kernel<<<(tot + 255) / 256, 256>>>(Hi, out);
}

// round 3
// speedup vs baseline: 5.0105x; 2.6840x over previous
#include <cuda_runtime.h>
#include <math.h>

// ---------------- problem constants ----------------
#define DIMN 2048
#define HEADS 16
#define HD 128
#define RANKN 64
#define IMG_SEQ 2048
#define TXT_SEQ 128
#define SEQN 2176          // IMG_SEQ + TXT_SEQ
#define CONDN 1024
#define BLOCKN 1024        // IMG_SEQ - COND
#define SBSN 1152          // SEQ - COND
#define EPSV 1e-5f

// ---------------- device scratch (no allocation allowed) ----------------
__device__ float g_Q[SEQN * DIMN];
__device__ float g_K[SEQN * DIMN];
__device__ float g_V[SEQN * DIMN];
__device__ float g_O[SEQN * DIMN];
__device__ float g_Hx[SEQN * DIMN];
__device__ float g_part[8 * CONDN * 192];
__device__ float g_L[CONDN * 192];
__device__ float g_Lp[CONDN * RANKN];

// ---------------- helpers ----------------
__device__ __forceinline__ float to_tf32(float x) {
    unsigned u;
    asm("cvt.rna.tf32.f32 %0, %1;" : "=r"(u) : "f"(x));
    return __uint_as_float(u);
}

__device__ __forceinline__ void mma_tf32(float c[4], const float a[4], const float b[2]) {
    asm volatile(
        "mma.sync.aligned.m16n8k8.row.col.f32.tf32.tf32.f32 "
        "{%0,%1,%2,%3}, {%4,%5,%6,%7}, {%8,%9}, {%0,%1,%2,%3};"
        : "+f"(c[0]), "+f"(c[1]), "+f"(c[2]), "+f"(c[3])
        : "r"(__float_as_uint(a[0])), "r"(__float_as_uint(a[1])),
          "r"(__float_as_uint(a[2])), "r"(__float_as_uint(a[3])),
          "r"(__float_as_uint(b[0])), "r"(__float_as_uint(b[1])));
}

// ============ dual-weight projection GEMM: C[r] = A[r] @ Wsel(r)^T ============
// M multiple of 128 (grid.y*128), N mult of 128, K mult of 32. No bounds checks.
// Rows < Msplit use (A1, W1); rows >= Msplit use (A2, W2).
__global__ __launch_bounds__(256) void proj_gemm(const float* __restrict__ A1,
                                                 const float* __restrict__ A2,
                                                 const float* __restrict__ W1,
                                                 const float* __restrict__ W2,
                                                 float* __restrict__ C,
                                                 int Msplit, int N, int K) {
    constexpr int BK = 32, LD = 36;
    __shared__ float As[128 * LD];
    __shared__ float Bs[128 * LD];

    const int tid = threadIdx.x;
    const int lane = tid & 31;
    const int warp = tid >> 5;
    const int wm = warp & 3;
    const int wn = warp >> 2;
    const int row0 = blockIdx.y * 128;
    const int col0 = blockIdx.x * 128;

    const float* A = (row0 < Msplit) ? A1 + (size_t)row0 * K
                                     : A2 + (size_t)(row0 - Msplit) * K;
    const float* W = (row0 < Msplit) ? W1 : W2;

    float c[2][8][4];
#pragma unroll
    for (int i = 0; i < 2; i++)
#pragma unroll
        for (int j = 0; j < 8; j++)
#pragma unroll
            for (int r = 0; r < 4; r++) c[i][j][r] = 0.f;

    const int lrow = lane >> 2;
    const int lcol = lane & 3;

    for (int k0 = 0; k0 < K; k0 += BK) {
#pragma unroll
        for (int f = 0; f < 4; f++) {
            int id = tid + f * 256;
            int r = id >> 3;
            int kq = (id & 7) << 2;
            float4 va = *(const float4*)&A[(size_t)r * K + k0 + kq];
            float* dst = &As[r * LD + kq];
            dst[0] = to_tf32(va.x); dst[1] = to_tf32(va.y);
            dst[2] = to_tf32(va.z); dst[3] = to_tf32(va.w);
            float4 vb = *(const float4*)&W[(size_t)(col0 + r) * K + k0 + kq];
            float* dstb = &Bs[r * LD + kq];
            dstb[0] = to_tf32(vb.x); dstb[1] = to_tf32(vb.y);
            dstb[2] = to_tf32(vb.z); dstb[3] = to_tf32(vb.w);
        }
        __syncthreads();
#pragma unroll
        for (int ks = 0; ks < BK / 8; ks++) {
            const int kb = ks * 8;
            float a[2][4];
#pragma unroll
            for (int mi = 0; mi < 2; mi++) {
                int ar = wm * 32 + mi * 16 + lrow;
                a[mi][0] = As[ar * LD + kb + lcol];
                a[mi][1] = As[(ar + 8) * LD + kb + lcol];
                a[mi][2] = As[ar * LD + kb + lcol + 4];
                a[mi][3] = As[(ar + 8) * LD + kb + lcol + 4];
            }
            float b[8][2];
#pragma unroll
            for (int ni = 0; ni < 8; ni++) {
                int br = wn * 64 + ni * 8 + lrow;
                b[ni][0] = Bs[br * LD + kb + lcol];
                b[ni][1] = Bs[br * LD + kb + lcol + 4];
            }
#pragma unroll
            for (int mi = 0; mi < 2; mi++)
#pragma unroll
                for (int ni = 0; ni < 8; ni++)
                    mma_tf32(c[mi][ni], a[mi], b[ni]);
        }
        __syncthreads();
    }

#pragma unroll
    for (int mi = 0; mi < 2; mi++)
#pragma unroll
        for (int ni = 0; ni < 8; ni++) {
            int gr = row0 + wm * 32 + mi * 16 + lrow;
            int gc = col0 + wn * 64 + ni * 8 + lcol * 2;
            *(float2*)&C[(size_t)gr * N + gc] =
                make_float2(c[mi][ni][0], c[mi][ni][1]);
            *(float2*)&C[(size_t)(gr + 8) * N + gc] =
                make_float2(c[mi][ni][2], c[mi][ni][3]);
        }
}

// ============ LoRA up-projection: C[M,N] += A[M,K;lda] @ W[N,K]^T ============
__global__ __launch_bounds__(256) void up_gemm_acc(const float* __restrict__ A,
                                                   int lda,
                                                   const float* __restrict__ W,
                                                   float* __restrict__ C,
                                                   int N, int K) {
    constexpr int BK = 32, LD = 36;
    __shared__ float As[128 * LD];
    __shared__ float Bs[128 * LD];

    const int tid = threadIdx.x;
    const int lane = tid & 31;
    const int warp = tid >> 5;
    const int wm = warp & 3;
    const int wn = warp >> 2;
    const int row0 = blockIdx.y * 128;
    const int col0 = blockIdx.x * 128;

    float c[2][8][4];
#pragma unroll
    for (int i = 0; i < 2; i++)
#pragma unroll
        for (int j = 0; j < 8; j++)
#pragma unroll
            for (int r = 0; r < 4; r++) c[i][j][r] = 0.f;

    const int lrow = lane >> 2;
    const int lcol = lane & 3;

    for (int k0 = 0; k0 < K; k0 += BK) {
#pragma unroll
        for (int f = 0; f < 4; f++) {
            int id = tid + f * 256;
            int r = id >> 3;
            int kq = (id & 7) << 2;
            float4 va = *(const float4*)&A[(size_t)(row0 + r) * lda + k0 + kq];
            float* dst = &As[r * LD + kq];
            dst[0] = to_tf32(va.x); dst[1] = to_tf32(va.y);
            dst[2] = to_tf32(va.z); dst[3] = to_tf32(va.w);
            float4 vb = *(const float4*)&W[(size_t)(col0 + r) * K + k0 + kq];
            float* dstb = &Bs[r * LD + kq];
            dstb[0] = to_tf32(vb.x); dstb[1] = to_tf32(vb.y);
            dstb[2] = to_tf32(vb.z); dstb[3] = to_tf32(vb.w);
        }
        __syncthreads();
#pragma unroll
        for (int ks = 0; ks < BK / 8; ks++) {
            const int kb = ks * 8;
            float a[2][4];
#pragma unroll
            for (int mi = 0; mi < 2; mi++) {
                int ar = wm * 32 + mi * 16 + lrow;
                a[mi][0] = As[ar * LD + kb + lcol];
                a[mi][1] = As[(ar + 8) * LD + kb + lcol];
                a[mi][2] = As[ar * LD + kb + lcol + 4];
                a[mi][3] = As[(ar + 8) * LD + kb + lcol + 4];
            }
            float b[8][2];
#pragma unroll
            for (int ni = 0; ni < 8; ni++) {
                int br = wn * 64 + ni * 8 + lrow;
                b[ni][0] = Bs[br * LD + kb + lcol];
                b[ni][1] = Bs[br * LD + kb + lcol + 4];
            }
#pragma unroll
            for (int mi = 0; mi < 2; mi++)
#pragma unroll
                for (int ni = 0; ni < 8; ni++)
                    mma_tf32(c[mi][ni], a[mi], b[ni]);
        }
        __syncthreads();
    }

#pragma unroll
    for (int mi = 0; mi < 2; mi++)
#pragma unroll
        for (int ni = 0; ni < 8; ni++) {
            int gr = row0 + wm * 32 + mi * 16 + lrow;
            int gc = col0 + wn * 64 + ni * 8 + lcol * 2;
            float2* p0 = (float2*)&C[(size_t)gr * N + gc];
            float2* p1 = (float2*)&C[(size_t)(gr + 8) * N + gc];
            float2 o0 = *p0, o1 = *p1;
            o0.x += c[mi][ni][0]; o0.y += c[mi][ni][1];
            o1.x += c[mi][ni][2]; o1.y += c[mi][ni][3];
            *p0 = o0; *p1 = o1;
        }
}

// ============ split-K LoRA down-projection (up to 3 fused weights) ============
// grid (ncb, M/128, 8). part[s][M][Ntot] partials; Kchunk = K/8.
__global__ __launch_bounds__(256) void down_gemm(const float* __restrict__ A,
                                                 const float* __restrict__ w0,
                                                 const float* __restrict__ w1,
                                                 const float* __restrict__ w2,
                                                 float* __restrict__ part,
                                                 int M, int Ntot, int Kfull) {
    constexpr int LD = 36;
    __shared__ float As[128 * LD];
    __shared__ float Ws[64 * LD];

    const int cb = blockIdx.x, mb = blockIdx.y, sp = blockIdx.z;
    const int Kc = Kfull >> 3;
    const int kbase = sp * Kc;
    const float* W = (cb == 0) ? w0 : (cb == 1 ? w1 : w2);

    const int tid = threadIdx.x;
    const int lane = tid & 31;
    const int warp = tid >> 5;
    const int wm = warp & 3;       // 32-row strip
    const int wn = warp >> 2;      // 32-col strip (of 64)
    const int lrow = lane >> 2;
    const int lcol = lane & 3;

    float c[2][4][4];
#pragma unroll
    for (int i = 0; i < 2; i++)
#pragma unroll
        for (int j = 0; j < 4; j++)
#pragma unroll
            for (int r = 0; r < 4; r++) c[i][j][r] = 0.f;

    for (int k0 = 0; k0 < Kc; k0 += 32) {
#pragma unroll
        for (int f = 0; f < 4; f++) {
            int id = tid + f * 256;
            int r = id >> 3;
            int kq = (id & 7) << 2;
            float4 va = *(const float4*)&A[(size_t)(mb * 128 + r) * Kfull + kbase + k0 + kq];
            float* dst = &As[r * LD + kq];
            dst[0] = to_tf32(va.x); dst[1] = to_tf32(va.y);
            dst[2] = to_tf32(va.z); dst[3] = to_tf32(va.w);
        }
#pragma unroll
        for (int f = 0; f < 2; f++) {
            int id = tid + f * 256;
            int r = id >> 3;          // 0..63
            int kq = (id & 7) << 2;
            float4 vb = *(const float4*)&W[(size_t)r * Kfull + kbase + k0 + kq];
            float* dst = &Ws[r * LD + kq];
            dst[0] = to_tf32(vb.x); dst[1] = to_tf32(vb.y);
            dst[2] = to_tf32(vb.z); dst[3] = to_tf32(vb.w);
        }
        __syncthreads();
#pragma unroll
        for (int ks = 0; ks < 4; ks++) {
            const int kb = ks * 8;
            float a[2][4];
#pragma unroll
            for (int mi = 0; mi < 2; mi++) {
                int ar = wm * 32 + mi * 16 + lrow;
                a[mi][0] = As[ar * LD + kb + lcol];
                a[mi][1] = As[(ar + 8) * LD + kb + lcol];
                a[mi][2] = As[ar * LD + kb + lcol + 4];
                a[mi][3] = As[(ar + 8) * LD + kb + lcol + 4];
            }
            float b[4][2];
#pragma unroll
            for (int ni = 0; ni < 4; ni++) {
                int br = wn * 32 + ni * 8 + lrow;
                b[ni][0] = Ws[br * LD + kb + lcol];
                b[ni][1] = Ws[br * LD + kb + lcol + 4];
            }
#pragma unroll
            for (int mi = 0; mi < 2; mi++)
#pragma unroll
                for (int ni = 0; ni < 4; ni++)
                    mma_tf32(c[mi][ni], a[mi], b[ni]);
        }
        __syncthreads();
    }

    float* base = part + (size_t)sp * M * Ntot;
#pragma unroll
    for (int mi = 0; mi < 2; mi++)
#pragma unroll
        for (int ni = 0; ni < 4; ni++) {
            int gr = mb * 128 + wm * 32 + mi * 16 + lrow;
            int gc = cb * 64 + wn * 32 + ni * 8 + lcol * 2;
            *(float2*)&base[(size_t)gr * Ntot + gc] =
                make_float2(c[mi][ni][0], c[mi][ni][1]);
            *(float2*)&base[(size_t)(gr + 8) * Ntot + gc] =
                make_float2(c[mi][ni][2], c[mi][ni][3]);
        }
}

__global__ void reduce8_kernel(const float* __restrict__ part,
                               float* __restrict__ out, int len) {
    int i = blockIdx.x * blockDim.x + threadIdx.x;
    if (i >= len) return;
    float v = 0.f;
#pragma unroll
    for (int s = 0; s < 8; s++) v += part[(size_t)s * len + i];
    out[i] = v;
}

// ---------------- fused RMS-norm (over DIM) + rope for Q and K ----------------
__global__ __launch_bounds__(256) void rmsrope_kernel(
    float* __restrict__ Q, float* __restrict__ K,
    const float* __restrict__ rope,
    const float* __restrict__ gq, const float* __restrict__ gk,
    const float* __restrict__ gqt, const float* __restrict__ gkt) {
    const int row = blockIdx.x;
    const int tid = threadIdx.x;
    __shared__ float sbuf[18];

    float* qrow = Q + (size_t)row * DIMN;
    float* krow = K + (size_t)row * DIMN;

    float sq = 0.f, sk = 0.f;
    for (int c4 = tid; c4 < DIMN / 4; c4 += 256) {
        float4 q = *(const float4*)&qrow[c4 * 4];
        sq += q.x * q.x + q.y * q.y + q.z * q.z + q.w * q.w;
        float4 kk = *(const float4*)&krow[c4 * 4];
        sk += kk.x * kk.x + kk.y * kk.y + kk.z * kk.z + kk.w * kk.w;
    }
#pragma unroll
    for (int o = 16; o > 0; o >>= 1) {
        sq += __shfl_xor_sync(0xffffffffu, sq, o);
        sk += __shfl_xor_sync(0xffffffffu, sk, o);
    }
    int w = tid >> 5;
    if ((tid & 31) == 0) { sbuf[w] = sq; sbuf[8 + w] = sk; }
    __syncthreads();
    if (tid == 0) {
        float a = 0.f, b = 0.f;
        for (int i = 0; i < 8; i++) { a += sbuf[i]; b += sbuf[8 + i]; }
        sbuf[16] = a; sbuf[17] = b;
    }
    __syncthreads();
    const float invq = rsqrtf(sbuf[16] / (float)DIMN + EPSV);
    const float invk = rsqrtf(sbuf[17] / (float)DIMN + EPSV);
    const float* gQ = (row < IMG_SEQ) ? gq : gqt;
    const float* gK = (row < IMG_SEQ) ? gk : gkt;
    const float* rp = rope + (size_t)row * 256;

    for (int pi = tid; pi < DIMN / 2; pi += 256) {
        int c0 = pi * 2;
        int j = pi & 63;
        float4 r = *(const float4*)&rp[j * 4];
        float x0 = qrow[c0] * invq * gQ[c0];
        float x1 = qrow[c0 + 1] * invq * gQ[c0 + 1];
        qrow[c0]     = r.x * x0 + r.y * x1;
        qrow[c0 + 1] = r.z * x0 + r.w * x1;
        float y0 = krow[c0] * invk * gK[c0];
        float y1 = krow[c0 + 1] * invk * gK[c0 + 1];
        krow[c0]     = r.x * y0 + r.y * y1;
        krow[c0 + 1] = r.z * y0 + r.w * y1;
    }
}

// ---------------- tensor-core flash attention (tf32 mma) ----------------
// Br=128 (8 warps x 16 rows), Bc=64. Q fragments in registers (pre-scaled tf32).
#define FB_KS 0          // [64][132]
#define FB_VT 8448       // [128][68]  (V^T: d-major)
#define FB_PS 17152      // [128][68]
#define FB_FLOATS 25856
#define FB_BYTES (FB_FLOATS * 4)

__global__ __launch_bounds__(256) void flash_mma(const float* __restrict__ Q,
                                                 const float* __restrict__ K,
                                                 const float* __restrict__ V,
                                                 float* __restrict__ O) {
    extern __shared__ float sm[];
    float* Ks = sm + FB_KS;
    float* Vt = sm + FB_VT;
    float* Ps = sm + FB_PS;

    const int tid = threadIdx.x;
    const int lane = tid & 31;
    const int warp = tid >> 5;
    const int lrow = lane >> 2;
    const int lcol = lane & 3;
    const int qrow0 = blockIdx.x * 128;
    const size_t hoff = (size_t)blockIdx.y * HD;
    const float scale = 0.08838834764831844f;  // 1/sqrt(128)

    // Q fragments: 16 ksteps x 4 regs, pre-scaled + tf32-rounded
    float qa[16][4];
    {
        const float* qb = Q + (size_t)(qrow0 + warp * 16) * DIMN + hoff;
#pragma unroll
        for (int ks = 0; ks < 16; ks++) {
            int kb = ks * 8;
            qa[ks][0] = to_tf32(scale * qb[(size_t)lrow * DIMN + kb + lcol]);
            qa[ks][1] = to_tf32(scale * qb[(size_t)(lrow + 8) * DIMN + kb + lcol]);
            qa[ks][2] = to_tf32(scale * qb[(size_t)lrow * DIMN + kb + lcol + 4]);
            qa[ks][3] = to_tf32(scale * qb[(size_t)(lrow + 8) * DIMN + kb + lcol + 4]);
        }
    }

    float o[16][4];
#pragma unroll
    for (int ni = 0; ni < 16; ni++)
#pragma unroll
        for (int r = 0; r < 4; r++) o[ni][r] = 0.f;
    float m0 = -INFINITY, m1 = -INFINITY, l0 = 0.f, l1 = 0.f;

    const int kt0 = (qrow0 >= SBSN) ? (SBSN / 64) : 0;

    for (int kt = kt0; kt < SEQN / 64; kt++) {
        const int kr0 = kt * 64;
        __syncthreads();
        // K tile -> Ks[64][132] (tf32), row-major
#pragma unroll
        for (int f = 0; f < 2; f++) {
            int id = tid + f * 256;           // 0..511 -> wait need 2048 items
            (void)id;
        }
#pragma unroll
        for (int f = 0; f < 8; f++) {
            int id = tid + f * 256;           // 0..2047
            int r = id >> 5;                  // 0..63
            int k4 = (id & 31) << 2;          // 0..124
            float4 v = *(const float4*)&K[(size_t)(kr0 + r) * DIMN + hoff + k4];
            float4 t = make_float4(to_tf32(v.x), to_tf32(v.y), to_tf32(v.z), to_tf32(v.w));
            *(float4*)&Ks[r * 132 + k4] = t;
        }
        // V tile -> Vt[d][j] transposed (tf32)
#pragma unroll
        for (int f = 0; f < 8; f++) {
            int id = tid + f * 256;           // 0..2047
            int j = id & 63;
            int d4 = (id >> 6) << 2;          // 0..124
            float4 v = *(const float4*)&V[(size_t)(kr0 + j) * DIMN + hoff + d4];
            Vt[(d4 + 0) * 68 + j] = to_tf32(v.x);
            Vt[(d4 + 1) * 68 + j] = to_tf32(v.y);
            Vt[(d4 + 2) * 68 + j] = to_tf32(v.z);
            Vt[(d4 + 3) * 68 + j] = to_tf32(v.w);
        }
        __syncthreads();

        // S = Q @ K^T : warp tile 16x64 (8 ntiles), k = 128 (16 ksteps)
        float s[8][4];
#pragma unroll
        for (int ni = 0; ni < 8; ni++)
#pragma unroll
            for (int r = 0; r < 4; r++) s[ni][r] = 0.f;
#pragma unroll
        for (int ks = 0; ks < 16; ks++) {
            const int kb = ks * 8;
#pragma unroll
            for (int ni = 0; ni < 8; ni++) {
                float b[2];
                b[0] = Ks[(ni * 8 + lrow) * 132 + kb + lcol];
                b[1] = Ks[(ni * 8 + lrow) * 132 + kb + lcol + 4];
                mma_tf32(s[ni], qa[ks], b);
            }
        }

        // online softmax (warp-local; lanes lcol 0..3 share a row)
        float mt0 = -INFINITY, mt1 = -INFINITY;
#pragma unroll
        for (int ni = 0; ni < 8; ni++) {
            mt0 = fmaxf(mt0, fmaxf(s[ni][0], s[ni][1]));
            mt1 = fmaxf(mt1, fmaxf(s[ni][2], s[ni][3]));
        }
#pragma unroll
        for (int off = 1; off <= 2; off <<= 1) {
            mt0 = fmaxf(mt0, __shfl_xor_sync(0xffffffffu, mt0, off));
            mt1 = fmaxf(mt1, __shfl_xor_sync(0xffffffffu, mt1, off));
        }
        float mn0 = fmaxf(m0, mt0), mn1 = fmaxf(m1, mt1);
        float corr0 = __expf(m0 - mn0), corr1 = __expf(m1 - mn1);
        m0 = mn0; m1 = mn1;

        float ps0 = 0.f, ps1 = 0.f;
#pragma unroll
        for (int ni = 0; ni < 8; ni++) {
            float p0 = to_tf32(__expf(s[ni][0] - mn0));
            float p1 = to_tf32(__expf(s[ni][1] - mn0));
            float p2 = to_tf32(__expf(s[ni][2] - mn1));
            float p3 = to_tf32(__expf(s[ni][3] - mn1));
            ps0 += p0 + p1; ps1 += p2 + p3;
            int col = ni * 8 + lcol * 2;
            *(float2*)&Ps[(warp * 16 + lrow) * 68 + col] = make_float2(p0, p1);
            *(float2*)&Ps[(warp * 16 + lrow + 8) * 68 + col] = make_float2(p2, p3);
        }
#pragma unroll
        for (int off = 1; off <= 2; off <<= 1) {
            ps0 += __shfl_xor_sync(0xffffffffu, ps0, off);
            ps1 += __shfl_xor_sync(0xffffffffu, ps1, off);
        }
        l0 = l0 * corr0 + ps0;
        l1 = l1 * corr1 + ps1;
#pragma unroll
        for (int ni = 0; ni < 16; ni++) {
            o[ni][0] *= corr0; o[ni][1] *= corr0;
            o[ni][2] *= corr1; o[ni][3] *= corr1;
        }
        __syncwarp();

        // O += P @ V : warp tile 16x128 (16 ntiles), k = 64 (8 ksteps)
#pragma unroll
        for (int ks = 0; ks < 8; ks++) {
            const int kb = ks * 8;
            float a[4];
            a[0] = Ps[(warp * 16 + lrow) * 68 + kb + lcol];
            a[1] = Ps[(warp * 16 + lrow + 8) * 68 + kb + lcol];
            a[2] = Ps[(warp * 16 + lrow) * 68 + kb + lcol + 4];
            a[3] = Ps[(warp * 16 + lrow + 8) * 68 + kb + lcol + 4];
#pragma unroll
            for (int ni = 0; ni < 16; ni++) {
                float b[2];
                b[0] = Vt[(ni * 8 + lrow) * 68 + kb + lcol];
                b[1] = Vt[(ni * 8 + lrow) * 68 + kb + lcol + 4];
                mma_tf32(o[ni], a, b);
            }
        }
    }

    // epilogue
    const float inv0 = 1.f / l0, inv1 = 1.f / l1;
    const int gr0 = qrow0 + warp * 16 + lrow;
#pragma unroll
    for (int ni = 0; ni < 16; ni++) {
        int gc = ni * 8 + lcol * 2;
        *(float2*)&O[(size_t)gr0 * DIMN + hoff + gc] =
            make_float2(o[ni][0] * inv0, o[ni][1] * inv0);
        *(float2*)&O[(size_t)(gr0 + 8) * DIMN + hoff + gc] =
            make_float2(o[ni][2] * inv1, o[ni][3] * inv1);
    }
}

// ---------------- output assembly: [h_img | h_t | cond] from Hx ----------------
__global__ void copyout_kernel(const float* __restrict__ Hx, float* __restrict__ out) {
    int i = blockIdx.x * blockDim.x + threadIdx.x;
    const int n1 = BLOCKN * DIMN;          // 1024*2048
    const int nt = TXT_SEQ * DIMN;         // 128*2048
    if (i >= SEQN * DIMN) return;
    if (i < n1)            out[i] = Hx[i];
    else if (i < n1 + nt)  out[i] = Hx[IMG_SEQ * DIMN + (i - n1)];
    else                   out[i] = Hx[n1 + (i - n1 - nt)];
}

// ---------------- launch ----------------
extern "C" void kernel_launch(void* const* d_in, const int* in_sizes, int n_in,
                              void* d_out, int out_size) {
    const float* img  = (const float*)d_in[0];
    const float* txt  = (const float*)d_in[1];
    const float* rope = (const float*)d_in[2];
    const float* wq   = (const float*)d_in[3];
    const float* wk   = (const float*)d_in[4];
    const float* wv   = (const float*)d_in[5];
    const float* wo   = (const float*)d_in[6];
    const float* wq_t = (const float*)d_in[7];
    const float* wk_t = (const float*)d_in[8];
    const float* wv_t = (const float*)d_in[9];
    const float* wo_t = (const float*)d_in[10];
    const float* gq   = (const float*)d_in[11];
    const float* gk   = (const float*)d_in[12];
    const float* gqt  = (const float*)d_in[13];
    const float* gkt  = (const float*)d_in[14];
    const float* q_down = (const float*)d_in[15];
    const float* q_up   = (const float*)d_in[16];
    const float* k_down = (const float*)d_in[17];
    const float* k_up   = (const float*)d_in[18];
    const float* v_down = (const float*)d_in[19];
    const float* v_up   = (const float*)d_in[20];
    const float* p_down = (const float*)d_in[21];
    const float* p_up   = (const float*)d_in[22];
    float* out = (float*)d_out;

    float *Q, *K, *V, *O, *Hx, *part, *L, *Lp;
    cudaGetSymbolAddress((void**)&Q,    g_Q);
    cudaGetSymbolAddress((void**)&K,    g_K);
    cudaGetSymbolAddress((void**)&V,    g_V);
    cudaGetSymbolAddress((void**)&O,    g_O);
    cudaGetSymbolAddress((void**)&Hx,   g_Hx);
    cudaGetSymbolAddress((void**)&part, g_part);
    cudaGetSymbolAddress((void**)&L,    g_L);
    cudaGetSymbolAddress((void**)&Lp,   g_Lp);

    const float* img_cond = img + (size_t)BLOCKN * DIMN;

    // 1) fused LoRA down-projections (q/k/v), split-K 8-way, then reduce
    down_gemm<<<dim3(3, CONDN / 128, 8), 256>>>(img_cond, q_down, k_down, v_down,
                                                part, CONDN, 192, DIMN);
    {
        int len = CONDN * 192;
        reduce8_kernel<<<(len + 255) / 256, 256>>>(part, L, len);
    }

    // 2) QKV projections, image+text batched (block-diagonal by row)
    dim3 pg(DIMN / 128, SEQN / 128);
    proj_gemm<<<pg, 256>>>(img, txt, wq, wq_t, Q, IMG_SEQ, DIMN, DIMN);
    proj_gemm<<<pg, 256>>>(img, txt, wk, wk_t, K, IMG_SEQ, DIMN, DIMN);
    proj_gemm<<<pg, 256>>>(img, txt, wv, wv_t, V, IMG_SEQ, DIMN, DIMN);

    // 3) LoRA up-projections accumulate into cond rows of Q/K/V
    dim3 ug(DIMN / 128, CONDN / 128);
    up_gemm_acc<<<ug, 256>>>(L + 0,   192, q_up, Q + (size_t)BLOCKN * DIMN, DIMN, RANKN);
    up_gemm_acc<<<ug, 256>>>(L + 64,  192, k_up, K + (size_t)BLOCKN * DIMN, DIMN, RANKN);
    up_gemm_acc<<<ug, 256>>>(L + 128, 192, v_up, V + (size_t)BLOCKN * DIMN, DIMN, RANKN);

    // 4) RMS + rope
    rmsrope_kernel<<<SEQN, 256>>>(Q, K, rope, gq, gk, gqt, gkt);

    // 5) flash attention (tensor cores)
    cudaFuncSetAttribute(flash_mma, cudaFuncAttributeMaxDynamicSharedMemorySize,
                         FB_BYTES);
    flash_mma<<<dim3(SEQN / 128, HEADS), 256, FB_BYTES>>>(Q, K, V, O);

    // 6) output projection, image+text batched
    proj_gemm<<<pg, 256>>>(O, O + (size_t)IMG_SEQ * DIMN, wo, wo_t, Hx,
                           IMG_SEQ, DIMN, DIMN);

    // 7) post-projection LoRA on cond rows of Hx
    down_gemm<<<dim3(1, CONDN / 128, 8), 256>>>(Hx + (size_t)BLOCKN * DIMN,
                                                p_down, p_down, p_down,
                                                part, CONDN, 64, DIMN);
    {
        int len = CONDN * 64;
        reduce8_kernel<<<(len + 255) / 256, 256>>>(part, Lp, len);
    }
    up_gemm_acc<<<ug, 256>>>(Lp, 64, p_up, Hx + (size_t)BLOCKN * DIMN, DIMN, RANKN);

    // 8) assemble outputs
    int tot = SEQN * DIMN;
    copyout_kernel<<<(tot + 255) / 256, 256>>>(Hx, out);
}

// round 4
// speedup vs baseline: 5.1364x; 1.0251x over previous
#include <cuda_runtime.h>
#include <math.h>

// ---------------- problem constants ----------------
#define DIMN 2048
#define HEADS 16
#define HD 128
#define RANKN 64
#define IMG_SEQ 2048
#define TXT_SEQ 128
#define SEQN 2176          // IMG_SEQ + TXT_SEQ
#define CONDN 1024
#define BLOCKN 1024        // IMG_SEQ - COND
#define SBSN 1152          // SEQ - COND
#define EPSV 1e-5f

// ---------------- device scratch (no allocation allowed) ----------------
__device__ float g_Q[SEQN * DIMN];
__device__ float g_K[SEQN * DIMN];
__device__ float g_V[SEQN * DIMN];
__device__ float g_O[SEQN * DIMN];
__device__ float g_Hx[SEQN * DIMN];
__device__ float g_part[8 * CONDN * 192];
__device__ float g_L[CONDN * 192];
__device__ float g_Lp[CONDN * RANKN];

// ---------------- helpers ----------------
__device__ __forceinline__ float to_tf32(float x) {
    unsigned u;
    asm("cvt.rna.tf32.f32 %0, %1;" : "=r"(u) : "f"(x));
    return __uint_as_float(u);
}

__device__ __forceinline__ void mma_tf32(float c[4], const float a[4], const float b[2]) {
    asm volatile(
        "mma.sync.aligned.m16n8k8.row.col.f32.tf32.tf32.f32 "
        "{%0,%1,%2,%3}, {%4,%5,%6,%7}, {%8,%9}, {%0,%1,%2,%3};"
        : "+f"(c[0]), "+f"(c[1]), "+f"(c[2]), "+f"(c[3])
        : "r"(__float_as_uint(a[0])), "r"(__float_as_uint(a[1])),
          "r"(__float_as_uint(a[2])), "r"(__float_as_uint(a[3])),
          "r"(__float_as_uint(b[0])), "r"(__float_as_uint(b[1])));
}

// store 8 k-values (lo: k0..3, hi: k4..7) pair-interleaved + tf32 rounded
__device__ __forceinline__ void sts_perm(float* d, float4 lo, float4 hi) {
    float4 v1 = make_float4(to_tf32(lo.x), to_tf32(hi.x), to_tf32(lo.y), to_tf32(hi.y));
    float4 v2 = make_float4(to_tf32(lo.z), to_tf32(hi.z), to_tf32(lo.w), to_tf32(hi.w));
    *(float4*)d = v1;
    *(float4*)(d + 4) = v2;
}

// ===== pipelined TF32 GEMM: C[r] = A_sel(r) @ W_sel(r,z)^T ====================
// 128x128 CTA tile, 4 warps (64x64 warp tiles), BK=32, dual-buffer smem,
// pair-permuted layout (LD=40) -> conflict-free LDS.64 fragments.
// grid.z selects among up to 3 (W1/W2, C) triples. All dims multiples of 128/32.
#define PLD 40
#define PSTAGE 10240   // floats per stage (A 128*40 + B 128*40)
#define PROJ_SMEM_BYTES (2 * PSTAGE * 4)

__global__ __launch_bounds__(128, 2) void proj_gemm3(
    const float* __restrict__ A1, const float* __restrict__ A2,
    const float* __restrict__ Wa0, const float* __restrict__ Wb0, float* __restrict__ C0,
    const float* __restrict__ Wa1, const float* __restrict__ Wb1, float* __restrict__ C1,
    const float* __restrict__ Wa2, const float* __restrict__ Wb2, float* __restrict__ C2,
    int Msplit, int N, int K) {
    extern __shared__ float smp[];

    const int tid = threadIdx.x;
    const int lane = tid & 31;
    const int warp = tid >> 5;
    const int wm = warp & 1;
    const int wn = warp >> 1;
    const int lrow = lane >> 2;
    const int lcol = lane & 3;
    const int row0 = blockIdx.y * 128;
    const int col0 = blockIdx.x * 128;
    const int z = blockIdx.z;

    const float* A = (row0 < Msplit) ? A1 + (size_t)row0 * K
                                     : A2 + (size_t)(row0 - Msplit) * K;
    const float* W;
    float* C;
    if (z == 0)      { W = (row0 < Msplit) ? Wa0 : Wb0; C = C0; }
    else if (z == 1) { W = (row0 < Msplit) ? Wa1 : Wb1; C = C1; }
    else             { W = (row0 < Msplit) ? Wa2 : Wb2; C = C2; }

    const int rB = tid >> 2;        // 0..31 base row
    const int gG = tid & 3;         // group (8 k's)

    float c[4][8][4];
#pragma unroll
    for (int i = 0; i < 4; i++)
#pragma unroll
        for (int j = 0; j < 8; j++)
#pragma unroll
            for (int r = 0; r < 4; r++) c[i][j][r] = 0.f;

    float4 pa[4][2], pb[4][2];

    // prologue: load + store stage 0
#pragma unroll
    for (int f = 0; f < 4; f++) {
        int r = rB + 32 * f;
        const float* ap = &A[(size_t)r * K + gG * 8];
        pa[f][0] = *(const float4*)ap; pa[f][1] = *(const float4*)(ap + 4);
        const float* wp = &W[(size_t)(col0 + r) * K + gG * 8];
        pb[f][0] = *(const float4*)wp; pb[f][1] = *(const float4*)(wp + 4);
    }
    {
        float* As = smp;
        float* Bs = smp + 128 * PLD;
#pragma unroll
        for (int f = 0; f < 4; f++) {
            int r = rB + 32 * f;
            sts_perm(&As[r * PLD + gG * 8], pa[f][0], pa[f][1]);
            sts_perm(&Bs[r * PLD + gG * 8], pb[f][0], pb[f][1]);
        }
    }

    const int iters = K / 32;
    for (int it = 0; it < iters; it++) {
        __syncthreads();
        float* cAs = smp + (it & 1) * PSTAGE;
        float* cBs = cAs + 128 * PLD;

        if (it + 1 < iters) {
            int k0 = (it + 1) * 32;
#pragma unroll
            for (int f = 0; f < 4; f++) {
                int r = rB + 32 * f;
                const float* ap = &A[(size_t)r * K + k0 + gG * 8];
                pa[f][0] = *(const float4*)ap; pa[f][1] = *(const float4*)(ap + 4);
                const float* wp = &W[(size_t)(col0 + r) * K + k0 + gG * 8];
                pb[f][0] = *(const float4*)wp; pb[f][1] = *(const float4*)(wp + 4);
            }
        }

#pragma unroll
        for (int ks = 0; ks < 4; ks++) {
            const int so = ks * 8 + 2 * lcol;
            float a[4][4];
#pragma unroll
            for (int mi = 0; mi < 4; mi++) {
                int ar = wm * 64 + mi * 16 + lrow;
                float2 a0 = *(const float2*)&cAs[ar * PLD + so];
                float2 a1 = *(const float2*)&cAs[(ar + 8) * PLD + so];
                a[mi][0] = a0.x; a[mi][1] = a1.x; a[mi][2] = a0.y; a[mi][3] = a1.y;
            }
            float b[8][2];
#pragma unroll
            for (int ni = 0; ni < 8; ni++) {
                int br = wn * 64 + ni * 8 + lrow;
                float2 b0 = *(const float2*)&cBs[br * PLD + so];
                b[ni][0] = b0.x; b[ni][1] = b0.y;
            }
#pragma unroll
            for (int mi = 0; mi < 4; mi++)
#pragma unroll
                for (int ni = 0; ni < 8; ni++)
                    mma_tf32(c[mi][ni], a[mi], b[ni]);
        }

        if (it + 1 < iters) {
            float* nAs = smp + ((it + 1) & 1) * PSTAGE;
            float* nBs = nAs + 128 * PLD;
#pragma unroll
            for (int f = 0; f < 4; f++) {
                int r = rB + 32 * f;
                sts_perm(&nAs[r * PLD + gG * 8], pa[f][0], pa[f][1]);
                sts_perm(&nBs[r * PLD + gG * 8], pb[f][0], pb[f][1]);
            }
        }
    }

#pragma unroll
    for (int mi = 0; mi < 4; mi++)
#pragma unroll
        for (int ni = 0; ni < 8; ni++) {
            int gr = row0 + wm * 64 + mi * 16 + lrow;
            int gc = col0 + wn * 64 + ni * 8 + lcol * 2;
            *(float2*)&C[(size_t)gr * N + gc] =
                make_float2(c[mi][ni][0], c[mi][ni][1]);
            *(float2*)&C[(size_t)(gr + 8) * N + gc] =
                make_float2(c[mi][ni][2], c[mi][ni][3]);
        }
}

// ============ LoRA up-projection: C[M,N] += A[M,K;lda] @ W[N,K]^T ============
__global__ __launch_bounds__(256) void up_gemm_acc(const float* __restrict__ A,
                                                   int lda,
                                                   const float* __restrict__ W,
                                                   float* __restrict__ C,
                                                   int N, int K) {
    constexpr int BK = 32, LD = 36;
    __shared__ float As[128 * LD];
    __shared__ float Bs[128 * LD];

    const int tid = threadIdx.x;
    const int lane = tid & 31;
    const int warp = tid >> 5;
    const int wm = warp & 3;
    const int wn = warp >> 2;
    const int row0 = blockIdx.y * 128;
    const int col0 = blockIdx.x * 128;

    float c[2][8][4];
#pragma unroll
    for (int i = 0; i < 2; i++)
#pragma unroll
        for (int j = 0; j < 8; j++)
#pragma unroll
            for (int r = 0; r < 4; r++) c[i][j][r] = 0.f;

    const int lrow = lane >> 2;
    const int lcol = lane & 3;

    for (int k0 = 0; k0 < K; k0 += BK) {
#pragma unroll
        for (int f = 0; f < 4; f++) {
            int id = tid + f * 256;
            int r = id >> 3;
            int kq = (id & 7) << 2;
            float4 va = *(const float4*)&A[(size_t)(row0 + r) * lda + k0 + kq];
            float* dst = &As[r * LD + kq];
            dst[0] = to_tf32(va.x); dst[1] = to_tf32(va.y);
            dst[2] = to_tf32(va.z); dst[3] = to_tf32(va.w);
            float4 vb = *(const float4*)&W[(size_t)(col0 + r) * K + k0 + kq];
            float* dstb = &Bs[r * LD + kq];
            dstb[0] = to_tf32(vb.x); dstb[1] = to_tf32(vb.y);
            dstb[2] = to_tf32(vb.z); dstb[3] = to_tf32(vb.w);
        }
        __syncthreads();
#pragma unroll
        for (int ks = 0; ks < BK / 8; ks++) {
            const int kb = ks * 8;
            float a[2][4];
#pragma unroll
            for (int mi = 0; mi < 2; mi++) {
                int ar = wm * 32 + mi * 16 + lrow;
                a[mi][0] = As[ar * LD + kb + lcol];
                a[mi][1] = As[(ar + 8) * LD + kb + lcol];
                a[mi][2] = As[ar * LD + kb + lcol + 4];
                a[mi][3] = As[(ar + 8) * LD + kb + lcol + 4];
            }
            float b[8][2];
#pragma unroll
            for (int ni = 0; ni < 8; ni++) {
                int br = wn * 64 + ni * 8 + lrow;
                b[ni][0] = Bs[br * LD + kb + lcol];
                b[ni][1] = Bs[br * LD + kb + lcol + 4];
            }
#pragma unroll
            for (int mi = 0; mi < 2; mi++)
#pragma unroll
                for (int ni = 0; ni < 8; ni++)
                    mma_tf32(c[mi][ni], a[mi], b[ni]);
        }
        __syncthreads();
    }

#pragma unroll
    for (int mi = 0; mi < 2; mi++)
#pragma unroll
        for (int ni = 0; ni < 8; ni++) {
            int gr = row0 + wm * 32 + mi * 16 + lrow;
            int gc = col0 + wn * 64 + ni * 8 + lcol * 2;
            float2* p0 = (float2*)&C[(size_t)gr * N + gc];
            float2* p1 = (float2*)&C[(size_t)(gr + 8) * N + gc];
            float2 o0 = *p0, o1 = *p1;
            o0.x += c[mi][ni][0]; o0.y += c[mi][ni][1];
            o1.x += c[mi][ni][2]; o1.y += c[mi][ni][3];
            *p0 = o0; *p1 = o1;
        }
}

// ============ split-K LoRA down-projection (up to 3 fused weights) ============
__global__ __launch_bounds__(256) void down_gemm(const float* __restrict__ A,
                                                 const float* __restrict__ w0,
                                                 const float* __restrict__ w1,
                                                 const float* __restrict__ w2,
                                                 float* __restrict__ part,
                                                 int M, int Ntot, int Kfull) {
    constexpr int LD = 36;
    __shared__ float As[128 * LD];
    __shared__ float Ws[64 * LD];

    const int cb = blockIdx.x, mb = blockIdx.y, sp = blockIdx.z;
    const int Kc = Kfull >> 3;
    const int kbase = sp * Kc;
    const float* W = (cb == 0) ? w0 : (cb == 1 ? w1 : w2);

    const int tid = threadIdx.x;
    const int lane = tid & 31;
    const int warp = tid >> 5;
    const int wm = warp & 3;
    const int wn = warp >> 2;
    const int lrow = lane >> 2;
    const int lcol = lane & 3;

    float c[2][4][4];
#pragma unroll
    for (int i = 0; i < 2; i++)
#pragma unroll
        for (int j = 0; j < 4; j++)
#pragma unroll
            for (int r = 0; r < 4; r++) c[i][j][r] = 0.f;

    for (int k0 = 0; k0 < Kc; k0 += 32) {
#pragma unroll
        for (int f = 0; f < 4; f++) {
            int id = tid + f * 256;
            int r = id >> 3;
            int kq = (id & 7) << 2;
            float4 va = *(const float4*)&A[(size_t)(mb * 128 + r) * Kfull + kbase + k0 + kq];
            float* dst = &As[r * LD + kq];
            dst[0] = to_tf32(va.x); dst[1] = to_tf32(va.y);
            dst[2] = to_tf32(va.z); dst[3] = to_tf32(va.w);
        }
#pragma unroll
        for (int f = 0; f < 2; f++) {
            int id = tid + f * 256;
            int r = id >> 3;
            int kq = (id & 7) << 2;
            float4 vb = *(const float4*)&W[(size_t)r * Kfull + kbase + k0 + kq];
            float* dst = &Ws[r * LD + kq];
            dst[0] = to_tf32(vb.x); dst[1] = to_tf32(vb.y);
            dst[2] = to_tf32(vb.z); dst[3] = to_tf32(vb.w);
        }
        __syncthreads();
#pragma unroll
        for (int ks = 0; ks < 4; ks++) {
            const int kb = ks * 8;
            float a[2][4];
#pragma unroll
            for (int mi = 0; mi < 2; mi++) {
                int ar = wm * 32 + mi * 16 + lrow;
                a[mi][0] = As[ar * LD + kb + lcol];
                a[mi][1] = As[(ar + 8) * LD + kb + lcol];
                a[mi][2] = As[ar * LD + kb + lcol + 4];
                a[mi][3] = As[(ar + 8) * LD + kb + lcol + 4];
            }
            float b[4][2];
#pragma unroll
            for (int ni = 0; ni < 4; ni++) {
                int br = wn * 32 + ni * 8 + lrow;
                b[ni][0] = Ws[br * LD + kb + lcol];
                b[ni][1] = Ws[br * LD + kb + lcol + 4];
            }
#pragma unroll
            for (int mi = 0; mi < 2; mi++)
#pragma unroll
                for (int ni = 0; ni < 4; ni++)
                    mma_tf32(c[mi][ni], a[mi], b[ni]);
        }
        __syncthreads();
    }

    float* base = part + (size_t)sp * M * Ntot;
#pragma unroll
    for (int mi = 0; mi < 2; mi++)
#pragma unroll
        for (int ni = 0; ni < 4; ni++) {
            int gr = mb * 128 + wm * 32 + mi * 16 + lrow;
            int gc = cb * 64 + wn * 32 + ni * 8 + lcol * 2;
            *(float2*)&base[(size_t)gr * Ntot + gc] =
                make_float2(c[mi][ni][0], c[mi][ni][1]);
            *(float2*)&base[(size_t)(gr + 8) * Ntot + gc] =
                make_float2(c[mi][ni][2], c[mi][ni][3]);
        }
}

__global__ void reduce8_kernel(const float* __restrict__ part,
                               float* __restrict__ out, int len) {
    int i = blockIdx.x * blockDim.x + threadIdx.x;
    if (i >= len) return;
    float v = 0.f;
#pragma unroll
    for (int s = 0; s < 8; s++) v += part[(size_t)s * len + i];
    out[i] = v;
}

// ---------------- fused RMS-norm (over DIM) + rope for Q and K ----------------
__global__ __launch_bounds__(256) void rmsrope_kernel(
    float* __restrict__ Q, float* __restrict__ K,
    const float* __restrict__ rope,
    const float* __restrict__ gq, const float* __restrict__ gk,
    const float* __restrict__ gqt, const float* __restrict__ gkt) {
    const int row = blockIdx.x;
    const int tid = threadIdx.x;
    __shared__ float sbuf[18];

    float* qrow = Q + (size_t)row * DIMN;
    float* krow = K + (size_t)row * DIMN;

    float sq = 0.f, sk = 0.f;
    for (int c4 = tid; c4 < DIMN / 4; c4 += 256) {
        float4 q = *(const float4*)&qrow[c4 * 4];
        sq += q.x * q.x + q.y * q.y + q.z * q.z + q.w * q.w;
        float4 kk = *(const float4*)&krow[c4 * 4];
        sk += kk.x * kk.x + kk.y * kk.y + kk.z * kk.z + kk.w * kk.w;
    }
#pragma unroll
    for (int o = 16; o > 0; o >>= 1) {
        sq += __shfl_xor_sync(0xffffffffu, sq, o);
        sk += __shfl_xor_sync(0xffffffffu, sk, o);
    }
    int w = tid >> 5;
    if ((tid & 31) == 0) { sbuf[w] = sq; sbuf[8 + w] = sk; }
    __syncthreads();
    if (tid == 0) {
        float a = 0.f, b = 0.f;
        for (int i = 0; i < 8; i++) { a += sbuf[i]; b += sbuf[8 + i]; }
        sbuf[16] = a; sbuf[17] = b;
    }
    __syncthreads();
    const float invq = rsqrtf(sbuf[16] / (float)DIMN + EPSV);
    const float invk = rsqrtf(sbuf[17] / (float)DIMN + EPSV);
    const float* gQ = (row < IMG_SEQ) ? gq : gqt;
    const float* gK = (row < IMG_SEQ) ? gk : gkt;
    const float* rp = rope + (size_t)row * 256;

    for (int pi = tid; pi < DIMN / 2; pi += 256) {
        int c0 = pi * 2;
        int j = pi & 63;
        float4 r = *(const float4*)&rp[j * 4];
        float x0 = qrow[c0] * invq * gQ[c0];
        float x1 = qrow[c0 + 1] * invq * gQ[c0 + 1];
        qrow[c0]     = r.x * x0 + r.y * x1;
        qrow[c0 + 1] = r.z * x0 + r.w * x1;
        float y0 = krow[c0] * invk * gK[c0];
        float y1 = krow[c0 + 1] * invk * gK[c0 + 1];
        krow[c0]     = r.x * y0 + r.y * y1;
        krow[c0 + 1] = r.z * y0 + r.w * y1;
    }
}

// ---------------- tensor-core flash attention (tf32 mma) ----------------
#define FB_KS 0          // [64][132]
#define FB_VT 8448       // [128][68]
#define FB_PS 17152      // [128][68]
#define FB_FLOATS 25856
#define FB_BYTES (FB_FLOATS * 4)

__global__ __launch_bounds__(256) void flash_mma(const float* __restrict__ Q,
                                                 const float* __restrict__ K,
                                                 const float* __restrict__ V,
                                                 float* __restrict__ O) {
    extern __shared__ float sm[];
    float* Ks = sm + FB_KS;
    float* Vt = sm + FB_VT;
    float* Ps = sm + FB_PS;

    const int tid = threadIdx.x;
    const int lane = tid & 31;
    const int warp = tid >> 5;
    const int lrow = lane >> 2;
    const int lcol = lane & 3;
    const int qrow0 = blockIdx.x * 128;
    const size_t hoff = (size_t)blockIdx.y * HD;
    const float scale = 0.08838834764831844f;

    float qa[16][4];
    {
        const float* qb = Q + (size_t)(qrow0 + warp * 16) * DIMN + hoff;
#pragma unroll
        for (int ks = 0; ks < 16; ks++) {
            int kb = ks * 8;
            qa[ks][0] = to_tf32(scale * qb[(size_t)lrow * DIMN + kb + lcol]);
            qa[ks][1] = to_tf32(scale * qb[(size_t)(lrow + 8) * DIMN + kb + lcol]);
            qa[ks][2] = to_tf32(scale * qb[(size_t)lrow * DIMN + kb + lcol + 4]);
            qa[ks][3] = to_tf32(scale * qb[(size_t)(lrow + 8) * DIMN + kb + lcol + 4]);
        }
    }

    float o[16][4];
#pragma unroll
    for (int ni = 0; ni < 16; ni++)
#pragma unroll
        for (int r = 0; r < 4; r++) o[ni][r] = 0.f;
    float m0 = -INFINITY, m1 = -INFINITY, l0 = 0.f, l1 = 0.f;

    const int kt0 = (qrow0 >= SBSN) ? (SBSN / 64) : 0;

    for (int kt = kt0; kt < SEQN / 64; kt++) {
        const int kr0 = kt * 64;
        __syncthreads();
#pragma unroll
        for (int f = 0; f < 8; f++) {
            int id = tid + f * 256;
            int r = id >> 5;
            int k4 = (id & 31) << 2;
            float4 v = *(const float4*)&K[(size_t)(kr0 + r) * DIMN + hoff + k4];
            float4 t = make_float4(to_tf32(v.x), to_tf32(v.y), to_tf32(v.z), to_tf32(v.w));
            *(float4*)&Ks[r * 132 + k4] = t;
        }
#pragma unroll
        for (int f = 0; f < 8; f++) {
            int id = tid + f * 256;
            int j = id & 63;
            int d4 = (id >> 6) << 2;
            float4 v = *(const float4*)&V[(size_t)(kr0 + j) * DIMN + hoff + d4];
            Vt[(d4 + 0) * 68 + j] = to_tf32(v.x);
            Vt[(d4 + 1) * 68 + j] = to_tf32(v.y);
            Vt[(d4 + 2) * 68 + j] = to_tf32(v.z);
            Vt[(d4 + 3) * 68 + j] = to_tf32(v.w);
        }
        __syncthreads();

        float s[8][4];
#pragma unroll
        for (int ni = 0; ni < 8; ni++)
#pragma unroll
            for (int r = 0; r < 4; r++) s[ni][r] = 0.f;
#pragma unroll
        for (int ks = 0; ks < 16; ks++) {
            const int kb = ks * 8;
#pragma unroll
            for (int ni = 0; ni < 8; ni++) {
                float b[2];
                b[0] = Ks[(ni * 8 + lrow) * 132 + kb + lcol];
                b[1] = Ks[(ni * 8 + lrow) * 132 + kb + lcol + 4];
                mma_tf32(s[ni], qa[ks], b);
            }
        }

        float mt0 = -INFINITY, mt1 = -INFINITY;
#pragma unroll
        for (int ni = 0; ni < 8; ni++) {
            mt0 = fmaxf(mt0, fmaxf(s[ni][0], s[ni][1]));
            mt1 = fmaxf(mt1, fmaxf(s[ni][2], s[ni][3]));
        }
#pragma unroll
        for (int off = 1; off <= 2; off <<= 1) {
            mt0 = fmaxf(mt0, __shfl_xor_sync(0xffffffffu, mt0, off));
            mt1 = fmaxf(mt1, __shfl_xor_sync(0xffffffffu, mt1, off));
        }
        float mn0 = fmaxf(m0, mt0), mn1 = fmaxf(m1, mt1);
        float corr0 = __expf(m0 - mn0), corr1 = __expf(m1 - mn1);
        m0 = mn0; m1 = mn1;

        float ps0 = 0.f, ps1 = 0.f;
#pragma unroll
        for (int ni = 0; ni < 8; ni++) {
            float p0 = to_tf32(__expf(s[ni][0] - mn0));
            float p1 = to_tf32(__expf(s[ni][1] - mn0));
            float p2 = to_tf32(__expf(s[ni][2] - mn1));
            float p3 = to_tf32(__expf(s[ni][3] - mn1));
            ps0 += p0 + p1; ps1 += p2 + p3;
            int col = ni * 8 + lcol * 2;
            *(float2*)&Ps[(warp * 16 + lrow) * 68 + col] = make_float2(p0, p1);
            *(float2*)&Ps[(warp * 16 + lrow + 8) * 68 + col] = make_float2(p2, p3);
        }
#pragma unroll
        for (int off = 1; off <= 2; off <<= 1) {
            ps0 += __shfl_xor_sync(0xffffffffu, ps0, off);
            ps1 += __shfl_xor_sync(0xffffffffu, ps1, off);
        }
        l0 = l0 * corr0 + ps0;
        l1 = l1 * corr1 + ps1;
#pragma unroll
        for (int ni = 0; ni < 16; ni++) {
            o[ni][0] *= corr0; o[ni][1] *= corr0;
            o[ni][2] *= corr1; o[ni][3] *= corr1;
        }
        __syncwarp();

#pragma unroll
        for (int ks = 0; ks < 8; ks++) {
            const int kb = ks * 8;
            float a[4];
            a[0] = Ps[(warp * 16 + lrow) * 68 + kb + lcol];
            a[1] = Ps[(warp * 16 + lrow + 8) * 68 + kb + lcol];
            a[2] = Ps[(warp * 16 + lrow) * 68 + kb + lcol + 4];
            a[3] = Ps[(warp * 16 + lrow + 8) * 68 + kb + lcol + 4];
#pragma unroll
            for (int ni = 0; ni < 16; ni++) {
                float b[2];
                b[0] = Vt[(ni * 8 + lrow) * 68 + kb + lcol];
                b[1] = Vt[(ni * 8 + lrow) * 68 + kb + lcol + 4];
                mma_tf32(o[ni], a, b);
            }
        }
    }

    const float inv0 = 1.f / l0, inv1 = 1.f / l1;
    const int gr0 = qrow0 + warp * 16 + lrow;
#pragma unroll
    for (int ni = 0; ni < 16; ni++) {
        int gc = ni * 8 + lcol * 2;
        *(float2*)&O[(size_t)gr0 * DIMN + hoff + gc] =
            make_float2(o[ni][0] * inv0, o[ni][1] * inv0);
        *(float2*)&O[(size_t)(gr0 + 8) * DIMN + hoff + gc] =
            make_float2(o[ni][2] * inv1, o[ni][3] * inv1);
    }
}

// ---------------- output assembly ----------------
__global__ void copyout_kernel(const float* __restrict__ Hx, float* __restrict__ out) {
    int i = blockIdx.x * blockDim.x + threadIdx.x;
    const int n1 = BLOCKN * DIMN;
    const int nt = TXT_SEQ * DIMN;
    if (i >= SEQN * DIMN) return;
    if (i < n1)            out[i] = Hx[i];
    else if (i < n1 + nt)  out[i] = Hx[IMG_SEQ * DIMN + (i - n1)];
    else                   out[i] = Hx[n1 + (i - n1 - nt)];
}

// ---------------- launch ----------------
extern "C" void kernel_launch(void* const* d_in, const int* in_sizes, int n_in,
                              void* d_out, int out_size) {
    const float* img  = (const float*)d_in[0];
    const float* txt  = (const float*)d_in[1];
    const float* rope = (const float*)d_in[2];
    const float* wq   = (const float*)d_in[3];
    const float* wk   = (const float*)d_in[4];
    const float* wv   = (const float*)d_in[5];
    const float* wo   = (const float*)d_in[6];
    const float* wq_t = (const float*)d_in[7];
    const float* wk_t = (const float*)d_in[8];
    const float* wv_t = (const float*)d_in[9];
    const float* wo_t = (const float*)d_in[10];
    const float* gq   = (const float*)d_in[11];
    const float* gk   = (const float*)d_in[12];
    const float* gqt  = (const float*)d_in[13];
    const float* gkt  = (const float*)d_in[14];
    const float* q_down = (const float*)d_in[15];
    const float* q_up   = (const float*)d_in[16];
    const float* k_down = (const float*)d_in[17];
    const float* k_up   = (const float*)d_in[18];
    const float* v_down = (const float*)d_in[19];
    const float* v_up   = (const float*)d_in[20];
    const float* p_down = (const float*)d_in[21];
    const float* p_up   = (const float*)d_in[22];
    float* out = (float*)d_out;

    float *Q, *K, *V, *O, *Hx, *part, *L, *Lp;
    cudaGetSymbolAddress((void**)&Q,    g_Q);
    cudaGetSymbolAddress((void**)&K,    g_K);
    cudaGetSymbolAddress((void**)&V,    g_V);
    cudaGetSymbolAddress((void**)&O,    g_O);
    cudaGetSymbolAddress((void**)&Hx,   g_Hx);
    cudaGetSymbolAddress((void**)&part, g_part);
    cudaGetSymbolAddress((void**)&L,    g_L);
    cudaGetSymbolAddress((void**)&Lp,   g_Lp);

    const float* img_cond = img + (size_t)BLOCKN * DIMN;

    cudaFuncSetAttribute(proj_gemm3, cudaFuncAttributeMaxDynamicSharedMemorySize,
                         PROJ_SMEM_BYTES);

    // 1) fused LoRA down-projections (q/k/v), split-K 8-way, then reduce
    down_gemm<<<dim3(3, CONDN / 128, 8), 256>>>(img_cond, q_down, k_down, v_down,
                                                part, CONDN, 192, DIMN);
    {
        int len = CONDN * 192;
        reduce8_kernel<<<(len + 255) / 256, 256>>>(part, L, len);
    }

    // 2) QKV projections in ONE launch (grid.z selects weight/output)
    proj_gemm3<<<dim3(DIMN / 128, SEQN / 128, 3), 128, PROJ_SMEM_BYTES>>>(
        img, txt,
        wq, wq_t, Q,
        wk, wk_t, K,
        wv, wv_t, V,
        IMG_SEQ, DIMN, DIMN);

    // 3) LoRA up-projections accumulate into cond rows of Q/K/V
    dim3 ug(DIMN / 128, CONDN / 128);
    up_gemm_acc<<<ug, 256>>>(L + 0,   192, q_up, Q + (size_t)BLOCKN * DIMN, DIMN, RANKN);
    up_gemm_acc<<<ug, 256>>>(L + 64,  192, k_up, K + (size_t)BLOCKN * DIMN, DIMN, RANKN);
    up_gemm_acc<<<ug, 256>>>(L + 128, 192, v_up, V + (size_t)BLOCKN * DIMN, DIMN, RANKN);

    // 4) RMS + rope
    rmsrope_kernel<<<SEQN, 256>>>(Q, K, rope, gq, gk, gqt, gkt);

    // 5) flash attention (tensor cores)
    cudaFuncSetAttribute(flash_mma, cudaFuncAttributeMaxDynamicSharedMemorySize,
                         FB_BYTES);
    flash_mma<<<dim3(SEQN / 128, HEADS), 256, FB_BYTES>>>(Q, K, V, O);

    // 6) output projection, image+text batched
    proj_gemm3<<<dim3(DIMN / 128, SEQN / 128, 1), 128, PROJ_SMEM_BYTES>>>(
        O, O + (size_t)IMG_SEQ * DIMN,
        wo, wo_t, Hx,
        wo, wo_t, Hx,
        wo, wo_t, Hx,
        IMG_SEQ, DIMN, DIMN);

    // 7) post-projection LoRA on cond rows of Hx
    down_gemm<<<dim3(1, CONDN / 128, 8), 256>>>(Hx + (size_t)BLOCKN * DIMN,
                                                p_down, p_down, p_down,
                                                part, CONDN, 64, DIMN);
    {
        int len = CONDN * 64;
        reduce8_kernel<<<(len + 255) / 256, 256>>>(part, Lp, len);
    }
    up_gemm_acc<<<ug, 256>>>(Lp, 64, p_up, Hx + (size_t)BLOCKN * DIMN, DIMN, RANKN);

    // 8) assemble outputs
    int tot = SEQN * DIMN;
    copyout_kernel<<<(tot + 255) / 256, 256>>>(Hx, out);
}

// round 6
// speedup vs baseline: 6.2022x; 1.2075x over previous
#include <cuda_runtime.h>
#include <cuda_fp16.h>
#include <math.h>
#include <stdint.h>

// ---------------- problem constants ----------------
#define DIMN 2048
#define HEADS 16
#define HD 128
#define RANKN 64
#define IMG_SEQ 2048
#define TXT_SEQ 128
#define SEQN 2176          // IMG_SEQ + TXT_SEQ
#define CONDN 1024
#define BLOCKN 1024        // IMG_SEQ - COND
#define SBSN 1152          // SEQ - COND
#define EPSV 1e-5f

// ---------------- device scratch (no allocation allowed) ----------------
__device__ float g_Q[SEQN * DIMN];
__device__ float g_K[SEQN * DIMN];
__device__ float g_V[SEQN * DIMN];
__device__ float g_O[SEQN * DIMN];
__device__ float g_Hx[SEQN * DIMN];
__device__ float g_part[8 * CONDN * 192];
__device__ float g_L[CONDN * 192];
__device__ float g_Lp[CONDN * RANKN];

// ---------------- helpers ----------------
__device__ __forceinline__ float to_tf32(float x) {
    unsigned u;
    asm("cvt.rna.tf32.f32 %0, %1;" : "=r"(u) : "f"(x));
    return __uint_as_float(u);
}

__device__ __forceinline__ uint32_t pack_h2(float x, float y) {
    __half2 h = __floats2half2_rn(x, y);
    return *(uint32_t*)&h;
}

__device__ __forceinline__ void mma_tf32(float c[4], const float a[4], const float b[2]) {
    asm volatile(
        "mma.sync.aligned.m16n8k8.row.col.f32.tf32.tf32.f32 "
        "{%0,%1,%2,%3}, {%4,%5,%6,%7}, {%8,%9}, {%0,%1,%2,%3};"
        : "+f"(c[0]), "+f"(c[1]), "+f"(c[2]), "+f"(c[3])
        : "r"(__float_as_uint(a[0])), "r"(__float_as_uint(a[1])),
          "r"(__float_as_uint(a[2])), "r"(__float_as_uint(a[3])),
          "r"(__float_as_uint(b[0])), "r"(__float_as_uint(b[1])));
}

__device__ __forceinline__ void mma_f16(float c[4], const uint32_t a[4],
                                        uint32_t b0, uint32_t b1) {
    asm volatile(
        "mma.sync.aligned.m16n8k16.row.col.f32.f16.f16.f32 "
        "{%0,%1,%2,%3}, {%4,%5,%6,%7}, {%8,%9}, {%0,%1,%2,%3};"
        : "+f"(c[0]), "+f"(c[1]), "+f"(c[2]), "+f"(c[3])
        : "r"(a[0]), "r"(a[1]), "r"(a[2]), "r"(a[3]),
          "r"(b0), "r"(b1));
}

#define HLD 40   // halves per smem row (pad: 20 words -> conflict-free frags)

// ===== fp16 projection GEMM: C[r] = A_sel(r) @ W_sel(r,z)^T ==================
// 128x128 CTA tile, 8 warps (32x64 warp tiles), BK=32 (2 k16-steps).
// grid.z selects among up to 3 (W1/W2, C) triples; rows >= Msplit use B-side.
__global__ __launch_bounds__(256, 2) void proj_gemm3h(
    const float* __restrict__ A1, const float* __restrict__ A2,
    const float* __restrict__ Wa0, const float* __restrict__ Wb0, float* __restrict__ C0,
    const float* __restrict__ Wa1, const float* __restrict__ Wb1, float* __restrict__ C1,
    const float* __restrict__ Wa2, const float* __restrict__ Wb2, float* __restrict__ C2,
    int Msplit, int N, int K) {
    __shared__ __half As[128 * HLD];
    __shared__ __half Bs[128 * HLD];

    const int tid = threadIdx.x;
    const int lane = tid & 31;
    const int warp = tid >> 5;
    const int wm = warp & 3;
    const int wn = warp >> 2;
    const int lrow = lane >> 2;
    const int lcol = lane & 3;
    const int row0 = blockIdx.y * 128;
    const int col0 = blockIdx.x * 128;
    const int z = blockIdx.z;

    const float* A = (row0 < Msplit) ? A1 + (size_t)row0 * K
                                     : A2 + (size_t)(row0 - Msplit) * K;
    const float* W;
    float* C;
    if (z == 0)      { W = (row0 < Msplit) ? Wa0 : Wb0; C = C0; }
    else if (z == 1) { W = (row0 < Msplit) ? Wa1 : Wb1; C = C1; }
    else             { W = (row0 < Msplit) ? Wa2 : Wb2; C = C2; }

    float c[2][8][4];
#pragma unroll
    for (int i = 0; i < 2; i++)
#pragma unroll
        for (int j = 0; j < 8; j++)
#pragma unroll
            for (int r = 0; r < 4; r++) c[i][j][r] = 0.f;

    for (int k0 = 0; k0 < K; k0 += 32) {
#pragma unroll
        for (int f = 0; f < 4; f++) {
            int id = tid + f * 256;        // 0..1023
            int r = id >> 3;               // 0..127
            int kq = (id & 7) << 2;        // 0,4,...,28
            float4 va = *(const float4*)&A[(size_t)r * K + k0 + kq];
            uint2 ua = make_uint2(pack_h2(va.x, va.y), pack_h2(va.z, va.w));
            *(uint2*)&As[r * HLD + kq] = ua;
            float4 vb = *(const float4*)&W[(size_t)(col0 + r) * K + k0 + kq];
            uint2 ub = make_uint2(pack_h2(vb.x, vb.y), pack_h2(vb.z, vb.w));
            *(uint2*)&Bs[r * HLD + kq] = ub;
        }
        __syncthreads();

#pragma unroll
        for (int ks = 0; ks < 2; ks++) {
            const int kb = ks * 16 + 2 * lcol;
            uint32_t a[2][4];
#pragma unroll
            for (int mi = 0; mi < 2; mi++) {
                int ar = wm * 32 + mi * 16 + lrow;
                a[mi][0] = *(const uint32_t*)&As[ar * HLD + kb];
                a[mi][1] = *(const uint32_t*)&As[(ar + 8) * HLD + kb];
                a[mi][2] = *(const uint32_t*)&As[ar * HLD + kb + 8];
                a[mi][3] = *(const uint32_t*)&As[(ar + 8) * HLD + kb + 8];
            }
            uint32_t b[8][2];
#pragma unroll
            for (int ni = 0; ni < 8; ni++) {
                int br = wn * 64 + ni * 8 + lrow;
                b[ni][0] = *(const uint32_t*)&Bs[br * HLD + kb];
                b[ni][1] = *(const uint32_t*)&Bs[br * HLD + kb + 8];
            }
#pragma unroll
            for (int mi = 0; mi < 2; mi++)
#pragma unroll
                for (int ni = 0; ni < 8; ni++)
                    mma_f16(c[mi][ni], a[mi], b[ni][0], b[ni][1]);
        }
        __syncthreads();
    }

#pragma unroll
    for (int mi = 0; mi < 2; mi++)
#pragma unroll
        for (int ni = 0; ni < 8; ni++) {
            int gr = row0 + wm * 32 + mi * 16 + lrow;
            int gc = col0 + wn * 64 + ni * 8 + lcol * 2;
            *(float2*)&C[(size_t)gr * N + gc] =
                make_float2(c[mi][ni][0], c[mi][ni][1]);
            *(float2*)&C[(size_t)(gr + 8) * N + gc] =
                make_float2(c[mi][ni][2], c[mi][ni][3]);
        }
}

// ===== fp16 LoRA up-projection: C[M,N] += A[M,K;lda] @ W[N,K]^T ==============
__global__ __launch_bounds__(256) void up_gemm_acc_h(const float* __restrict__ A,
                                                     int lda,
                                                     const float* __restrict__ W,
                                                     float* __restrict__ C,
                                                     int N, int K) {
    __shared__ __half As[128 * HLD];
    __shared__ __half Bs[128 * HLD];

    const int tid = threadIdx.x;
    const int lane = tid & 31;
    const int warp = tid >> 5;
    const int wm = warp & 3;
    const int wn = warp >> 2;
    const int lrow = lane >> 2;
    const int lcol = lane & 3;
    const int row0 = blockIdx.y * 128;
    const int col0 = blockIdx.x * 128;

    float c[2][8][4];
#pragma unroll
    for (int i = 0; i < 2; i++)
#pragma unroll
        for (int j = 0; j < 8; j++)
#pragma unroll
            for (int r = 0; r < 4; r++) c[i][j][r] = 0.f;

    for (int k0 = 0; k0 < K; k0 += 32) {
#pragma unroll
        for (int f = 0; f < 4; f++) {
            int id = tid + f * 256;
            int r = id >> 3;
            int kq = (id & 7) << 2;
            float4 va = *(const float4*)&A[(size_t)(row0 + r) * lda + k0 + kq];
            *(uint2*)&As[r * HLD + kq] =
                make_uint2(pack_h2(va.x, va.y), pack_h2(va.z, va.w));
            float4 vb = *(const float4*)&W[(size_t)(col0 + r) * K + k0 + kq];
            *(uint2*)&Bs[r * HLD + kq] =
                make_uint2(pack_h2(vb.x, vb.y), pack_h2(vb.z, vb.w));
        }
        __syncthreads();

#pragma unroll
        for (int ks = 0; ks < 2; ks++) {
            const int kb = ks * 16 + 2 * lcol;
            uint32_t a[2][4];
#pragma unroll
            for (int mi = 0; mi < 2; mi++) {
                int ar = wm * 32 + mi * 16 + lrow;
                a[mi][0] = *(const uint32_t*)&As[ar * HLD + kb];
                a[mi][1] = *(const uint32_t*)&As[(ar + 8) * HLD + kb];
                a[mi][2] = *(const uint32_t*)&As[ar * HLD + kb + 8];
                a[mi][3] = *(const uint32_t*)&As[(ar + 8) * HLD + kb + 8];
            }
            uint32_t b[8][2];
#pragma unroll
            for (int ni = 0; ni < 8; ni++) {
                int br = wn * 64 + ni * 8 + lrow;
                b[ni][0] = *(const uint32_t*)&Bs[br * HLD + kb];
                b[ni][1] = *(const uint32_t*)&Bs[br * HLD + kb + 8];
            }
#pragma unroll
            for (int mi = 0; mi < 2; mi++)
#pragma unroll
                for (int ni = 0; ni < 8; ni++)
                    mma_f16(c[mi][ni], a[mi], b[ni][0], b[ni][1]);
        }
        __syncthreads();
    }

#pragma unroll
    for (int mi = 0; mi < 2; mi++)
#pragma unroll
        for (int ni = 0; ni < 8; ni++) {
            int gr = row0 + wm * 32 + mi * 16 + lrow;
            int gc = col0 + wn * 64 + ni * 8 + lcol * 2;
            float2* p0 = (float2*)&C[(size_t)gr * N + gc];
            float2* p1 = (float2*)&C[(size_t)(gr + 8) * N + gc];
            float2 o0 = *p0, o1 = *p1;
            o0.x += c[mi][ni][0]; o0.y += c[mi][ni][1];
            o1.x += c[mi][ni][2]; o1.y += c[mi][ni][3];
            *p0 = o0; *p1 = o1;
        }
}

// ===== fp16 split-K LoRA down-projection (up to 3 fused weights) =============
__global__ __launch_bounds__(256) void down_gemm_h(const float* __restrict__ A,
                                                   const float* __restrict__ w0,
                                                   const float* __restrict__ w1,
                                                   const float* __restrict__ w2,
                                                   float* __restrict__ part,
                                                   int M, int Ntot, int Kfull) {
    __shared__ __half As[128 * HLD];
    __shared__ __half Ws[64 * HLD];

    const int cb = blockIdx.x, mb = blockIdx.y, sp = blockIdx.z;
    const int Kc = Kfull >> 3;
    const int kbase = sp * Kc;
    const float* W = (cb == 0) ? w0 : (cb == 1 ? w1 : w2);

    const int tid = threadIdx.x;
    const int lane = tid & 31;
    const int warp = tid >> 5;
    const int wm = warp & 3;
    const int wn = warp >> 2;
    const int lrow = lane >> 2;
    const int lcol = lane & 3;

    float c[2][4][4];
#pragma unroll
    for (int i = 0; i < 2; i++)
#pragma unroll
        for (int j = 0; j < 4; j++)
#pragma unroll
            for (int r = 0; r < 4; r++) c[i][j][r] = 0.f;

    for (int k0 = 0; k0 < Kc; k0 += 32) {
#pragma unroll
        for (int f = 0; f < 4; f++) {
            int id = tid + f * 256;
            int r = id >> 3;
            int kq = (id & 7) << 2;
            float4 va = *(const float4*)&A[(size_t)(mb * 128 + r) * Kfull + kbase + k0 + kq];
            *(uint2*)&As[r * HLD + kq] =
                make_uint2(pack_h2(va.x, va.y), pack_h2(va.z, va.w));
        }
#pragma unroll
        for (int f = 0; f < 2; f++) {
            int id = tid + f * 256;
            int r = id >> 3;          // 0..63
            int kq = (id & 7) << 2;
            float4 vb = *(const float4*)&W[(size_t)r * Kfull + kbase + k0 + kq];
            *(uint2*)&Ws[r * HLD + kq] =
                make_uint2(pack_h2(vb.x, vb.y), pack_h2(vb.z, vb.w));
        }
        __syncthreads();

#pragma unroll
        for (int ks = 0; ks < 2; ks++) {
            const int kb = ks * 16 + 2 * lcol;
            uint32_t a[2][4];
#pragma unroll
            for (int mi = 0; mi < 2; mi++) {
                int ar = wm * 32 + mi * 16 + lrow;
                a[mi][0] = *(const uint32_t*)&As[ar * HLD + kb];
                a[mi][1] = *(const uint32_t*)&As[(ar + 8) * HLD + kb];
                a[mi][2] = *(const uint32_t*)&As[ar * HLD + kb + 8];
                a[mi][3] = *(const uint32_t*)&As[(ar + 8) * HLD + kb + 8];
            }
            uint32_t b[4][2];
#pragma unroll
            for (int ni = 0; ni < 4; ni++) {
                int br = wn * 32 + ni * 8 + lrow;
                b[ni][0] = *(const uint32_t*)&Ws[br * HLD + kb];
                b[ni][1] = *(const uint32_t*)&Ws[br * HLD + kb + 8];
            }
#pragma unroll
            for (int mi = 0; mi < 2; mi++)
#pragma unroll
                for (int ni = 0; ni < 4; ni++)
                    mma_f16(c[mi][ni], a[mi], b[ni][0], b[ni][1]);
        }
        __syncthreads();
    }

    float* basep = part + (size_t)sp * M * Ntot;
#pragma unroll
    for (int mi = 0; mi < 2; mi++)
#pragma unroll
        for (int ni = 0; ni < 4; ni++) {
            int gr = mb * 128 + wm * 32 + mi * 16 + lrow;
            int gc = cb * 64 + wn * 32 + ni * 8 + lcol * 2;
            *(float2*)&basep[(size_t)gr * Ntot + gc] =
                make_float2(c[mi][ni][0], c[mi][ni][1]);
            *(float2*)&basep[(size_t)(gr + 8) * Ntot + gc] =
                make_float2(c[mi][ni][2], c[mi][ni][3]);
        }
}

__global__ void reduce8_kernel(const float* __restrict__ part,
                               float* __restrict__ out, int len) {
    int i = blockIdx.x * blockDim.x + threadIdx.x;
    if (i >= len) return;
    float v = 0.f;
#pragma unroll
    for (int s = 0; s < 8; s++) v += part[(size_t)s * len + i];
    out[i] = v;
}

// ---------------- fused RMS-norm (over DIM) + rope for Q and K ----------------
__global__ __launch_bounds__(256) void rmsrope_kernel(
    float* __restrict__ Q, float* __restrict__ K,
    const float* __restrict__ rope,
    const float* __restrict__ gq, const float* __restrict__ gk,
    const float* __restrict__ gqt, const float* __restrict__ gkt) {
    const int row = blockIdx.x;
    const int tid = threadIdx.x;
    __shared__ float sbuf[18];

    float* qrow = Q + (size_t)row * DIMN;
    float* krow = K + (size_t)row * DIMN;

    float sq = 0.f, sk = 0.f;
    for (int c4 = tid; c4 < DIMN / 4; c4 += 256) {
        float4 q = *(const float4*)&qrow[c4 * 4];
        sq += q.x * q.x + q.y * q.y + q.z * q.z + q.w * q.w;
        float4 kk = *(const float4*)&krow[c4 * 4];
        sk += kk.x * kk.x + kk.y * kk.y + kk.z * kk.z + kk.w * kk.w;
    }
#pragma unroll
    for (int o = 16; o > 0; o >>= 1) {
        sq += __shfl_xor_sync(0xffffffffu, sq, o);
        sk += __shfl_xor_sync(0xffffffffu, sk, o);
    }
    int w = tid >> 5;
    if ((tid & 31) == 0) { sbuf[w] = sq; sbuf[8 + w] = sk; }
    __syncthreads();
    if (tid == 0) {
        float a = 0.f, b = 0.f;
        for (int i = 0; i < 8; i++) { a += sbuf[i]; b += sbuf[8 + i]; }
        sbuf[16] = a; sbuf[17] = b;
    }
    __syncthreads();
    const float invq = rsqrtf(sbuf[16] / (float)DIMN + EPSV);
    const float invk = rsqrtf(sbuf[17] / (float)DIMN + EPSV);
    const float* gQ = (row < IMG_SEQ) ? gq : gqt;
    const float* gK = (row < IMG_SEQ) ? gk : gkt;
    const float* rp = rope + (size_t)row * 256;

    for (int pi = tid; pi < DIMN / 2; pi += 256) {
        int c0 = pi * 2;
        int j = pi & 63;
        float4 r = *(const float4*)&rp[j * 4];
        float x0 = qrow[c0] * invq * gQ[c0];
        float x1 = qrow[c0 + 1] * invq * gQ[c0 + 1];
        qrow[c0]     = r.x * x0 + r.y * x1;
        qrow[c0 + 1] = r.z * x0 + r.w * x1;
        float y0 = krow[c0] * invk * gK[c0];
        float y1 = krow[c0 + 1] * invk * gK[c0 + 1];
        krow[c0]     = r.x * y0 + r.y * y1;
        krow[c0 + 1] = r.z * y0 + r.w * y1;
    }
}

// ---------------- flash attention: QK fp16 mma, PV tf32 mma ----------------
// Br=128 (8 warps x 16 rows), Bc=64.
#define FB_KS_OFF 0                 // half Ks[64][136] = 17408 B
#define FB_VT_OFF 17408             // float Vt[128][68] = 34816 B
#define FB_PS_OFF 52224             // float Ps[128][68] = 34816 B
#define FB_BYTES 87040
#define KLD 136

__global__ __launch_bounds__(256) void flash_mma(const float* __restrict__ Q,
                                                 const float* __restrict__ K,
                                                 const float* __restrict__ V,
                                                 float* __restrict__ O) {
    extern __shared__ char smc[];
    __half* Ks = (__half*)(smc + FB_KS_OFF);
    float* Vt = (float*)(smc + FB_VT_OFF);
    float* Ps = (float*)(smc + FB_PS_OFF);

    const int tid = threadIdx.x;
    const int lane = tid & 31;
    const int warp = tid >> 5;
    const int lrow = lane >> 2;
    const int lcol = lane & 3;
    const int qrow0 = blockIdx.x * 128;
    const size_t hoff = (size_t)blockIdx.y * HD;
    const float scale = 0.08838834764831844f;  // 1/sqrt(128)

    // Q fragments (fp16, pre-scaled): 8 k16-steps x 4 b32
    uint32_t qa[8][4];
    {
        const float* qb = Q + (size_t)(qrow0 + warp * 16) * DIMN + hoff;
#pragma unroll
        for (int ks = 0; ks < 8; ks++) {
            int kb = ks * 16 + 2 * lcol;
            qa[ks][0] = pack_h2(scale * qb[(size_t)lrow * DIMN + kb],
                                scale * qb[(size_t)lrow * DIMN + kb + 1]);
            qa[ks][1] = pack_h2(scale * qb[(size_t)(lrow + 8) * DIMN + kb],
                                scale * qb[(size_t)(lrow + 8) * DIMN + kb + 1]);
            qa[ks][2] = pack_h2(scale * qb[(size_t)lrow * DIMN + kb + 8],
                                scale * qb[(size_t)lrow * DIMN + kb + 9]);
            qa[ks][3] = pack_h2(scale * qb[(size_t)(lrow + 8) * DIMN + kb + 8],
                                scale * qb[(size_t)(lrow + 8) * DIMN + kb + 9]);
        }
    }

    float o[16][4];
#pragma unroll
    for (int ni = 0; ni < 16; ni++)
#pragma unroll
        for (int r = 0; r < 4; r++) o[ni][r] = 0.f;
    float m0 = -INFINITY, m1 = -INFINITY, l0 = 0.f, l1 = 0.f;

    const int kt0 = (qrow0 >= SBSN) ? (SBSN / 64) : 0;

    for (int kt = kt0; kt < SEQN / 64; kt++) {
        const int kr0 = kt * 64;
        __syncthreads();
        // K tile -> Ks[64][136] halves
#pragma unroll
        for (int f = 0; f < 8; f++) {
            int id = tid + f * 256;           // 0..2047
            int r = id >> 5;                  // 0..63
            int k4 = (id & 31) << 2;          // 0..124
            float4 v = *(const float4*)&K[(size_t)(kr0 + r) * DIMN + hoff + k4];
            *(uint2*)&Ks[r * KLD + k4] =
                make_uint2(pack_h2(v.x, v.y), pack_h2(v.z, v.w));
        }
        // V tile -> Vt[d][j] transposed (tf32)
#pragma unroll
        for (int f = 0; f < 8; f++) {
            int id = tid + f * 256;
            int j = id & 63;
            int d4 = (id >> 6) << 2;
            float4 v = *(const float4*)&V[(size_t)(kr0 + j) * DIMN + hoff + d4];
            Vt[(d4 + 0) * 68 + j] = to_tf32(v.x);
            Vt[(d4 + 1) * 68 + j] = to_tf32(v.y);
            Vt[(d4 + 2) * 68 + j] = to_tf32(v.z);
            Vt[(d4 + 3) * 68 + j] = to_tf32(v.w);
        }
        __syncthreads();

        // S = Q @ K^T : 8 k16-steps, 8 n-tiles
        float s[8][4];
#pragma unroll
        for (int ni = 0; ni < 8; ni++)
#pragma unroll
            for (int r = 0; r < 4; r++) s[ni][r] = 0.f;
#pragma unroll
        for (int ks = 0; ks < 8; ks++) {
            const int kb = ks * 16 + 2 * lcol;
#pragma unroll
            for (int ni = 0; ni < 8; ni++) {
                int br = ni * 8 + lrow;
                uint32_t b0 = *(const uint32_t*)&Ks[br * KLD + kb];
                uint32_t b1 = *(const uint32_t*)&Ks[br * KLD + kb + 8];
                mma_f16(s[ni], qa[ks], b0, b1);
            }
        }

        // online softmax (warp-local)
        float mt0 = -INFINITY, mt1 = -INFINITY;
#pragma unroll
        for (int ni = 0; ni < 8; ni++) {
            mt0 = fmaxf(mt0, fmaxf(s[ni][0], s[ni][1]));
            mt1 = fmaxf(mt1, fmaxf(s[ni][2], s[ni][3]));
        }
#pragma unroll
        for (int off = 1; off <= 2; off <<= 1) {
            mt0 = fmaxf(mt0, __shfl_xor_sync(0xffffffffu, mt0, off));
            mt1 = fmaxf(mt1, __shfl_xor_sync(0xffffffffu, mt1, off));
        }
        float mn0 = fmaxf(m0, mt0), mn1 = fmaxf(m1, mt1);
        float corr0 = __expf(m0 - mn0), corr1 = __expf(m1 - mn1);
        m0 = mn0; m1 = mn1;

        float ps0 = 0.f, ps1 = 0.f;
#pragma unroll
        for (int ni = 0; ni < 8; ni++) {
            float p0 = to_tf32(__expf(s[ni][0] - mn0));
            float p1 = to_tf32(__expf(s[ni][1] - mn0));
            float p2 = to_tf32(__expf(s[ni][2] - mn1));
            float p3 = to_tf32(__expf(s[ni][3] - mn1));
            ps0 += p0 + p1; ps1 += p2 + p3;
            int col = ni * 8 + lcol * 2;
            *(float2*)&Ps[(warp * 16 + lrow) * 68 + col] = make_float2(p0, p1);
            *(float2*)&Ps[(warp * 16 + lrow + 8) * 68 + col] = make_float2(p2, p3);
        }
#pragma unroll
        for (int off = 1; off <= 2; off <<= 1) {
            ps0 += __shfl_xor_sync(0xffffffffu, ps0, off);
            ps1 += __shfl_xor_sync(0xffffffffu, ps1, off);
        }
        l0 = l0 * corr0 + ps0;
        l1 = l1 * corr1 + ps1;
#pragma unroll
        for (int ni = 0; ni < 16; ni++) {
            o[ni][0] *= corr0; o[ni][1] *= corr0;
            o[ni][2] *= corr1; o[ni][3] *= corr1;
        }
        __syncwarp();

        // O += P @ V (tf32)
#pragma unroll
        for (int ks = 0; ks < 8; ks++) {
            const int kb = ks * 8;
            float a[4];
            a[0] = Ps[(warp * 16 + lrow) * 68 + kb + lcol];
            a[1] = Ps[(warp * 16 + lrow + 8) * 68 + kb + lcol];
            a[2] = Ps[(warp * 16 + lrow) * 68 + kb + lcol + 4];
            a[3] = Ps[(warp * 16 + lrow + 8) * 68 + kb + lcol + 4];
#pragma unroll
            for (int ni = 0; ni < 16; ni++) {
                float b[2];
                b[0] = Vt[(ni * 8 + lrow) * 68 + kb + lcol];
                b[1] = Vt[(ni * 8 + lrow) * 68 + kb + lcol + 4];
                mma_tf32(o[ni], a, b);
            }
        }
    }

    const float inv0 = 1.f / l0, inv1 = 1.f / l1;
    const int gr0 = qrow0 + warp * 16 + lrow;
#pragma unroll
    for (int ni = 0; ni < 16; ni++) {
        int gc = ni * 8 + lcol * 2;
        *(float2*)&O[(size_t)gr0 * DIMN + hoff + gc] =
            make_float2(o[ni][0] * inv0, o[ni][1] * inv0);
        *(float2*)&O[(size_t)(gr0 + 8) * DIMN + hoff + gc] =
            make_float2(o[ni][2] * inv1, o[ni][3] * inv1);
    }
}

// ---------------- output assembly ----------------
__global__ void copyout_kernel(const float* __restrict__ Hx, float* __restrict__ out) {
    int i = blockIdx.x * blockDim.x + threadIdx.x;
    const int n1 = BLOCKN * DIMN;
    const int nt = TXT_SEQ * DIMN;
    if (i >= SEQN * DIMN) return;
    if (i < n1)            out[i] = Hx[i];
    else if (i < n1 + nt)  out[i] = Hx[IMG_SEQ * DIMN + (i - n1)];
    else                   out[i] = Hx[n1 + (i - n1 - nt)];
}

// ---------------- launch ----------------
extern "C" void kernel_launch(void* const* d_in, const int* in_sizes, int n_in,
                              void* d_out, int out_size) {
    const float* img  = (const float*)d_in[0];
    const float* txt  = (const float*)d_in[1];
    const float* rope = (const float*)d_in[2];
    const float* wq   = (const float*)d_in[3];
    const float* wk   = (const float*)d_in[4];
    const float* wv   = (const float*)d_in[5];
    const float* wo   = (const float*)d_in[6];
    const float* wq_t = (const float*)d_in[7];
    const float* wk_t = (const float*)d_in[8];
    const float* wv_t = (const float*)d_in[9];
    const float* wo_t = (const float*)d_in[10];
    const float* gq   = (const float*)d_in[11];
    const float* gk   = (const float*)d_in[12];
    const float* gqt  = (const float*)d_in[13];
    const float* gkt  = (const float*)d_in[14];
    const float* q_down = (const float*)d_in[15];
    const float* q_up   = (const float*)d_in[16];
    const float* k_down = (const float*)d_in[17];
    const float* k_up   = (const float*)d_in[18];
    const float* v_down = (const float*)d_in[19];
    const float* v_up   = (const float*)d_in[20];
    const float* p_down = (const float*)d_in[21];
    const float* p_up   = (const float*)d_in[22];
    float* out = (float*)d_out;

    float *Q, *K, *V, *O, *Hx, *part, *L, *Lp;
    cudaGetSymbolAddress((void**)&Q,    g_Q);
    cudaGetSymbolAddress((void**)&K,    g_K);
    cudaGetSymbolAddress((void**)&V,    g_V);
    cudaGetSymbolAddress((void**)&O,    g_O);
    cudaGetSymbolAddress((void**)&Hx,   g_Hx);
    cudaGetSymbolAddress((void**)&part, g_part);
    cudaGetSymbolAddress((void**)&L,    g_L);
    cudaGetSymbolAddress((void**)&Lp,   g_Lp);

    const float* img_cond = img + (size_t)BLOCKN * DIMN;

    // 1) fused LoRA down-projections (q/k/v), split-K 8-way, then reduce
    down_gemm_h<<<dim3(3, CONDN / 128, 8), 256>>>(img_cond, q_down, k_down, v_down,
                                                  part, CONDN, 192, DIMN);
    {
        int len = CONDN * 192;
        reduce8_kernel<<<(len + 255) / 256, 256>>>(part, L, len);
    }

    // 2) QKV projections in ONE launch (grid.z selects weight/output)
    proj_gemm3h<<<dim3(DIMN / 128, SEQN / 128, 3), 256>>>(
        img, txt,
        wq, wq_t, Q,
        wk, wk_t, K,
        wv, wv_t, V,
        IMG_SEQ, DIMN, DIMN);

    // 3) LoRA up-projections accumulate into cond rows of Q/K/V
    dim3 ug(DIMN / 128, CONDN / 128);
    up_gemm_acc_h<<<ug, 256>>>(L + 0,   192, q_up, Q + (size_t)BLOCKN * DIMN, DIMN, RANKN);
    up_gemm_acc_h<<<ug, 256>>>(L + 64,  192, k_up, K + (size_t)BLOCKN * DIMN, DIMN, RANKN);
    up_gemm_acc_h<<<ug, 256>>>(L + 128, 192, v_up, V + (size_t)BLOCKN * DIMN, DIMN, RANKN);

    // 4) RMS + rope
    rmsrope_kernel<<<SEQN, 256>>>(Q, K, rope, gq, gk, gqt, gkt);

    // 5) flash attention
    cudaFuncSetAttribute(flash_mma, cudaFuncAttributeMaxDynamicSharedMemorySize,
                         FB_BYTES);
    flash_mma<<<dim3(SEQN / 128, HEADS), 256, FB_BYTES>>>(Q, K, V, O);

    // 6) output projection, image+text batched
    proj_gemm3h<<<dim3(DIMN / 128, SEQN / 128, 1), 256>>>(
        O, O + (size_t)IMG_SEQ * DIMN,
        wo, wo_t, Hx,
        wo, wo_t, Hx,
        wo, wo_t, Hx,
        IMG_SEQ, DIMN, DIMN);

    // 7) post-projection LoRA on cond rows of Hx
    down_gemm_h<<<dim3(1, CONDN / 128, 8), 256>>>(Hx + (size_t)BLOCKN * DIMN,
                                                  p_down, p_down, p_down,
                                                  part, CONDN, 64, DIMN);
    {
        int len = CONDN * 64;
        reduce8_kernel<<<(len + 255) / 256, 256>>>(part, Lp, len);
    }
    up_gemm_acc_h<<<ug, 256>>>(Lp, 64, p_up, Hx + (size_t)BLOCKN * DIMN, DIMN, RANKN);

    // 8) assemble outputs
    int tot = SEQN * DIMN;
    copyout_kernel<<<(tot + 255) / 256, 256>>>(Hx, out);
}

// round 7
// speedup vs baseline: 6.7465x; 1.0878x over previous
#include <cuda_runtime.h>
#include <cuda_fp16.h>
#include <math.h>
#include <stdint.h>

// ---------------- problem constants ----------------
#define DIMN 2048
#define HEADS 16
#define HD 128
#define RANKN 64
#define IMG_SEQ 2048
#define TXT_SEQ 128
#define SEQN 2176          // IMG_SEQ + TXT_SEQ
#define CONDN 1024
#define BLOCKN 1024        // IMG_SEQ - COND
#define SBSN 1152          // SEQ - COND
#define EPSV 1e-5f

// ---------------- device scratch (no allocation allowed) ----------------
__device__ float g_Q[SEQN * DIMN];
__device__ float g_K[SEQN * DIMN];
__device__ float g_V[SEQN * DIMN];
__device__ float g_O[SEQN * DIMN];
__device__ float g_part[8 * CONDN * 192];
__device__ float g_L[CONDN * 192];
__device__ float g_Lp[CONDN * RANKN];

// ---------------- helpers ----------------
__device__ __forceinline__ uint32_t pack_h2(float x, float y) {
    __half2 h = __floats2half2_rn(x, y);
    return *(uint32_t*)&h;
}

__device__ __forceinline__ void mma_f16(float c[4], const uint32_t a[4],
                                        uint32_t b0, uint32_t b1) {
    asm volatile(
        "mma.sync.aligned.m16n8k16.row.col.f32.f16.f16.f32 "
        "{%0,%1,%2,%3}, {%4,%5,%6,%7}, {%8,%9}, {%0,%1,%2,%3};"
        : "+f"(c[0]), "+f"(c[1]), "+f"(c[2]), "+f"(c[3])
        : "r"(a[0]), "r"(a[1]), "r"(a[2]), "r"(a[3]),
          "r"(b0), "r"(b1));
}

#define HLD 40   // halves per smem row (pad: 20 words -> conflict-free frags)

// ===== fp16 projection GEMM: C[remap(r)] = A_sel(r) @ W_sel(r,z)^T ===========
// 128x128 CTA tile, 8 warps (32x64 warp tiles), BK=32 (2 k16-steps).
// grid.z selects among up to 3 (W1/W2, C) triples; rows >= Msplit use B-side.
// remap!=0: output rows rearranged [img | text | cond] (128-aligned regions).
__global__ __launch_bounds__(256, 2) void proj_gemm3h(
    const float* __restrict__ A1, const float* __restrict__ A2,
    const float* __restrict__ Wa0, const float* __restrict__ Wb0, float* __restrict__ C0,
    const float* __restrict__ Wa1, const float* __restrict__ Wb1, float* __restrict__ C1,
    const float* __restrict__ Wa2, const float* __restrict__ Wb2, float* __restrict__ C2,
    int Msplit, int N, int K, int remap) {
    __shared__ __half As[128 * HLD];
    __shared__ __half Bs[128 * HLD];

    const int tid = threadIdx.x;
    const int lane = tid & 31;
    const int warp = tid >> 5;
    const int wm = warp & 3;
    const int wn = warp >> 2;
    const int lrow = lane >> 2;
    const int lcol = lane & 3;
    const int row0 = blockIdx.y * 128;
    const int col0 = blockIdx.x * 128;
    const int z = blockIdx.z;

    const float* A = (row0 < Msplit) ? A1 + (size_t)row0 * K
                                     : A2 + (size_t)(row0 - Msplit) * K;
    const float* W;
    float* C;
    if (z == 0)      { W = (row0 < Msplit) ? Wa0 : Wb0; C = C0; }
    else if (z == 1) { W = (row0 < Msplit) ? Wa1 : Wb1; C = C1; }
    else             { W = (row0 < Msplit) ? Wa2 : Wb2; C = C2; }

    // per-CTA output row offset (regions are 128-row aligned)
    int row_out0 = row0;
    if (remap) {
        if (row0 >= IMG_SEQ)      row_out0 = row0 - CONDN;     // text -> after img
        else if (row0 >= BLOCKN)  row_out0 = row0 + TXT_SEQ;   // cond -> tail
    }

    float c[2][8][4];
#pragma unroll
    for (int i = 0; i < 2; i++)
#pragma unroll
        for (int j = 0; j < 8; j++)
#pragma unroll
            for (int r = 0; r < 4; r++) c[i][j][r] = 0.f;

    for (int k0 = 0; k0 < K; k0 += 32) {
#pragma unroll
        for (int f = 0; f < 4; f++) {
            int id = tid + f * 256;        // 0..1023
            int r = id >> 3;               // 0..127
            int kq = (id & 7) << 2;        // 0,4,...,28
            float4 va = *(const float4*)&A[(size_t)r * K + k0 + kq];
            *(uint2*)&As[r * HLD + kq] =
                make_uint2(pack_h2(va.x, va.y), pack_h2(va.z, va.w));
            float4 vb = *(const float4*)&W[(size_t)(col0 + r) * K + k0 + kq];
            *(uint2*)&Bs[r * HLD + kq] =
                make_uint2(pack_h2(vb.x, vb.y), pack_h2(vb.z, vb.w));
        }
        __syncthreads();

#pragma unroll
        for (int ks = 0; ks < 2; ks++) {
            const int kb = ks * 16 + 2 * lcol;
            uint32_t a[2][4];
#pragma unroll
            for (int mi = 0; mi < 2; mi++) {
                int ar = wm * 32 + mi * 16 + lrow;
                a[mi][0] = *(const uint32_t*)&As[ar * HLD + kb];
                a[mi][1] = *(const uint32_t*)&As[(ar + 8) * HLD + kb];
                a[mi][2] = *(const uint32_t*)&As[ar * HLD + kb + 8];
                a[mi][3] = *(const uint32_t*)&As[(ar + 8) * HLD + kb + 8];
            }
            uint32_t b[8][2];
#pragma unroll
            for (int ni = 0; ni < 8; ni++) {
                int br = wn * 64 + ni * 8 + lrow;
                b[ni][0] = *(const uint32_t*)&Bs[br * HLD + kb];
                b[ni][1] = *(const uint32_t*)&Bs[br * HLD + kb + 8];
            }
#pragma unroll
            for (int mi = 0; mi < 2; mi++)
#pragma unroll
                for (int ni = 0; ni < 8; ni++)
                    mma_f16(c[mi][ni], a[mi], b[ni][0], b[ni][1]);
        }
        __syncthreads();
    }

#pragma unroll
    for (int mi = 0; mi < 2; mi++)
#pragma unroll
        for (int ni = 0; ni < 8; ni++) {
            int gr = row_out0 + wm * 32 + mi * 16 + lrow;
            int gc = col0 + wn * 64 + ni * 8 + lcol * 2;
            *(float2*)&C[(size_t)gr * N + gc] =
                make_float2(c[mi][ni][0], c[mi][ni][1]);
            *(float2*)&C[(size_t)(gr + 8) * N + gc] =
                make_float2(c[mi][ni][2], c[mi][ni][3]);
        }
}

// ===== fp16 LoRA up-projection: C[M,N] += A[M,K;lda] @ W[N,K]^T ==============
__global__ __launch_bounds__(256) void up_gemm_acc_h(const float* __restrict__ A,
                                                     int lda,
                                                     const float* __restrict__ W,
                                                     float* __restrict__ C,
                                                     int N, int K) {
    __shared__ __half As[128 * HLD];
    __shared__ __half Bs[128 * HLD];

    const int tid = threadIdx.x;
    const int lane = tid & 31;
    const int warp = tid >> 5;
    const int wm = warp & 3;
    const int wn = warp >> 2;
    const int lrow = lane >> 2;
    const int lcol = lane & 3;
    const int row0 = blockIdx.y * 128;
    const int col0 = blockIdx.x * 128;

    float c[2][8][4];
#pragma unroll
    for (int i = 0; i < 2; i++)
#pragma unroll
        for (int j = 0; j < 8; j++)
#pragma unroll
            for (int r = 0; r < 4; r++) c[i][j][r] = 0.f;

    for (int k0 = 0; k0 < K; k0 += 32) {
#pragma unroll
        for (int f = 0; f < 4; f++) {
            int id = tid + f * 256;
            int r = id >> 3;
            int kq = (id & 7) << 2;
            float4 va = *(const float4*)&A[(size_t)(row0 + r) * lda + k0 + kq];
            *(uint2*)&As[r * HLD + kq] =
                make_uint2(pack_h2(va.x, va.y), pack_h2(va.z, va.w));
            float4 vb = *(const float4*)&W[(size_t)(col0 + r) * K + k0 + kq];
            *(uint2*)&Bs[r * HLD + kq] =
                make_uint2(pack_h2(vb.x, vb.y), pack_h2(vb.z, vb.w));
        }
        __syncthreads();

#pragma unroll
        for (int ks = 0; ks < 2; ks++) {
            const int kb = ks * 16 + 2 * lcol;
            uint32_t a[2][4];
#pragma unroll
            for (int mi = 0; mi < 2; mi++) {
                int ar = wm * 32 + mi * 16 + lrow;
                a[mi][0] = *(const uint32_t*)&As[ar * HLD + kb];
                a[mi][1] = *(const uint32_t*)&As[(ar + 8) * HLD + kb];
                a[mi][2] = *(const uint32_t*)&As[ar * HLD + kb + 8];
                a[mi][3] = *(const uint32_t*)&As[(ar + 8) * HLD + kb + 8];
            }
            uint32_t b[8][2];
#pragma unroll
            for (int ni = 0; ni < 8; ni++) {
                int br = wn * 64 + ni * 8 + lrow;
                b[ni][0] = *(const uint32_t*)&Bs[br * HLD + kb];
                b[ni][1] = *(const uint32_t*)&Bs[br * HLD + kb + 8];
            }
#pragma unroll
            for (int mi = 0; mi < 2; mi++)
#pragma unroll
                for (int ni = 0; ni < 8; ni++)
                    mma_f16(c[mi][ni], a[mi], b[ni][0], b[ni][1]);
        }
        __syncthreads();
    }

#pragma unroll
    for (int mi = 0; mi < 2; mi++)
#pragma unroll
        for (int ni = 0; ni < 8; ni++) {
            int gr = row0 + wm * 32 + mi * 16 + lrow;
            int gc = col0 + wn * 64 + ni * 8 + lcol * 2;
            float2* p0 = (float2*)&C[(size_t)gr * N + gc];
            float2* p1 = (float2*)&C[(size_t)(gr + 8) * N + gc];
            float2 o0 = *p0, o1 = *p1;
            o0.x += c[mi][ni][0]; o0.y += c[mi][ni][1];
            o1.x += c[mi][ni][2]; o1.y += c[mi][ni][3];
            *p0 = o0; *p1 = o1;
        }
}

// ===== fp16 split-K LoRA down-projection (up to 3 fused weights) =============
__global__ __launch_bounds__(256) void down_gemm_h(const float* __restrict__ A,
                                                   const float* __restrict__ w0,
                                                   const float* __restrict__ w1,
                                                   const float* __restrict__ w2,
                                                   float* __restrict__ part,
                                                   int M, int Ntot, int Kfull) {
    __shared__ __half As[128 * HLD];
    __shared__ __half Ws[64 * HLD];

    const int cb = blockIdx.x, mb = blockIdx.y, sp = blockIdx.z;
    const int Kc = Kfull >> 3;
    const int kbase = sp * Kc;
    const float* W = (cb == 0) ? w0 : (cb == 1 ? w1 : w2);

    const int tid = threadIdx.x;
    const int lane = tid & 31;
    const int warp = tid >> 5;
    const int wm = warp & 3;
    const int wn = warp >> 2;
    const int lrow = lane >> 2;
    const int lcol = lane & 3;

    float c[2][4][4];
#pragma unroll
    for (int i = 0; i < 2; i++)
#pragma unroll
        for (int j = 0; j < 4; j++)
#pragma unroll
            for (int r = 0; r < 4; r++) c[i][j][r] = 0.f;

    for (int k0 = 0; k0 < Kc; k0 += 32) {
#pragma unroll
        for (int f = 0; f < 4; f++) {
            int id = tid + f * 256;
            int r = id >> 3;
            int kq = (id & 7) << 2;
            float4 va = *(const float4*)&A[(size_t)(mb * 128 + r) * Kfull + kbase + k0 + kq];
            *(uint2*)&As[r * HLD + kq] =
                make_uint2(pack_h2(va.x, va.y), pack_h2(va.z, va.w));
        }
#pragma unroll
        for (int f = 0; f < 2; f++) {
            int id = tid + f * 256;
            int r = id >> 3;          // 0..63
            int kq = (id & 7) << 2;
            float4 vb = *(const float4*)&W[(size_t)r * Kfull + kbase + k0 + kq];
            *(uint2*)&Ws[r * HLD + kq] =
                make_uint2(pack_h2(vb.x, vb.y), pack_h2(vb.z, vb.w));
        }
        __syncthreads();

#pragma unroll
        for (int ks = 0; ks < 2; ks++) {
            const int kb = ks * 16 + 2 * lcol;
            uint32_t a[2][4];
#pragma unroll
            for (int mi = 0; mi < 2; mi++) {
                int ar = wm * 32 + mi * 16 + lrow;
                a[mi][0] = *(const uint32_t*)&As[ar * HLD + kb];
                a[mi][1] = *(const uint32_t*)&As[(ar + 8) * HLD + kb];
                a[mi][2] = *(const uint32_t*)&As[ar * HLD + kb + 8];
                a[mi][3] = *(const uint32_t*)&As[(ar + 8) * HLD + kb + 8];
            }
            uint32_t b[4][2];
#pragma unroll
            for (int ni = 0; ni < 4; ni++) {
                int br = wn * 32 + ni * 8 + lrow;
                b[ni][0] = *(const uint32_t*)&Ws[br * HLD + kb];
                b[ni][1] = *(const uint32_t*)&Ws[br * HLD + kb + 8];
            }
#pragma unroll
            for (int mi = 0; mi < 2; mi++)
#pragma unroll
                for (int ni = 0; ni < 4; ni++)
                    mma_f16(c[mi][ni], a[mi], b[ni][0], b[ni][1]);
        }
        __syncthreads();
    }

    float* basep = part + (size_t)sp * M * Ntot;
#pragma unroll
    for (int mi = 0; mi < 2; mi++)
#pragma unroll
        for (int ni = 0; ni < 4; ni++) {
            int gr = mb * 128 + wm * 32 + mi * 16 + lrow;
            int gc = cb * 64 + wn * 32 + ni * 8 + lcol * 2;
            *(float2*)&basep[(size_t)gr * Ntot + gc] =
                make_float2(c[mi][ni][0], c[mi][ni][1]);
            *(float2*)&basep[(size_t)(gr + 8) * Ntot + gc] =
                make_float2(c[mi][ni][2], c[mi][ni][3]);
        }
}

__global__ void reduce8_kernel(const float* __restrict__ part,
                               float* __restrict__ out, int len) {
    int i = blockIdx.x * blockDim.x + threadIdx.x;
    if (i >= len) return;
    float v = 0.f;
#pragma unroll
    for (int s = 0; s < 8; s++) v += part[(size_t)s * len + i];
    out[i] = v;
}

// ---------------- fused RMS-norm (over DIM) + rope for Q and K ----------------
__global__ __launch_bounds__(256) void rmsrope_kernel(
    float* __restrict__ Q, float* __restrict__ K,
    const float* __restrict__ rope,
    const float* __restrict__ gq, const float* __restrict__ gk,
    const float* __restrict__ gqt, const float* __restrict__ gkt) {
    const int row = blockIdx.x;
    const int tid = threadIdx.x;
    __shared__ float sbuf[18];

    float* qrow = Q + (size_t)row * DIMN;
    float* krow = K + (size_t)row * DIMN;

    float sq = 0.f, sk = 0.f;
    for (int c4 = tid; c4 < DIMN / 4; c4 += 256) {
        float4 q = *(const float4*)&qrow[c4 * 4];
        sq += q.x * q.x + q.y * q.y + q.z * q.z + q.w * q.w;
        float4 kk = *(const float4*)&krow[c4 * 4];
        sk += kk.x * kk.x + kk.y * kk.y + kk.z * kk.z + kk.w * kk.w;
    }
#pragma unroll
    for (int o = 16; o > 0; o >>= 1) {
        sq += __shfl_xor_sync(0xffffffffu, sq, o);
        sk += __shfl_xor_sync(0xffffffffu, sk, o);
    }
    int w = tid >> 5;
    if ((tid & 31) == 0) { sbuf[w] = sq; sbuf[8 + w] = sk; }
    __syncthreads();
    if (tid == 0) {
        float a = 0.f, b = 0.f;
        for (int i = 0; i < 8; i++) { a += sbuf[i]; b += sbuf[8 + i]; }
        sbuf[16] = a; sbuf[17] = b;
    }
    __syncthreads();
    const float invq = rsqrtf(sbuf[16] / (float)DIMN + EPSV);
    const float invk = rsqrtf(sbuf[17] / (float)DIMN + EPSV);
    const float* gQ = (row < IMG_SEQ) ? gq : gqt;
    const float* gK = (row < IMG_SEQ) ? gk : gkt;
    const float* rp = rope + (size_t)row * 256;

    for (int pi = tid; pi < DIMN / 2; pi += 256) {
        int c0 = pi * 2;
        int j = pi & 63;
        float4 r = *(const float4*)&rp[j * 4];
        float x0 = qrow[c0] * invq * gQ[c0];
        float x1 = qrow[c0 + 1] * invq * gQ[c0 + 1];
        qrow[c0]     = r.x * x0 + r.y * x1;
        qrow[c0 + 1] = r.z * x0 + r.w * x1;
        float y0 = krow[c0] * invk * gK[c0];
        float y1 = krow[c0 + 1] * invk * gK[c0 + 1];
        krow[c0]     = r.x * y0 + r.y * y1;
        krow[c0 + 1] = r.z * y0 + r.w * y1;
    }
}

// ---------------- flash attention: all-fp16 mma, fp32 accum ----------------
// Br=128 (8 warps x 16 rows), Bc=64.
#define KLD 136                      // halves per Ks row
#define VLD 72                       // halves per Vt row (d-major)
#define PLD 72                       // halves per Ps row
#define FB_KS_OFF 0                  // half Ks[64][136]  = 17408 B
#define FB_VT_OFF 17408              // half Vt[128][72]  = 18432 B
#define FB_PS_OFF 35840              // half Ps[128][72]  = 18432 B
#define FB_BYTES 54272

__global__ __launch_bounds__(256) void flash_mma(const float* __restrict__ Q,
                                                 const float* __restrict__ K,
                                                 const float* __restrict__ V,
                                                 float* __restrict__ O) {
    extern __shared__ char smc[];
    __half* Ks = (__half*)(smc + FB_KS_OFF);
    __half* Vt = (__half*)(smc + FB_VT_OFF);
    __half* Ps = (__half*)(smc + FB_PS_OFF);

    const int tid = threadIdx.x;
    const int lane = tid & 31;
    const int warp = tid >> 5;
    const int lrow = lane >> 2;
    const int lcol = lane & 3;
    const int qrow0 = blockIdx.x * 128;
    const size_t hoff = (size_t)blockIdx.y * HD;
    const float scale = 0.08838834764831844f;  // 1/sqrt(128)

    // Q fragments (fp16, pre-scaled): 8 k16-steps x 4 b32
    uint32_t qa[8][4];
    {
        const float* qb = Q + (size_t)(qrow0 + warp * 16) * DIMN + hoff;
#pragma unroll
        for (int ks = 0; ks < 8; ks++) {
            int kb = ks * 16 + 2 * lcol;
            qa[ks][0] = pack_h2(scale * qb[(size_t)lrow * DIMN + kb],
                                scale * qb[(size_t)lrow * DIMN + kb + 1]);
            qa[ks][1] = pack_h2(scale * qb[(size_t)(lrow + 8) * DIMN + kb],
                                scale * qb[(size_t)(lrow + 8) * DIMN + kb + 1]);
            qa[ks][2] = pack_h2(scale * qb[(size_t)lrow * DIMN + kb + 8],
                                scale * qb[(size_t)lrow * DIMN + kb + 9]);
            qa[ks][3] = pack_h2(scale * qb[(size_t)(lrow + 8) * DIMN + kb + 8],
                                scale * qb[(size_t)(lrow + 8) * DIMN + kb + 9]);
        }
    }

    float o[16][4];
#pragma unroll
    for (int ni = 0; ni < 16; ni++)
#pragma unroll
        for (int r = 0; r < 4; r++) o[ni][r] = 0.f;
    float m0 = -INFINITY, m1 = -INFINITY, l0 = 0.f, l1 = 0.f;

    const int kt0 = (qrow0 >= SBSN) ? (SBSN / 64) : 0;

    for (int kt = kt0; kt < SEQN / 64; kt++) {
        const int kr0 = kt * 64;
        __syncthreads();
        // K tile -> Ks[64][KLD] halves
#pragma unroll
        for (int f = 0; f < 8; f++) {
            int id = tid + f * 256;           // 0..2047
            int r = id >> 5;                  // 0..63
            int k4 = (id & 31) << 2;          // 0..124
            float4 v = *(const float4*)&K[(size_t)(kr0 + r) * DIMN + hoff + k4];
            *(uint2*)&Ks[r * KLD + k4] =
                make_uint2(pack_h2(v.x, v.y), pack_h2(v.z, v.w));
        }
        // V tile -> Vt[d][j] transposed halves
#pragma unroll
        for (int f = 0; f < 8; f++) {
            int id = tid + f * 256;
            int j = id & 63;
            int d4 = (id >> 6) << 2;
            float4 v = *(const float4*)&V[(size_t)(kr0 + j) * DIMN + hoff + d4];
            Vt[(d4 + 0) * VLD + j] = __float2half_rn(v.x);
            Vt[(d4 + 1) * VLD + j] = __float2half_rn(v.y);
            Vt[(d4 + 2) * VLD + j] = __float2half_rn(v.z);
            Vt[(d4 + 3) * VLD + j] = __float2half_rn(v.w);
        }
        __syncthreads();

        // S = Q @ K^T : 8 k16-steps, 8 n-tiles
        float s[8][4];
#pragma unroll
        for (int ni = 0; ni < 8; ni++)
#pragma unroll
            for (int r = 0; r < 4; r++) s[ni][r] = 0.f;
#pragma unroll
        for (int ks = 0; ks < 8; ks++) {
            const int kb = ks * 16 + 2 * lcol;
#pragma unroll
            for (int ni = 0; ni < 8; ni++) {
                int br = ni * 8 + lrow;
                uint32_t b0 = *(const uint32_t*)&Ks[br * KLD + kb];
                uint32_t b1 = *(const uint32_t*)&Ks[br * KLD + kb + 8];
                mma_f16(s[ni], qa[ks], b0, b1);
            }
        }

        // online softmax (warp-local)
        float mt0 = -INFINITY, mt1 = -INFINITY;
#pragma unroll
        for (int ni = 0; ni < 8; ni++) {
            mt0 = fmaxf(mt0, fmaxf(s[ni][0], s[ni][1]));
            mt1 = fmaxf(mt1, fmaxf(s[ni][2], s[ni][3]));
        }
#pragma unroll
        for (int off = 1; off <= 2; off <<= 1) {
            mt0 = fmaxf(mt0, __shfl_xor_sync(0xffffffffu, mt0, off));
            mt1 = fmaxf(mt1, __shfl_xor_sync(0xffffffffu, mt1, off));
        }
        float mn0 = fmaxf(m0, mt0), mn1 = fmaxf(m1, mt1);
        float corr0 = __expf(m0 - mn0), corr1 = __expf(m1 - mn1);
        m0 = mn0; m1 = mn1;

        // P in fp16; l sums the ROUNDED halves for exact O/l consistency
        float ps0 = 0.f, ps1 = 0.f;
#pragma unroll
        for (int ni = 0; ni < 8; ni++) {
            __half2 h01 = __floats2half2_rn(__expf(s[ni][0] - mn0),
                                            __expf(s[ni][1] - mn0));
            __half2 h23 = __floats2half2_rn(__expf(s[ni][2] - mn1),
                                            __expf(s[ni][3] - mn1));
            ps0 += __low2float(h01) + __high2float(h01);
            ps1 += __low2float(h23) + __high2float(h23);
            int col = ni * 8 + 2 * lcol;
            *(uint32_t*)&Ps[(warp * 16 + lrow) * PLD + col] = *(uint32_t*)&h01;
            *(uint32_t*)&Ps[(warp * 16 + lrow + 8) * PLD + col] = *(uint32_t*)&h23;
        }
#pragma unroll
        for (int off = 1; off <= 2; off <<= 1) {
            ps0 += __shfl_xor_sync(0xffffffffu, ps0, off);
            ps1 += __shfl_xor_sync(0xffffffffu, ps1, off);
        }
        l0 = l0 * corr0 + ps0;
        l1 = l1 * corr1 + ps1;
#pragma unroll
        for (int ni = 0; ni < 16; ni++) {
            o[ni][0] *= corr0; o[ni][1] *= corr0;
            o[ni][2] *= corr1; o[ni][3] *= corr1;
        }
        __syncwarp();

        // O += P @ V : 4 k16-steps (j=64), 16 n-tiles, all fp16
#pragma unroll
        for (int ks = 0; ks < 4; ks++) {
            const int kb = ks * 16 + 2 * lcol;
            uint32_t a[4];
            a[0] = *(const uint32_t*)&Ps[(warp * 16 + lrow) * PLD + kb];
            a[1] = *(const uint32_t*)&Ps[(warp * 16 + lrow + 8) * PLD + kb];
            a[2] = *(const uint32_t*)&Ps[(warp * 16 + lrow) * PLD + kb + 8];
            a[3] = *(const uint32_t*)&Ps[(warp * 16 + lrow + 8) * PLD + kb + 8];
#pragma unroll
            for (int ni = 0; ni < 16; ni++) {
                int br = ni * 8 + lrow;
                uint32_t b0 = *(const uint32_t*)&Vt[br * VLD + kb];
                uint32_t b1 = *(const uint32_t*)&Vt[br * VLD + kb + 8];
                mma_f16(o[ni], a, b0, b1);
            }
        }
    }

    const float inv0 = 1.f / l0, inv1 = 1.f / l1;
    const int gr0 = qrow0 + warp * 16 + lrow;
#pragma unroll
    for (int ni = 0; ni < 16; ni++) {
        int gc = ni * 8 + lcol * 2;
        *(float2*)&O[(size_t)gr0 * DIMN + hoff + gc] =
            make_float2(o[ni][0] * inv0, o[ni][1] * inv0);
        *(float2*)&O[(size_t)(gr0 + 8) * DIMN + hoff + gc] =
            make_float2(o[ni][2] * inv1, o[ni][3] * inv1);
    }
}

// ---------------- launch ----------------
extern "C" void kernel_launch(void* const* d_in, const int* in_sizes, int n_in,
                              void* d_out, int out_size) {
    const float* img  = (const float*)d_in[0];
    const float* txt  = (const float*)d_in[1];
    const float* rope = (const float*)d_in[2];
    const float* wq   = (const float*)d_in[3];
    const float* wk   = (const float*)d_in[4];
    const float* wv   = (const float*)d_in[5];
    const float* wo   = (const float*)d_in[6];
    const float* wq_t = (const float*)d_in[7];
    const float* wk_t = (const float*)d_in[8];
    const float* wv_t = (const float*)d_in[9];
    const float* wo_t = (const float*)d_in[10];
    const float* gq   = (const float*)d_in[11];
    const float* gk   = (const float*)d_in[12];
    const float* gqt  = (const float*)d_in[13];
    const float* gkt  = (const float*)d_in[14];
    const float* q_down = (const float*)d_in[15];
    const float* q_up   = (const float*)d_in[16];
    const float* k_down = (const float*)d_in[17];
    const float* k_up   = (const float*)d_in[18];
    const float* v_down = (const float*)d_in[19];
    const float* v_up   = (const float*)d_in[20];
    const float* p_down = (const float*)d_in[21];
    const float* p_up   = (const float*)d_in[22];
    float* out = (float*)d_out;

    float *Q, *K, *V, *O, *part, *L, *Lp;
    cudaGetSymbolAddress((void**)&Q,    g_Q);
    cudaGetSymbolAddress((void**)&K,    g_K);
    cudaGetSymbolAddress((void**)&V,    g_V);
    cudaGetSymbolAddress((void**)&O,    g_O);
    cudaGetSymbolAddress((void**)&part, g_part);
    cudaGetSymbolAddress((void**)&L,    g_L);
    cudaGetSymbolAddress((void**)&Lp,   g_Lp);

    const float* img_cond = img + (size_t)BLOCKN * DIMN;
    float* out_cond = out + (size_t)SBSN * DIMN;   // cond region in output

    // 1) fused LoRA down-projections (q/k/v), split-K 8-way, then reduce
    down_gemm_h<<<dim3(3, CONDN / 128, 8), 256>>>(img_cond, q_down, k_down, v_down,
                                                  part, CONDN, 192, DIMN);
    {
        int len = CONDN * 192;
        reduce8_kernel<<<(len + 255) / 256, 256>>>(part, L, len);
    }

    // 2) QKV projections in ONE launch (grid.z selects weight/output)
    proj_gemm3h<<<dim3(DIMN / 128, SEQN / 128, 3), 256>>>(
        img, txt,
        wq, wq_t, Q,
        wk, wk_t, K,
        wv, wv_t, V,
        IMG_SEQ, DIMN, DIMN, 0);

    // 3) LoRA up-projections accumulate into cond rows of Q/K/V
    dim3 ug(DIMN / 128, CONDN / 128);
    up_gemm_acc_h<<<ug, 256>>>(L + 0,   192, q_up, Q + (size_t)BLOCKN * DIMN, DIMN, RANKN);
    up_gemm_acc_h<<<ug, 256>>>(L + 64,  192, k_up, K + (size_t)BLOCKN * DIMN, DIMN, RANKN);
    up_gemm_acc_h<<<ug, 256>>>(L + 128, 192, v_up, V + (size_t)BLOCKN * DIMN, DIMN, RANKN);

    // 4) RMS + rope
    rmsrope_kernel<<<SEQN, 256>>>(Q, K, rope, gq, gk, gqt, gkt);

    // 5) flash attention (all-fp16 mma)
    cudaFuncSetAttribute(flash_mma, cudaFuncAttributeMaxDynamicSharedMemorySize,
                         FB_BYTES);
    flash_mma<<<dim3(SEQN / 128, HEADS), 256, FB_BYTES>>>(Q, K, V, O);

    // 6) output projection, written DIRECTLY in output layout [img|text|cond]
    proj_gemm3h<<<dim3(DIMN / 128, SEQN / 128, 1), 256>>>(
        O, O + (size_t)IMG_SEQ * DIMN,
        wo, wo_t, out,
        wo, wo_t, out,
        wo, wo_t, out,
        IMG_SEQ, DIMN, DIMN, 1);

    // 7) post-projection LoRA on cond region of out
    down_gemm_h<<<dim3(1, CONDN / 128, 8), 256>>>(out_cond,
                                                  p_down, p_down, p_down,
                                                  part, CONDN, 64, DIMN);
    {
        int len = CONDN * 64;
        reduce8_kernel<<<(len + 255) / 256, 256>>>(part, Lp, len);
    }
    up_gemm_acc_h<<<ug, 256>>>(Lp, 64, p_up, out_cond, DIMN, RANKN);
}

// round 8
// speedup vs baseline: 7.2555x; 1.0754x over previous
#include <cuda_runtime.h>
#include <cuda_fp16.h>
#include <math.h>
#include <stdint.h>

// ---------------- problem constants ----------------
#define DIMN 2048
#define HEADS 16
#define HD 128
#define RANKN 64
#define IMG_SEQ 2048
#define TXT_SEQ 128
#define SEQN 2176          // IMG_SEQ + TXT_SEQ
#define CONDN 1024
#define BLOCKN 1024        // IMG_SEQ - COND
#define SBSN 1152          // SEQ - COND
#define EPSV 1e-5f

// ---------------- device scratch (no allocation allowed) ----------------
__device__ float g_Q[SEQN * DIMN];
__device__ float g_K[SEQN * DIMN];
__device__ float g_V[SEQN * DIMN];
__device__ float g_O[SEQN * DIMN];
__device__ float g_part[8 * CONDN * 192];

// ---------------- helpers ----------------
__device__ __forceinline__ uint32_t pack_h2(float x, float y) {
    __half2 h = __floats2half2_rn(x, y);
    return *(uint32_t*)&h;
}

__device__ __forceinline__ void mma_f16(float c[4], const uint32_t a[4],
                                        uint32_t b0, uint32_t b1) {
    asm volatile(
        "mma.sync.aligned.m16n8k16.row.col.f32.f16.f16.f32 "
        "{%0,%1,%2,%3}, {%4,%5,%6,%7}, {%8,%9}, {%0,%1,%2,%3};"
        : "+f"(c[0]), "+f"(c[1]), "+f"(c[2]), "+f"(c[3])
        : "r"(a[0]), "r"(a[1]), "r"(a[2]), "r"(a[3]),
          "r"(b0), "r"(b1));
}

#define HLD 40   // halves per smem row (pad: 20 words -> conflict-free frags)

// ===== fp16 projection GEMM + fused LoRA-up =================================
// C[remap(r)] = A_sel(r) @ W_sel(r,z)^T  (+ LoRA-up for cond rows if lora!=0)
// 128x128 CTA tile, 8 warps (32x64 warp tiles), BK=32 (2 k16-steps).
// grid.z selects among up to 3 (W1/W2, C, up) triples.
// lora!=0: for row0 in [BLOCKN, IMG_SEQ), adds (sum_s part[s]) @ up^T (K=64,
//          A cols z*64..z*64+63 of the 192-wide partial buffer).
// remap!=0: output rows rearranged [img | text | cond] (128-aligned regions).
__global__ __launch_bounds__(256, 2) void proj_gemm3h(
    const float* __restrict__ A1, const float* __restrict__ A2,
    const float* __restrict__ Wa0, const float* __restrict__ Wb0, float* __restrict__ C0,
    const float* __restrict__ Wa1, const float* __restrict__ Wb1, float* __restrict__ C1,
    const float* __restrict__ Wa2, const float* __restrict__ Wb2, float* __restrict__ C2,
    const float* __restrict__ part,
    const float* __restrict__ up0, const float* __restrict__ up1,
    const float* __restrict__ up2,
    int Msplit, int N, int K, int lora, int remap) {
    __shared__ __half As[128 * HLD];
    __shared__ __half Bs[128 * HLD];

    const int tid = threadIdx.x;
    const int lane = tid & 31;
    const int warp = tid >> 5;
    const int wm = warp & 3;
    const int wn = warp >> 2;
    const int lrow = lane >> 2;
    const int lcol = lane & 3;
    const int row0 = blockIdx.y * 128;
    const int col0 = blockIdx.x * 128;
    const int z = blockIdx.z;

    const float* A = (row0 < Msplit) ? A1 + (size_t)row0 * K
                                     : A2 + (size_t)(row0 - Msplit) * K;
    const float* W;
    float* C;
    const float* up;
    if (z == 0)      { W = (row0 < Msplit) ? Wa0 : Wb0; C = C0; up = up0; }
    else if (z == 1) { W = (row0 < Msplit) ? Wa1 : Wb1; C = C1; up = up1; }
    else             { W = (row0 < Msplit) ? Wa2 : Wb2; C = C2; up = up2; }

    int row_out0 = row0;
    if (remap) {
        if (row0 >= IMG_SEQ)      row_out0 = row0 - CONDN;     // text -> after img
        else if (row0 >= BLOCKN)  row_out0 = row0 + TXT_SEQ;   // cond -> tail
    }

    float c[2][8][4];
#pragma unroll
    for (int i = 0; i < 2; i++)
#pragma unroll
        for (int j = 0; j < 8; j++)
#pragma unroll
            for (int r = 0; r < 4; r++) c[i][j][r] = 0.f;

    for (int k0 = 0; k0 < K; k0 += 32) {
#pragma unroll
        for (int f = 0; f < 4; f++) {
            int id = tid + f * 256;        // 0..1023
            int r = id >> 3;               // 0..127
            int kq = (id & 7) << 2;        // 0,4,...,28
            float4 va = *(const float4*)&A[(size_t)r * K + k0 + kq];
            *(uint2*)&As[r * HLD + kq] =
                make_uint2(pack_h2(va.x, va.y), pack_h2(va.z, va.w));
            float4 vb = *(const float4*)&W[(size_t)(col0 + r) * K + k0 + kq];
            *(uint2*)&Bs[r * HLD + kq] =
                make_uint2(pack_h2(vb.x, vb.y), pack_h2(vb.z, vb.w));
        }
        __syncthreads();

#pragma unroll
        for (int ks = 0; ks < 2; ks++) {
            const int kb = ks * 16 + 2 * lcol;
            uint32_t a[2][4];
#pragma unroll
            for (int mi = 0; mi < 2; mi++) {
                int ar = wm * 32 + mi * 16 + lrow;
                a[mi][0] = *(const uint32_t*)&As[ar * HLD + kb];
                a[mi][1] = *(const uint32_t*)&As[(ar + 8) * HLD + kb];
                a[mi][2] = *(const uint32_t*)&As[ar * HLD + kb + 8];
                a[mi][3] = *(const uint32_t*)&As[(ar + 8) * HLD + kb + 8];
            }
            uint32_t b[8][2];
#pragma unroll
            for (int ni = 0; ni < 8; ni++) {
                int br = wn * 64 + ni * 8 + lrow;
                b[ni][0] = *(const uint32_t*)&Bs[br * HLD + kb];
                b[ni][1] = *(const uint32_t*)&Bs[br * HLD + kb + 8];
            }
#pragma unroll
            for (int mi = 0; mi < 2; mi++)
#pragma unroll
                for (int ni = 0; ni < 8; ni++)
                    mma_f16(c[mi][ni], a[mi], b[ni][0], b[ni][1]);
        }
        __syncthreads();
    }

    // ---- fused LoRA-up: 2 extra BK=32 iterations (K=64) for cond rows ----
    if (lora && row0 >= BLOCKN && row0 < IMG_SEQ) {
        const int arow0 = row0 - BLOCKN;
#pragma unroll
        for (int e = 0; e < 2; e++) {
            const int k0 = e * 32;
#pragma unroll
            for (int f = 0; f < 4; f++) {
                int id = tid + f * 256;
                int r = id >> 3;
                int kq = (id & 7) << 2;
                const float* pa = part + (size_t)(arow0 + r) * 192 + z * 64 + k0 + kq;
                float4 va = *(const float4*)pa;
#pragma unroll
                for (int s = 1; s < 8; s++) {
                    float4 t = *(const float4*)(pa + (size_t)s * CONDN * 192);
                    va.x += t.x; va.y += t.y; va.z += t.z; va.w += t.w;
                }
                *(uint2*)&As[r * HLD + kq] =
                    make_uint2(pack_h2(va.x, va.y), pack_h2(va.z, va.w));
                float4 vb = *(const float4*)&up[(size_t)(col0 + r) * 64 + k0 + kq];
                *(uint2*)&Bs[r * HLD + kq] =
                    make_uint2(pack_h2(vb.x, vb.y), pack_h2(vb.z, vb.w));
            }
            __syncthreads();
#pragma unroll
            for (int ks = 0; ks < 2; ks++) {
                const int kb = ks * 16 + 2 * lcol;
                uint32_t a[2][4];
#pragma unroll
                for (int mi = 0; mi < 2; mi++) {
                    int ar = wm * 32 + mi * 16 + lrow;
                    a[mi][0] = *(const uint32_t*)&As[ar * HLD + kb];
                    a[mi][1] = *(const uint32_t*)&As[(ar + 8) * HLD + kb];
                    a[mi][2] = *(const uint32_t*)&As[ar * HLD + kb + 8];
                    a[mi][3] = *(const uint32_t*)&As[(ar + 8) * HLD + kb + 8];
                }
                uint32_t b[8][2];
#pragma unroll
                for (int ni = 0; ni < 8; ni++) {
                    int br = wn * 64 + ni * 8 + lrow;
                    b[ni][0] = *(const uint32_t*)&Bs[br * HLD + kb];
                    b[ni][1] = *(const uint32_t*)&Bs[br * HLD + kb + 8];
                }
#pragma unroll
                for (int mi = 0; mi < 2; mi++)
#pragma unroll
                    for (int ni = 0; ni < 8; ni++)
                        mma_f16(c[mi][ni], a[mi], b[ni][0], b[ni][1]);
            }
            __syncthreads();
        }
    }

#pragma unroll
    for (int mi = 0; mi < 2; mi++)
#pragma unroll
        for (int ni = 0; ni < 8; ni++) {
            int gr = row_out0 + wm * 32 + mi * 16 + lrow;
            int gc = col0 + wn * 64 + ni * 8 + lcol * 2;
            *(float2*)&C[(size_t)gr * N + gc] =
                make_float2(c[mi][ni][0], c[mi][ni][1]);
            *(float2*)&C[(size_t)(gr + 8) * N + gc] =
                make_float2(c[mi][ni][2], c[mi][ni][3]);
        }
}

// ===== fp16 LoRA up-projection with inline 8-way partial sum ================
// C[M,N] += (sum_s part[s]) @ W[N,K]^T ; part layout [8][CONDN][64], K=64.
__global__ __launch_bounds__(256) void up_sum_gemm_acc_h(
    const float* __restrict__ part,
    const float* __restrict__ W,
    float* __restrict__ C, int N) {
    __shared__ __half As[128 * HLD];
    __shared__ __half Bs[128 * HLD];

    const int tid = threadIdx.x;
    const int lane = tid & 31;
    const int warp = tid >> 5;
    const int wm = warp & 3;
    const int wn = warp >> 2;
    const int lrow = lane >> 2;
    const int lcol = lane & 3;
    const int row0 = blockIdx.y * 128;
    const int col0 = blockIdx.x * 128;

    float c[2][8][4];
#pragma unroll
    for (int i = 0; i < 2; i++)
#pragma unroll
        for (int j = 0; j < 8; j++)
#pragma unroll
            for (int r = 0; r < 4; r++) c[i][j][r] = 0.f;

    for (int k0 = 0; k0 < 64; k0 += 32) {
#pragma unroll
        for (int f = 0; f < 4; f++) {
            int id = tid + f * 256;
            int r = id >> 3;
            int kq = (id & 7) << 2;
            const float* pa = part + (size_t)(row0 + r) * 64 + k0 + kq;
            float4 va = *(const float4*)pa;
#pragma unroll
            for (int s = 1; s < 8; s++) {
                float4 t = *(const float4*)(pa + (size_t)s * CONDN * 64);
                va.x += t.x; va.y += t.y; va.z += t.z; va.w += t.w;
            }
            *(uint2*)&As[r * HLD + kq] =
                make_uint2(pack_h2(va.x, va.y), pack_h2(va.z, va.w));
            float4 vb = *(const float4*)&W[(size_t)(col0 + r) * 64 + k0 + kq];
            *(uint2*)&Bs[r * HLD + kq] =
                make_uint2(pack_h2(vb.x, vb.y), pack_h2(vb.z, vb.w));
        }
        __syncthreads();

#pragma unroll
        for (int ks = 0; ks < 2; ks++) {
            const int kb = ks * 16 + 2 * lcol;
            uint32_t a[2][4];
#pragma unroll
            for (int mi = 0; mi < 2; mi++) {
                int ar = wm * 32 + mi * 16 + lrow;
                a[mi][0] = *(const uint32_t*)&As[ar * HLD + kb];
                a[mi][1] = *(const uint32_t*)&As[(ar + 8) * HLD + kb];
                a[mi][2] = *(const uint32_t*)&As[ar * HLD + kb + 8];
                a[mi][3] = *(const uint32_t*)&As[(ar + 8) * HLD + kb + 8];
            }
            uint32_t b[8][2];
#pragma unroll
            for (int ni = 0; ni < 8; ni++) {
                int br = wn * 64 + ni * 8 + lrow;
                b[ni][0] = *(const uint32_t*)&Bs[br * HLD + kb];
                b[ni][1] = *(const uint32_t*)&Bs[br * HLD + kb + 8];
            }
#pragma unroll
            for (int mi = 0; mi < 2; mi++)
#pragma unroll
                for (int ni = 0; ni < 8; ni++)
                    mma_f16(c[mi][ni], a[mi], b[ni][0], b[ni][1]);
        }
        __syncthreads();
    }

#pragma unroll
    for (int mi = 0; mi < 2; mi++)
#pragma unroll
        for (int ni = 0; ni < 8; ni++) {
            int gr = row0 + wm * 32 + mi * 16 + lrow;
            int gc = col0 + wn * 64 + ni * 8 + lcol * 2;
            float2* p0 = (float2*)&C[(size_t)gr * N + gc];
            float2* p1 = (float2*)&C[(size_t)(gr + 8) * N + gc];
            float2 o0 = *p0, o1 = *p1;
            o0.x += c[mi][ni][0]; o0.y += c[mi][ni][1];
            o1.x += c[mi][ni][2]; o1.y += c[mi][ni][3];
            *p0 = o0; *p1 = o1;
        }
}

// ===== fp16 split-K LoRA down-projection (up to 3 fused weights) =============
__global__ __launch_bounds__(256) void down_gemm_h(const float* __restrict__ A,
                                                   const float* __restrict__ w0,
                                                   const float* __restrict__ w1,
                                                   const float* __restrict__ w2,
                                                   float* __restrict__ part,
                                                   int M, int Ntot, int Kfull) {
    __shared__ __half As[128 * HLD];
    __shared__ __half Ws[64 * HLD];

    const int cb = blockIdx.x, mb = blockIdx.y, sp = blockIdx.z;
    const int Kc = Kfull >> 3;
    const int kbase = sp * Kc;
    const float* W = (cb == 0) ? w0 : (cb == 1 ? w1 : w2);

    const int tid = threadIdx.x;
    const int lane = tid & 31;
    const int warp = tid >> 5;
    const int wm = warp & 3;
    const int wn = warp >> 2;
    const int lrow = lane >> 2;
    const int lcol = lane & 3;

    float c[2][4][4];
#pragma unroll
    for (int i = 0; i < 2; i++)
#pragma unroll
        for (int j = 0; j < 4; j++)
#pragma unroll
            for (int r = 0; r < 4; r++) c[i][j][r] = 0.f;

    for (int k0 = 0; k0 < Kc; k0 += 32) {
#pragma unroll
        for (int f = 0; f < 4; f++) {
            int id = tid + f * 256;
            int r = id >> 3;
            int kq = (id & 7) << 2;
            float4 va = *(const float4*)&A[(size_t)(mb * 128 + r) * Kfull + kbase + k0 + kq];
            *(uint2*)&As[r * HLD + kq] =
                make_uint2(pack_h2(va.x, va.y), pack_h2(va.z, va.w));
        }
#pragma unroll
        for (int f = 0; f < 2; f++) {
            int id = tid + f * 256;
            int r = id >> 3;          // 0..63
            int kq = (id & 7) << 2;
            float4 vb = *(const float4*)&W[(size_t)r * Kfull + kbase + k0 + kq];
            *(uint2*)&Ws[r * HLD + kq] =
                make_uint2(pack_h2(vb.x, vb.y), pack_h2(vb.z, vb.w));
        }
        __syncthreads();

#pragma unroll
        for (int ks = 0; ks < 2; ks++) {
            const int kb = ks * 16 + 2 * lcol;
            uint32_t a[2][4];
#pragma unroll
            for (int mi = 0; mi < 2; mi++) {
                int ar = wm * 32 + mi * 16 + lrow;
                a[mi][0] = *(const uint32_t*)&As[ar * HLD + kb];
                a[mi][1] = *(const uint32_t*)&As[(ar + 8) * HLD + kb];
                a[mi][2] = *(const uint32_t*)&As[ar * HLD + kb + 8];
                a[mi][3] = *(const uint32_t*)&As[(ar + 8) * HLD + kb + 8];
            }
            uint32_t b[4][2];
#pragma unroll
            for (int ni = 0; ni < 4; ni++) {
                int br = wn * 32 + ni * 8 + lrow;
                b[ni][0] = *(const uint32_t*)&Ws[br * HLD + kb];
                b[ni][1] = *(const uint32_t*)&Ws[br * HLD + kb + 8];
            }
#pragma unroll
            for (int mi = 0; mi < 2; mi++)
#pragma unroll
                for (int ni = 0; ni < 4; ni++)
                    mma_f16(c[mi][ni], a[mi], b[ni][0], b[ni][1]);
        }
        __syncthreads();
    }

    float* basep = part + (size_t)sp * M * Ntot;
#pragma unroll
    for (int mi = 0; mi < 2; mi++)
#pragma unroll
        for (int ni = 0; ni < 4; ni++) {
            int gr = mb * 128 + wm * 32 + mi * 16 + lrow;
            int gc = cb * 64 + wn * 32 + ni * 8 + lcol * 2;
            *(float2*)&basep[(size_t)gr * Ntot + gc] =
                make_float2(c[mi][ni][0], c[mi][ni][1]);
            *(float2*)&basep[(size_t)(gr + 8) * Ntot + gc] =
                make_float2(c[mi][ni][2], c[mi][ni][3]);
        }
}

// ---------------- fused RMS-norm (over DIM) + rope for Q and K ----------------
__global__ __launch_bounds__(256) void rmsrope_kernel(
    float* __restrict__ Q, float* __restrict__ K,
    const float* __restrict__ rope,
    const float* __restrict__ gq, const float* __restrict__ gk,
    const float* __restrict__ gqt, const float* __restrict__ gkt) {
    const int row = blockIdx.x;
    const int tid = threadIdx.x;
    __shared__ float sbuf[18];

    float* qrow = Q + (size_t)row * DIMN;
    float* krow = K + (size_t)row * DIMN;

    float sq = 0.f, sk = 0.f;
    for (int c4 = tid; c4 < DIMN / 4; c4 += 256) {
        float4 q = *(const float4*)&qrow[c4 * 4];
        sq += q.x * q.x + q.y * q.y + q.z * q.z + q.w * q.w;
        float4 kk = *(const float4*)&krow[c4 * 4];
        sk += kk.x * kk.x + kk.y * kk.y + kk.z * kk.z + kk.w * kk.w;
    }
#pragma unroll
    for (int o = 16; o > 0; o >>= 1) {
        sq += __shfl_xor_sync(0xffffffffu, sq, o);
        sk += __shfl_xor_sync(0xffffffffu, sk, o);
    }
    int w = tid >> 5;
    if ((tid & 31) == 0) { sbuf[w] = sq; sbuf[8 + w] = sk; }
    __syncthreads();
    if (tid == 0) {
        float a = 0.f, b = 0.f;
        for (int i = 0; i < 8; i++) { a += sbuf[i]; b += sbuf[8 + i]; }
        sbuf[16] = a; sbuf[17] = b;
    }
    __syncthreads();
    const float invq = rsqrtf(sbuf[16] / (float)DIMN + EPSV);
    const float invk = rsqrtf(sbuf[17] / (float)DIMN + EPSV);
    const float* gQ = (row < IMG_SEQ) ? gq : gqt;
    const float* gK = (row < IMG_SEQ) ? gk : gkt;
    const float* rp = rope + (size_t)row * 256;

    for (int pi = tid; pi < DIMN / 2; pi += 256) {
        int c0 = pi * 2;
        int j = pi & 63;
        float4 r = *(const float4*)&rp[j * 4];
        float x0 = qrow[c0] * invq * gQ[c0];
        float x1 = qrow[c0 + 1] * invq * gQ[c0 + 1];
        qrow[c0]     = r.x * x0 + r.y * x1;
        qrow[c0 + 1] = r.z * x0 + r.w * x1;
        float y0 = krow[c0] * invk * gK[c0];
        float y1 = krow[c0 + 1] * invk * gK[c0 + 1];
        krow[c0]     = r.x * y0 + r.y * y1;
        krow[c0 + 1] = r.z * y0 + r.w * y1;
    }
}

// ---------------- flash attention: all-fp16 mma, fp32 accum ----------------
// Br=128 (8 warps x 16 rows), Bc=64.
#define KLD 136                      // halves per Ks row
#define VLD 72                       // halves per Vt row (d-major)
#define PLD 72                       // halves per Ps row
#define FB_KS_OFF 0                  // half Ks[64][136]  = 17408 B
#define FB_VT_OFF 17408              // half Vt[128][72]  = 18432 B
#define FB_PS_OFF 35840              // half Ps[128][72]  = 18432 B
#define FB_BYTES 54272

__global__ __launch_bounds__(256) void flash_mma(const float* __restrict__ Q,
                                                 const float* __restrict__ K,
                                                 const float* __restrict__ V,
                                                 float* __restrict__ O) {
    extern __shared__ char smc[];
    __half* Ks = (__half*)(smc + FB_KS_OFF);
    __half* Vt = (__half*)(smc + FB_VT_OFF);
    __half* Ps = (__half*)(smc + FB_PS_OFF);

    const int tid = threadIdx.x;
    const int lane = tid & 31;
    const int warp = tid >> 5;
    const int lrow = lane >> 2;
    const int lcol = lane & 3;
    const int qrow0 = blockIdx.x * 128;
    const size_t hoff = (size_t)blockIdx.y * HD;
    const float scale = 0.08838834764831844f;  // 1/sqrt(128)

    // Q fragments (fp16, pre-scaled): 8 k16-steps x 4 b32
    uint32_t qa[8][4];
    {
        const float* qb = Q + (size_t)(qrow0 + warp * 16) * DIMN + hoff;
#pragma unroll
        for (int ks = 0; ks < 8; ks++) {
            int kb = ks * 16 + 2 * lcol;
            qa[ks][0] = pack_h2(scale * qb[(size_t)lrow * DIMN + kb],
                                scale * qb[(size_t)lrow * DIMN + kb + 1]);
            qa[ks][1] = pack_h2(scale * qb[(size_t)(lrow + 8) * DIMN + kb],
                                scale * qb[(size_t)(lrow + 8) * DIMN + kb + 1]);
            qa[ks][2] = pack_h2(scale * qb[(size_t)lrow * DIMN + kb + 8],
                                scale * qb[(size_t)lrow * DIMN + kb + 9]);
            qa[ks][3] = pack_h2(scale * qb[(size_t)(lrow + 8) * DIMN + kb + 8],
                                scale * qb[(size_t)(lrow + 8) * DIMN + kb + 9]);
        }
    }

    float o[16][4];
#pragma unroll
    for (int ni = 0; ni < 16; ni++)
#pragma unroll
        for (int r = 0; r < 4; r++) o[ni][r] = 0.f;
    float m0 = -INFINITY, m1 = -INFINITY, l0 = 0.f, l1 = 0.f;

    const int kt0 = (qrow0 >= SBSN) ? (SBSN / 64) : 0;

    for (int kt = kt0; kt < SEQN / 64; kt++) {
        const int kr0 = kt * 64;
        __syncthreads();
        // K tile -> Ks[64][KLD] halves
#pragma unroll
        for (int f = 0; f < 8; f++) {
            int id = tid + f * 256;           // 0..2047
            int r = id >> 5;                  // 0..63
            int k4 = (id & 31) << 2;          // 0..124
            float4 v = *(const float4*)&K[(size_t)(kr0 + r) * DIMN + hoff + k4];
            *(uint2*)&Ks[r * KLD + k4] =
                make_uint2(pack_h2(v.x, v.y), pack_h2(v.z, v.w));
        }
        // V tile -> Vt[d][j] transposed halves
#pragma unroll
        for (int f = 0; f < 8; f++) {
            int id = tid + f * 256;
            int j = id & 63;
            int d4 = (id >> 6) << 2;
            float4 v = *(const float4*)&V[(size_t)(kr0 + j) * DIMN + hoff + d4];
            Vt[(d4 + 0) * VLD + j] = __float2half_rn(v.x);
            Vt[(d4 + 1) * VLD + j] = __float2half_rn(v.y);
            Vt[(d4 + 2) * VLD + j] = __float2half_rn(v.z);
            Vt[(d4 + 3) * VLD + j] = __float2half_rn(v.w);
        }
        __syncthreads();

        // S = Q @ K^T : 8 k16-steps, 8 n-tiles
        float s[8][4];
#pragma unroll
        for (int ni = 0; ni < 8; ni++)
#pragma unroll
            for (int r = 0; r < 4; r++) s[ni][r] = 0.f;
#pragma unroll
        for (int ks = 0; ks < 8; ks++) {
            const int kb = ks * 16 + 2 * lcol;
#pragma unroll
            for (int ni = 0; ni < 8; ni++) {
                int br = ni * 8 + lrow;
                uint32_t b0 = *(const uint32_t*)&Ks[br * KLD + kb];
                uint32_t b1 = *(const uint32_t*)&Ks[br * KLD + kb + 8];
                mma_f16(s[ni], qa[ks], b0, b1);
            }
        }

        // online softmax (warp-local)
        float mt0 = -INFINITY, mt1 = -INFINITY;
#pragma unroll
        for (int ni = 0; ni < 8; ni++) {
            mt0 = fmaxf(mt0, fmaxf(s[ni][0], s[ni][1]));
            mt1 = fmaxf(mt1, fmaxf(s[ni][2], s[ni][3]));
        }
#pragma unroll
        for (int off = 1; off <= 2; off <<= 1) {
            mt0 = fmaxf(mt0, __shfl_xor_sync(0xffffffffu, mt0, off));
            mt1 = fmaxf(mt1, __shfl_xor_sync(0xffffffffu, mt1, off));
        }
        float mn0 = fmaxf(m0, mt0), mn1 = fmaxf(m1, mt1);
        float corr0 = __expf(m0 - mn0), corr1 = __expf(m1 - mn1);
        m0 = mn0; m1 = mn1;

        // P in fp16; l sums the ROUNDED halves for exact O/l consistency
        float ps0 = 0.f, ps1 = 0.f;
#pragma unroll
        for (int ni = 0; ni < 8; ni++) {
            __half2 h01 = __floats2half2_rn(__expf(s[ni][0] - mn0),
                                            __expf(s[ni][1] - mn0));
            __half2 h23 = __floats2half2_rn(__expf(s[ni][2] - mn1),
                                            __expf(s[ni][3] - mn1));
            ps0 += __low2float(h01) + __high2float(h01);
            ps1 += __low2float(h23) + __high2float(h23);
            int col = ni * 8 + 2 * lcol;
            *(uint32_t*)&Ps[(warp * 16 + lrow) * PLD + col] = *(uint32_t*)&h01;
            *(uint32_t*)&Ps[(warp * 16 + lrow + 8) * PLD + col] = *(uint32_t*)&h23;
        }
#pragma unroll
        for (int off = 1; off <= 2; off <<= 1) {
            ps0 += __shfl_xor_sync(0xffffffffu, ps0, off);
            ps1 += __shfl_xor_sync(0xffffffffu, ps1, off);
        }
        l0 = l0 * corr0 + ps0;
        l1 = l1 * corr1 + ps1;
#pragma unroll
        for (int ni = 0; ni < 16; ni++) {
            o[ni][0] *= corr0; o[ni][1] *= corr0;
            o[ni][2] *= corr1; o[ni][3] *= corr1;
        }
        __syncwarp();

        // O += P @ V : 4 k16-steps (j=64), 16 n-tiles, all fp16
#pragma unroll
        for (int ks = 0; ks < 4; ks++) {
            const int kb = ks * 16 + 2 * lcol;
            uint32_t a[4];
            a[0] = *(const uint32_t*)&Ps[(warp * 16 + lrow) * PLD + kb];
            a[1] = *(const uint32_t*)&Ps[(warp * 16 + lrow + 8) * PLD + kb];
            a[2] = *(const uint32_t*)&Ps[(warp * 16 + lrow) * PLD + kb + 8];
            a[3] = *(const uint32_t*)&Ps[(warp * 16 + lrow + 8) * PLD + kb + 8];
#pragma unroll
            for (int ni = 0; ni < 16; ni++) {
                int br = ni * 8 + lrow;
                uint32_t b0 = *(const uint32_t*)&Vt[br * VLD + kb];
                uint32_t b1 = *(const uint32_t*)&Vt[br * VLD + kb + 8];
                mma_f16(o[ni], a, b0, b1);
            }
        }
    }

    const float inv0 = 1.f / l0, inv1 = 1.f / l1;
    const int gr0 = qrow0 + warp * 16 + lrow;
#pragma unroll
    for (int ni = 0; ni < 16; ni++) {
        int gc = ni * 8 + lcol * 2;
        *(float2*)&O[(size_t)gr0 * DIMN + hoff + gc] =
            make_float2(o[ni][0] * inv0, o[ni][1] * inv0);
        *(float2*)&O[(size_t)(gr0 + 8) * DIMN + hoff + gc] =
            make_float2(o[ni][2] * inv1, o[ni][3] * inv1);
    }
}

// ---------------- launch ----------------
extern "C" void kernel_launch(void* const* d_in, const int* in_sizes, int n_in,
                              void* d_out, int out_size) {
    const float* img  = (const float*)d_in[0];
    const float* txt  = (const float*)d_in[1];
    const float* rope = (const float*)d_in[2];
    const float* wq   = (const float*)d_in[3];
    const float* wk   = (const float*)d_in[4];
    const float* wv   = (const float*)d_in[5];
    const float* wo   = (const float*)d_in[6];
    const float* wq_t = (const float*)d_in[7];
    const float* wk_t = (const float*)d_in[8];
    const float* wv_t = (const float*)d_in[9];
    const float* wo_t = (const float*)d_in[10];
    const float* gq   = (const float*)d_in[11];
    const float* gk   = (const float*)d_in[12];
    const float* gqt  = (const float*)d_in[13];
    const float* gkt  = (const float*)d_in[14];
    const float* q_down = (const float*)d_in[15];
    const float* q_up   = (const float*)d_in[16];
    const float* k_down = (const float*)d_in[17];
    const float* k_up   = (const float*)d_in[18];
    const float* v_down = (const float*)d_in[19];
    const float* v_up   = (const float*)d_in[20];
    const float* p_down = (const float*)d_in[21];
    const float* p_up   = (const float*)d_in[22];
    float* out = (float*)d_out;

    float *Q, *K, *V, *O, *part;
    cudaGetSymbolAddress((void**)&Q,    g_Q);
    cudaGetSymbolAddress((void**)&K,    g_K);
    cudaGetSymbolAddress((void**)&V,    g_V);
    cudaGetSymbolAddress((void**)&O,    g_O);
    cudaGetSymbolAddress((void**)&part, g_part);

    const float* img_cond = img + (size_t)BLOCKN * DIMN;
    float* out_cond = out + (size_t)SBSN * DIMN;   // cond region in output

    // 1) fused LoRA down-projections (q/k/v), split-K 8-way -> partials
    down_gemm_h<<<dim3(3, CONDN / 128, 8), 256>>>(img_cond, q_down, k_down, v_down,
                                                  part, CONDN, 192, DIMN);

    // 2) QKV projections in ONE launch, LoRA-up FUSED into cond-row epilogue
    proj_gemm3h<<<dim3(DIMN / 128, SEQN / 128, 3), 256>>>(
        img, txt,
        wq, wq_t, Q,
        wk, wk_t, K,
        wv, wv_t, V,
        part, q_up, k_up, v_up,
        IMG_SEQ, DIMN, DIMN, 1, 0);

    // 3) RMS + rope
    rmsrope_kernel<<<SEQN, 256>>>(Q, K, rope, gq, gk, gqt, gkt);

    // 4) flash attention (all-fp16 mma)
    cudaFuncSetAttribute(flash_mma, cudaFuncAttributeMaxDynamicSharedMemorySize,
                         FB_BYTES);
    flash_mma<<<dim3(SEQN / 128, HEADS), 256, FB_BYTES>>>(Q, K, V, O);

    // 5) output projection, written DIRECTLY in output layout [img|text|cond]
    proj_gemm3h<<<dim3(DIMN / 128, SEQN / 128, 1), 256>>>(
        O, O + (size_t)IMG_SEQ * DIMN,
        wo, wo_t, out,
        wo, wo_t, out,
        wo, wo_t, out,
        part, q_up, k_up, v_up,
        IMG_SEQ, DIMN, DIMN, 0, 1);

    // 6) post-projection LoRA on cond region of out (down -> fused-sum up)
    down_gemm_h<<<dim3(1, CONDN / 128, 8), 256>>>(out_cond,
                                                  p_down, p_down, p_down,
                                                  part, CONDN, 64, DIMN);
    up_sum_gemm_acc_h<<<dim3(DIMN / 128, CONDN / 128), 256>>>(part, p_up,
                                                              out_cond, DIMN);
}

// round 9
// speedup vs baseline: 8.3770x; 1.1546x over previous
#include <cuda_runtime.h>
#include <cuda_fp16.h>
#include <math.h>
#include <stdint.h>

// ---------------- problem constants ----------------
#define DIMN 2048
#define HEADS 16
#define HD 128
#define RANKN 64
#define IMG_SEQ 2048
#define TXT_SEQ 128
#define SEQN 2176          // IMG_SEQ + TXT_SEQ
#define CONDN 1024
#define BLOCKN 1024        // IMG_SEQ - COND
#define SBSN 1152          // SEQ - COND
#define EPSV 1e-5f

// ---------------- device scratch (no allocation allowed) ----------------
__device__ float g_Q[SEQN * DIMN];
__device__ float g_K[SEQN * DIMN];
__device__ float g_V[SEQN * DIMN];
__device__ float g_O[SEQN * DIMN];
__device__ float g_part[8 * CONDN * 192];
__device__ __half g_Qh[SEQN * DIMN];
__device__ __half g_Kh[SEQN * DIMN];
__device__ __half g_Vth[DIMN * SEQN];   // per head: [d=128][seq] fp16

// ---------------- helpers ----------------
__device__ __forceinline__ uint32_t pack_h2(float x, float y) {
    __half2 h = __floats2half2_rn(x, y);
    return *(uint32_t*)&h;
}

__device__ __forceinline__ void mma_f16(float c[4], const uint32_t a[4],
                                        uint32_t b0, uint32_t b1) {
    asm volatile(
        "mma.sync.aligned.m16n8k16.row.col.f32.f16.f16.f32 "
        "{%0,%1,%2,%3}, {%4,%5,%6,%7}, {%8,%9}, {%0,%1,%2,%3};"
        : "+f"(c[0]), "+f"(c[1]), "+f"(c[2]), "+f"(c[3])
        : "r"(a[0]), "r"(a[1]), "r"(a[2]), "r"(a[3]),
          "r"(b0), "r"(b1));
}

__device__ __forceinline__ void cp_async16(uint32_t dst_smem, const void* src) {
    asm volatile("cp.async.cg.shared.global [%0], [%1], 16;"
                 :: "r"(dst_smem), "l"(src));
}
__device__ __forceinline__ void cp_commit() {
    asm volatile("cp.async.commit_group;" ::: "memory");
}
template <int N>
__device__ __forceinline__ void cp_wait() {
    asm volatile("cp.async.wait_group %0;" :: "n"(N) : "memory");
}

#define HLD 40   // halves per smem row (pad: 20 words -> conflict-free frags)

// ===== fp16 projection GEMM + fused LoRA-up =================================
// C[remap(r)] = A_sel(r) @ W_sel(r,z)^T  (+ LoRA-up for cond rows if lora!=0)
__global__ __launch_bounds__(256, 2) void proj_gemm3h(
    const float* __restrict__ A1, const float* __restrict__ A2,
    const float* __restrict__ Wa0, const float* __restrict__ Wb0, float* __restrict__ C0,
    const float* __restrict__ Wa1, const float* __restrict__ Wb1, float* __restrict__ C1,
    const float* __restrict__ Wa2, const float* __restrict__ Wb2, float* __restrict__ C2,
    const float* __restrict__ part,
    const float* __restrict__ up0, const float* __restrict__ up1,
    const float* __restrict__ up2,
    int Msplit, int N, int K, int lora, int remap) {
    __shared__ __half As[128 * HLD];
    __shared__ __half Bs[128 * HLD];

    const int tid = threadIdx.x;
    const int lane = tid & 31;
    const int warp = tid >> 5;
    const int wm = warp & 3;
    const int wn = warp >> 2;
    const int lrow = lane >> 2;
    const int lcol = lane & 3;
    const int row0 = blockIdx.y * 128;
    const int col0 = blockIdx.x * 128;
    const int z = blockIdx.z;

    const float* A = (row0 < Msplit) ? A1 + (size_t)row0 * K
                                     : A2 + (size_t)(row0 - Msplit) * K;
    const float* W;
    float* C;
    const float* up;
    if (z == 0)      { W = (row0 < Msplit) ? Wa0 : Wb0; C = C0; up = up0; }
    else if (z == 1) { W = (row0 < Msplit) ? Wa1 : Wb1; C = C1; up = up1; }
    else             { W = (row0 < Msplit) ? Wa2 : Wb2; C = C2; up = up2; }

    int row_out0 = row0;
    if (remap) {
        if (row0 >= IMG_SEQ)      row_out0 = row0 - CONDN;
        else if (row0 >= BLOCKN)  row_out0 = row0 + TXT_SEQ;
    }

    float c[2][8][4];
#pragma unroll
    for (int i = 0; i < 2; i++)
#pragma unroll
        for (int j = 0; j < 8; j++)
#pragma unroll
            for (int r = 0; r < 4; r++) c[i][j][r] = 0.f;

    for (int k0 = 0; k0 < K; k0 += 32) {
#pragma unroll
        for (int f = 0; f < 4; f++) {
            int id = tid + f * 256;
            int r = id >> 3;
            int kq = (id & 7) << 2;
            float4 va = *(const float4*)&A[(size_t)r * K + k0 + kq];
            *(uint2*)&As[r * HLD + kq] =
                make_uint2(pack_h2(va.x, va.y), pack_h2(va.z, va.w));
            float4 vb = *(const float4*)&W[(size_t)(col0 + r) * K + k0 + kq];
            *(uint2*)&Bs[r * HLD + kq] =
                make_uint2(pack_h2(vb.x, vb.y), pack_h2(vb.z, vb.w));
        }
        __syncthreads();

#pragma unroll
        for (int ks = 0; ks < 2; ks++) {
            const int kb = ks * 16 + 2 * lcol;
            uint32_t a[2][4];
#pragma unroll
            for (int mi = 0; mi < 2; mi++) {
                int ar = wm * 32 + mi * 16 + lrow;
                a[mi][0] = *(const uint32_t*)&As[ar * HLD + kb];
                a[mi][1] = *(const uint32_t*)&As[(ar + 8) * HLD + kb];
                a[mi][2] = *(const uint32_t*)&As[ar * HLD + kb + 8];
                a[mi][3] = *(const uint32_t*)&As[(ar + 8) * HLD + kb + 8];
            }
            uint32_t b[8][2];
#pragma unroll
            for (int ni = 0; ni < 8; ni++) {
                int br = wn * 64 + ni * 8 + lrow;
                b[ni][0] = *(const uint32_t*)&Bs[br * HLD + kb];
                b[ni][1] = *(const uint32_t*)&Bs[br * HLD + kb + 8];
            }
#pragma unroll
            for (int mi = 0; mi < 2; mi++)
#pragma unroll
                for (int ni = 0; ni < 8; ni++)
                    mma_f16(c[mi][ni], a[mi], b[ni][0], b[ni][1]);
        }
        __syncthreads();
    }

    // ---- fused LoRA-up: 2 extra BK=32 iterations (K=64) for cond rows ----
    if (lora && row0 >= BLOCKN && row0 < IMG_SEQ) {
        const int arow0 = row0 - BLOCKN;
#pragma unroll
        for (int e = 0; e < 2; e++) {
            const int k0 = e * 32;
#pragma unroll
            for (int f = 0; f < 4; f++) {
                int id = tid + f * 256;
                int r = id >> 3;
                int kq = (id & 7) << 2;
                const float* pa = part + (size_t)(arow0 + r) * 192 + z * 64 + k0 + kq;
                float4 va = *(const float4*)pa;
#pragma unroll
                for (int s = 1; s < 8; s++) {
                    float4 t = *(const float4*)(pa + (size_t)s * CONDN * 192);
                    va.x += t.x; va.y += t.y; va.z += t.z; va.w += t.w;
                }
                *(uint2*)&As[r * HLD + kq] =
                    make_uint2(pack_h2(va.x, va.y), pack_h2(va.z, va.w));
                float4 vb = *(const float4*)&up[(size_t)(col0 + r) * 64 + k0 + kq];
                *(uint2*)&Bs[r * HLD + kq] =
                    make_uint2(pack_h2(vb.x, vb.y), pack_h2(vb.z, vb.w));
            }
            __syncthreads();
#pragma unroll
            for (int ks = 0; ks < 2; ks++) {
                const int kb = ks * 16 + 2 * lcol;
                uint32_t a[2][4];
#pragma unroll
                for (int mi = 0; mi < 2; mi++) {
                    int ar = wm * 32 + mi * 16 + lrow;
                    a[mi][0] = *(const uint32_t*)&As[ar * HLD + kb];
                    a[mi][1] = *(const uint32_t*)&As[(ar + 8) * HLD + kb];
                    a[mi][2] = *(const uint32_t*)&As[ar * HLD + kb + 8];
                    a[mi][3] = *(const uint32_t*)&As[(ar + 8) * HLD + kb + 8];
                }
                uint32_t b[8][2];
#pragma unroll
                for (int ni = 0; ni < 8; ni++) {
                    int br = wn * 64 + ni * 8 + lrow;
                    b[ni][0] = *(const uint32_t*)&Bs[br * HLD + kb];
                    b[ni][1] = *(const uint32_t*)&Bs[br * HLD + kb + 8];
                }
#pragma unroll
                for (int mi = 0; mi < 2; mi++)
#pragma unroll
                    for (int ni = 0; ni < 8; ni++)
                        mma_f16(c[mi][ni], a[mi], b[ni][0], b[ni][1]);
            }
            __syncthreads();
        }
    }

#pragma unroll
    for (int mi = 0; mi < 2; mi++)
#pragma unroll
        for (int ni = 0; ni < 8; ni++) {
            int gr = row_out0 + wm * 32 + mi * 16 + lrow;
            int gc = col0 + wn * 64 + ni * 8 + lcol * 2;
            *(float2*)&C[(size_t)gr * N + gc] =
                make_float2(c[mi][ni][0], c[mi][ni][1]);
            *(float2*)&C[(size_t)(gr + 8) * N + gc] =
                make_float2(c[mi][ni][2], c[mi][ni][3]);
        }
}

// ===== fp16 LoRA up-projection with inline 8-way partial sum ================
__global__ __launch_bounds__(256) void up_sum_gemm_acc_h(
    const float* __restrict__ part,
    const float* __restrict__ W,
    float* __restrict__ C, int N) {
    __shared__ __half As[128 * HLD];
    __shared__ __half Bs[128 * HLD];

    const int tid = threadIdx.x;
    const int lane = tid & 31;
    const int warp = tid >> 5;
    const int wm = warp & 3;
    const int wn = warp >> 2;
    const int lrow = lane >> 2;
    const int lcol = lane & 3;
    const int row0 = blockIdx.y * 128;
    const int col0 = blockIdx.x * 128;

    float c[2][8][4];
#pragma unroll
    for (int i = 0; i < 2; i++)
#pragma unroll
        for (int j = 0; j < 8; j++)
#pragma unroll
            for (int r = 0; r < 4; r++) c[i][j][r] = 0.f;

    for (int k0 = 0; k0 < 64; k0 += 32) {
#pragma unroll
        for (int f = 0; f < 4; f++) {
            int id = tid + f * 256;
            int r = id >> 3;
            int kq = (id & 7) << 2;
            const float* pa = part + (size_t)(row0 + r) * 64 + k0 + kq;
            float4 va = *(const float4*)pa;
#pragma unroll
            for (int s = 1; s < 8; s++) {
                float4 t = *(const float4*)(pa + (size_t)s * CONDN * 64);
                va.x += t.x; va.y += t.y; va.z += t.z; va.w += t.w;
            }
            *(uint2*)&As[r * HLD + kq] =
                make_uint2(pack_h2(va.x, va.y), pack_h2(va.z, va.w));
            float4 vb = *(const float4*)&W[(size_t)(col0 + r) * 64 + k0 + kq];
            *(uint2*)&Bs[r * HLD + kq] =
                make_uint2(pack_h2(vb.x, vb.y), pack_h2(vb.z, vb.w));
        }
        __syncthreads();

#pragma unroll
        for (int ks = 0; ks < 2; ks++) {
            const int kb = ks * 16 + 2 * lcol;
            uint32_t a[2][4];
#pragma unroll
            for (int mi = 0; mi < 2; mi++) {
                int ar = wm * 32 + mi * 16 + lrow;
                a[mi][0] = *(const uint32_t*)&As[ar * HLD + kb];
                a[mi][1] = *(const uint32_t*)&As[(ar + 8) * HLD + kb];
                a[mi][2] = *(const uint32_t*)&As[ar * HLD + kb + 8];
                a[mi][3] = *(const uint32_t*)&As[(ar + 8) * HLD + kb + 8];
            }
            uint32_t b[8][2];
#pragma unroll
            for (int ni = 0; ni < 8; ni++) {
                int br = wn * 64 + ni * 8 + lrow;
                b[ni][0] = *(const uint32_t*)&Bs[br * HLD + kb];
                b[ni][1] = *(const uint32_t*)&Bs[br * HLD + kb + 8];
            }
#pragma unroll
            for (int mi = 0; mi < 2; mi++)
#pragma unroll
                for (int ni = 0; ni < 8; ni++)
                    mma_f16(c[mi][ni], a[mi], b[ni][0], b[ni][1]);
        }
        __syncthreads();
    }

#pragma unroll
    for (int mi = 0; mi < 2; mi++)
#pragma unroll
        for (int ni = 0; ni < 8; ni++) {
            int gr = row0 + wm * 32 + mi * 16 + lrow;
            int gc = col0 + wn * 64 + ni * 8 + lcol * 2;
            float2* p0 = (float2*)&C[(size_t)gr * N + gc];
            float2* p1 = (float2*)&C[(size_t)(gr + 8) * N + gc];
            float2 o0 = *p0, o1 = *p1;
            o0.x += c[mi][ni][0]; o0.y += c[mi][ni][1];
            o1.x += c[mi][ni][2]; o1.y += c[mi][ni][3];
            *p0 = o0; *p1 = o1;
        }
}

// ===== fp16 split-K LoRA down-projection (up to 3 fused weights) =============
__global__ __launch_bounds__(256) void down_gemm_h(const float* __restrict__ A,
                                                   const float* __restrict__ w0,
                                                   const float* __restrict__ w1,
                                                   const float* __restrict__ w2,
                                                   float* __restrict__ part,
                                                   int M, int Ntot, int Kfull) {
    __shared__ __half As[128 * HLD];
    __shared__ __half Ws[64 * HLD];

    const int cb = blockIdx.x, mb = blockIdx.y, sp = blockIdx.z;
    const int Kc = Kfull >> 3;
    const int kbase = sp * Kc;
    const float* W = (cb == 0) ? w0 : (cb == 1 ? w1 : w2);

    const int tid = threadIdx.x;
    const int lane = tid & 31;
    const int warp = tid >> 5;
    const int wm = warp & 3;
    const int wn = warp >> 2;
    const int lrow = lane >> 2;
    const int lcol = lane & 3;

    float c[2][4][4];
#pragma unroll
    for (int i = 0; i < 2; i++)
#pragma unroll
        for (int j = 0; j < 4; j++)
#pragma unroll
            for (int r = 0; r < 4; r++) c[i][j][r] = 0.f;

    for (int k0 = 0; k0 < Kc; k0 += 32) {
#pragma unroll
        for (int f = 0; f < 4; f++) {
            int id = tid + f * 256;
            int r = id >> 3;
            int kq = (id & 7) << 2;
            float4 va = *(const float4*)&A[(size_t)(mb * 128 + r) * Kfull + kbase + k0 + kq];
            *(uint2*)&As[r * HLD + kq] =
                make_uint2(pack_h2(va.x, va.y), pack_h2(va.z, va.w));
        }
#pragma unroll
        for (int f = 0; f < 2; f++) {
            int id = tid + f * 256;
            int r = id >> 3;
            int kq = (id & 7) << 2;
            float4 vb = *(const float4*)&W[(size_t)r * Kfull + kbase + k0 + kq];
            *(uint2*)&Ws[r * HLD + kq] =
                make_uint2(pack_h2(vb.x, vb.y), pack_h2(vb.z, vb.w));
        }
        __syncthreads();

#pragma unroll
        for (int ks = 0; ks < 2; ks++) {
            const int kb = ks * 16 + 2 * lcol;
            uint32_t a[2][4];
#pragma unroll
            for (int mi = 0; mi < 2; mi++) {
                int ar = wm * 32 + mi * 16 + lrow;
                a[mi][0] = *(const uint32_t*)&As[ar * HLD + kb];
                a[mi][1] = *(const uint32_t*)&As[(ar + 8) * HLD + kb];
                a[mi][2] = *(const uint32_t*)&As[ar * HLD + kb + 8];
                a[mi][3] = *(const uint32_t*)&As[(ar + 8) * HLD + kb + 8];
            }
            uint32_t b[4][2];
#pragma unroll
            for (int ni = 0; ni < 4; ni++) {
                int br = wn * 32 + ni * 8 + lrow;
                b[ni][0] = *(const uint32_t*)&Ws[br * HLD + kb];
                b[ni][1] = *(const uint32_t*)&Ws[br * HLD + kb + 8];
            }
#pragma unroll
            for (int mi = 0; mi < 2; mi++)
#pragma unroll
                for (int ni = 0; ni < 4; ni++)
                    mma_f16(c[mi][ni], a[mi], b[ni][0], b[ni][1]);
        }
        __syncthreads();
    }

    float* basep = part + (size_t)sp * M * Ntot;
#pragma unroll
    for (int mi = 0; mi < 2; mi++)
#pragma unroll
        for (int ni = 0; ni < 4; ni++) {
            int gr = mb * 128 + wm * 32 + mi * 16 + lrow;
            int gc = cb * 64 + wn * 32 + ni * 8 + lcol * 2;
            *(float2*)&basep[(size_t)gr * Ntot + gc] =
                make_float2(c[mi][ni][0], c[mi][ni][1]);
            *(float2*)&basep[(size_t)(gr + 8) * Ntot + gc] =
                make_float2(c[mi][ni][2], c[mi][ni][3]);
        }
}

// ---------------- fused RMS + rope -> fp16 Qh (pre-scaled), Kh --------------
__global__ __launch_bounds__(256) void rmsrope_kernel(
    const float* __restrict__ Q, const float* __restrict__ K,
    __half* __restrict__ Qh, __half* __restrict__ Kh,
    const float* __restrict__ rope,
    const float* __restrict__ gq, const float* __restrict__ gk,
    const float* __restrict__ gqt, const float* __restrict__ gkt) {
    const int row = blockIdx.x;
    const int tid = threadIdx.x;
    __shared__ float sbuf[18];

    const float* qrow = Q + (size_t)row * DIMN;
    const float* krow = K + (size_t)row * DIMN;
    __half* qh = Qh + (size_t)row * DIMN;
    __half* kh = Kh + (size_t)row * DIMN;

    float sq = 0.f, sk = 0.f;
    for (int c4 = tid; c4 < DIMN / 4; c4 += 256) {
        float4 q = *(const float4*)&qrow[c4 * 4];
        sq += q.x * q.x + q.y * q.y + q.z * q.z + q.w * q.w;
        float4 kk = *(const float4*)&krow[c4 * 4];
        sk += kk.x * kk.x + kk.y * kk.y + kk.z * kk.z + kk.w * kk.w;
    }
#pragma unroll
    for (int o = 16; o > 0; o >>= 1) {
        sq += __shfl_xor_sync(0xffffffffu, sq, o);
        sk += __shfl_xor_sync(0xffffffffu, sk, o);
    }
    int w = tid >> 5;
    if ((tid & 31) == 0) { sbuf[w] = sq; sbuf[8 + w] = sk; }
    __syncthreads();
    if (tid == 0) {
        float a = 0.f, b = 0.f;
        for (int i = 0; i < 8; i++) { a += sbuf[i]; b += sbuf[8 + i]; }
        sbuf[16] = a; sbuf[17] = b;
    }
    __syncthreads();
    const float scale = 0.08838834764831844f;  // 1/sqrt(128), folded into Qh
    const float invq = rsqrtf(sbuf[16] / (float)DIMN + EPSV);
    const float invk = rsqrtf(sbuf[17] / (float)DIMN + EPSV);
    const float* gQ = (row < IMG_SEQ) ? gq : gqt;
    const float* gK = (row < IMG_SEQ) ? gk : gkt;
    const float* rp = rope + (size_t)row * 256;

    for (int pi = tid; pi < DIMN / 2; pi += 256) {
        int c0 = pi * 2;
        int j = pi & 63;
        float4 r = *(const float4*)&rp[j * 4];
        float x0 = qrow[c0] * invq * gQ[c0];
        float x1 = qrow[c0 + 1] * invq * gQ[c0 + 1];
        *(uint32_t*)&qh[c0] = pack_h2(scale * (r.x * x0 + r.y * x1),
                                      scale * (r.z * x0 + r.w * x1));
        float y0 = krow[c0] * invk * gK[c0];
        float y1 = krow[c0 + 1] * invk * gK[c0 + 1];
        *(uint32_t*)&kh[c0] = pack_h2(r.x * y0 + r.y * y1,
                                      r.z * y0 + r.w * y1);
    }
}

// ---------------- V transpose+convert: V[j][h*128+d] -> Vth[h][d][j] --------
__global__ __launch_bounds__(256) void vtrans_kernel(const float* __restrict__ V,
                                                     __half* __restrict__ Vth) {
    __shared__ float ts[64][65];
    const int jb = blockIdx.x * 64;
    const int db = blockIdx.y * 64;
    const int tid = threadIdx.x;
#pragma unroll
    for (int f = 0; f < 16; f++) {
        int idx = tid + f * 256;
        int j = idx >> 6, d = idx & 63;
        ts[j][d] = V[(size_t)(jb + j) * DIMN + db + d];
    }
    __syncthreads();
    const int head = db >> 7;
    const int dh = db & 127;
#pragma unroll
    for (int f = 0; f < 16; f++) {
        int idx = tid + f * 256;
        int d = idx >> 6, j = idx & 63;
        Vth[(size_t)head * 128 * SEQN + (size_t)(dh + d) * SEQN + jb + j] =
            __float2half_rn(ts[j][d]);
    }
}

// ---------------- flash attention: fp16 mma + cp.async double buffering -----
// Br=128 (8 warps x 16 rows), Bc=64.
#define KLD 136                      // halves per Ks row
#define VLD 72                       // halves per Vt row (d-major)
#define PLD 72                       // halves per Ps row
#define KS_STG 17408                 // 64*136*2
#define VT_STG 18432                 // 128*72*2
#define FB_KS0 0
#define FB_KS1 17408
#define FB_VT0 34816
#define FB_VT1 53248
#define FB_PS  71680
#define FB_BYTES 90112

__global__ __launch_bounds__(256) void flash_mma(const __half* __restrict__ Qh,
                                                 const __half* __restrict__ Kh,
                                                 const __half* __restrict__ Vth,
                                                 float* __restrict__ O) {
    extern __shared__ char smc[];
    const uint32_t sbase = (uint32_t)__cvta_generic_to_shared(smc);
    __half* Ps = (__half*)(smc + FB_PS);

    const int tid = threadIdx.x;
    const int lane = tid & 31;
    const int warp = tid >> 5;
    const int lrow = lane >> 2;
    const int lcol = lane & 3;
    const int qrow0 = blockIdx.x * 128;
    const int head = blockIdx.y;
    const size_t hoff = (size_t)head * HD;
    const __half* Vh = Vth + (size_t)head * 128 * SEQN;

    // Q fragments (already scaled+roped fp16 in Qh)
    uint32_t qa[8][4];
    {
        const __half* qb = Qh + (size_t)(qrow0 + warp * 16) * DIMN + hoff;
#pragma unroll
        for (int ks = 0; ks < 8; ks++) {
            int kb = ks * 16 + 2 * lcol;
            qa[ks][0] = *(const uint32_t*)&qb[(size_t)lrow * DIMN + kb];
            qa[ks][1] = *(const uint32_t*)&qb[(size_t)(lrow + 8) * DIMN + kb];
            qa[ks][2] = *(const uint32_t*)&qb[(size_t)lrow * DIMN + kb + 8];
            qa[ks][3] = *(const uint32_t*)&qb[(size_t)(lrow + 8) * DIMN + kb + 8];
        }
    }

    float o[16][4];
#pragma unroll
    for (int ni = 0; ni < 16; ni++)
#pragma unroll
        for (int r = 0; r < 4; r++) o[ni][r] = 0.f;
    float m0 = -INFINITY, m1 = -INFINITY, l0 = 0.f, l1 = 0.f;

    const int kt0 = (qrow0 >= SBSN) ? (SBSN / 64) : 0;
    const int ktN = SEQN / 64;

    // tile issue: K tile 64x128 halves, V tile 128x64 halves (d-major)
    auto issue_tile = [&](int kt, int stg) {
        const int kr0 = kt * 64;
        const __half* ksrc = Kh + (size_t)kr0 * DIMN + hoff;
        const uint32_t kdst = sbase + (stg ? FB_KS1 : FB_KS0);
#pragma unroll
        for (int f = 0; f < 4; f++) {
            int id = tid + f * 256;          // 0..1023
            int r = id >> 4;                 // 0..63
            int c = id & 15;                 // 16B chunk
            cp_async16(kdst + (uint32_t)(r * KLD + c * 8) * 2,
                       ksrc + (size_t)r * DIMN + c * 8);
        }
        const __half* vsrc = Vh + kr0;
        const uint32_t vdst = sbase + (stg ? FB_VT1 : FB_VT0);
#pragma unroll
        for (int f = 0; f < 4; f++) {
            int id = tid + f * 256;          // 0..1023
            int d = id >> 3;                 // 0..127
            int c = id & 7;
            cp_async16(vdst + (uint32_t)(d * VLD + c * 8) * 2,
                       vsrc + (size_t)d * SEQN + c * 8);
        }
        cp_commit();
    };

    issue_tile(kt0, kt0 & 1);

    for (int kt = kt0; kt < ktN; kt++) {
        const int stg = kt & 1;
        if (kt + 1 < ktN) {
            issue_tile(kt + 1, stg ^ 1);
            cp_wait<1>();
        } else {
            cp_wait<0>();
        }
        __syncthreads();
        __half* Ks = (__half*)(smc + (stg ? FB_KS1 : FB_KS0));
        __half* Vt = (__half*)(smc + (stg ? FB_VT1 : FB_VT0));

        // S = Q @ K^T
        float s[8][4];
#pragma unroll
        for (int ni = 0; ni < 8; ni++)
#pragma unroll
            for (int r = 0; r < 4; r++) s[ni][r] = 0.f;
#pragma unroll
        for (int ks = 0; ks < 8; ks++) {
            const int kb = ks * 16 + 2 * lcol;
#pragma unroll
            for (int ni = 0; ni < 8; ni++) {
                int br = ni * 8 + lrow;
                uint32_t b0 = *(const uint32_t*)&Ks[br * KLD + kb];
                uint32_t b1 = *(const uint32_t*)&Ks[br * KLD + kb + 8];
                mma_f16(s[ni], qa[ks], b0, b1);
            }
        }

        // online softmax (warp-local)
        float mt0 = -INFINITY, mt1 = -INFINITY;
#pragma unroll
        for (int ni = 0; ni < 8; ni++) {
            mt0 = fmaxf(mt0, fmaxf(s[ni][0], s[ni][1]));
            mt1 = fmaxf(mt1, fmaxf(s[ni][2], s[ni][3]));
        }
#pragma unroll
        for (int off = 1; off <= 2; off <<= 1) {
            mt0 = fmaxf(mt0, __shfl_xor_sync(0xffffffffu, mt0, off));
            mt1 = fmaxf(mt1, __shfl_xor_sync(0xffffffffu, mt1, off));
        }
        float mn0 = fmaxf(m0, mt0), mn1 = fmaxf(m1, mt1);
        float corr0 = __expf(m0 - mn0), corr1 = __expf(m1 - mn1);
        m0 = mn0; m1 = mn1;

        float ps0 = 0.f, ps1 = 0.f;
#pragma unroll
        for (int ni = 0; ni < 8; ni++) {
            __half2 h01 = __floats2half2_rn(__expf(s[ni][0] - mn0),
                                            __expf(s[ni][1] - mn0));
            __half2 h23 = __floats2half2_rn(__expf(s[ni][2] - mn1),
                                            __expf(s[ni][3] - mn1));
            ps0 += __low2float(h01) + __high2float(h01);
            ps1 += __low2float(h23) + __high2float(h23);
            int col = ni * 8 + 2 * lcol;
            *(uint32_t*)&Ps[(warp * 16 + lrow) * PLD + col] = *(uint32_t*)&h01;
            *(uint32_t*)&Ps[(warp * 16 + lrow + 8) * PLD + col] = *(uint32_t*)&h23;
        }
#pragma unroll
        for (int off = 1; off <= 2; off <<= 1) {
            ps0 += __shfl_xor_sync(0xffffffffu, ps0, off);
            ps1 += __shfl_xor_sync(0xffffffffu, ps1, off);
        }
        l0 = l0 * corr0 + ps0;
        l1 = l1 * corr1 + ps1;
#pragma unroll
        for (int ni = 0; ni < 16; ni++) {
            o[ni][0] *= corr0; o[ni][1] *= corr0;
            o[ni][2] *= corr1; o[ni][3] *= corr1;
        }
        __syncwarp();

        // O += P @ V
#pragma unroll
        for (int ks = 0; ks < 4; ks++) {
            const int kb = ks * 16 + 2 * lcol;
            uint32_t a[4];
            a[0] = *(const uint32_t*)&Ps[(warp * 16 + lrow) * PLD + kb];
            a[1] = *(const uint32_t*)&Ps[(warp * 16 + lrow + 8) * PLD + kb];
            a[2] = *(const uint32_t*)&Ps[(warp * 16 + lrow) * PLD + kb + 8];
            a[3] = *(const uint32_t*)&Ps[(warp * 16 + lrow + 8) * PLD + kb + 8];
#pragma unroll
            for (int ni = 0; ni < 16; ni++) {
                int br = ni * 8 + lrow;
                uint32_t b0 = *(const uint32_t*)&Vt[br * VLD + kb];
                uint32_t b1 = *(const uint32_t*)&Vt[br * VLD + kb + 8];
                mma_f16(o[ni], a, b0, b1);
            }
        }
        __syncthreads();   // protect buffers before next iteration's cp.async
    }

    const float inv0 = 1.f / l0, inv1 = 1.f / l1;
    const int gr0 = qrow0 + warp * 16 + lrow;
#pragma unroll
    for (int ni = 0; ni < 16; ni++) {
        int gc = ni * 8 + lcol * 2;
        *(float2*)&O[(size_t)gr0 * DIMN + hoff + gc] =
            make_float2(o[ni][0] * inv0, o[ni][1] * inv0);
        *(float2*)&O[(size_t)(gr0 + 8) * DIMN + hoff + gc] =
            make_float2(o[ni][2] * inv1, o[ni][3] * inv1);
    }
}

// ---------------- launch ----------------
extern "C" void kernel_launch(void* const* d_in, const int* in_sizes, int n_in,
                              void* d_out, int out_size) {
    const float* img  = (const float*)d_in[0];
    const float* txt  = (const float*)d_in[1];
    const float* rope = (const float*)d_in[2];
    const float* wq   = (const float*)d_in[3];
    const float* wk   = (const float*)d_in[4];
    const float* wv   = (const float*)d_in[5];
    const float* wo   = (const float*)d_in[6];
    const float* wq_t = (const float*)d_in[7];
    const float* wk_t = (const float*)d_in[8];
    const float* wv_t = (const float*)d_in[9];
    const float* wo_t = (const float*)d_in[10];
    const float* gq   = (const float*)d_in[11];
    const float* gk   = (const float*)d_in[12];
    const float* gqt  = (const float*)d_in[13];
    const float* gkt  = (const float*)d_in[14];
    const float* q_down = (const float*)d_in[15];
    const float* q_up   = (const float*)d_in[16];
    const float* k_down = (const float*)d_in[17];
    const float* k_up   = (const float*)d_in[18];
    const float* v_down = (const float*)d_in[19];
    const float* v_up   = (const float*)d_in[20];
    const float* p_down = (const float*)d_in[21];
    const float* p_up   = (const float*)d_in[22];
    float* out = (float*)d_out;

    float *Q, *K, *V, *O, *part;
    __half *Qh, *Kh, *Vth;
    cudaGetSymbolAddress((void**)&Q,    g_Q);
    cudaGetSymbolAddress((void**)&K,    g_K);
    cudaGetSymbolAddress((void**)&V,    g_V);
    cudaGetSymbolAddress((void**)&O,    g_O);
    cudaGetSymbolAddress((void**)&part, g_part);
    cudaGetSymbolAddress((void**)&Qh,   g_Qh);
    cudaGetSymbolAddress((void**)&Kh,   g_Kh);
    cudaGetSymbolAddress((void**)&Vth,  g_Vth);

    const float* img_cond = img + (size_t)BLOCKN * DIMN;
    float* out_cond = out + (size_t)SBSN * DIMN;

    // 1) fused LoRA down-projections (q/k/v), split-K 8-way -> partials
    down_gemm_h<<<dim3(3, CONDN / 128, 8), 256>>>(img_cond, q_down, k_down, v_down,
                                                  part, CONDN, 192, DIMN);

    // 2) QKV projections in ONE launch, LoRA-up FUSED into cond-row epilogue
    proj_gemm3h<<<dim3(DIMN / 128, SEQN / 128, 3), 256>>>(
        img, txt,
        wq, wq_t, Q,
        wk, wk_t, K,
        wv, wv_t, V,
        part, q_up, k_up, v_up,
        IMG_SEQ, DIMN, DIMN, 1, 0);

    // 3) RMS + rope -> fp16 Qh (pre-scaled), Kh ; V -> transposed fp16 Vth
    rmsrope_kernel<<<SEQN, 256>>>(Q, K, Qh, Kh, rope, gq, gk, gqt, gkt);
    vtrans_kernel<<<dim3(SEQN / 64, DIMN / 64), 256>>>(V, Vth);

    // 4) flash attention (fp16 mma + cp.async double buffering)
    cudaFuncSetAttribute(flash_mma, cudaFuncAttributeMaxDynamicSharedMemorySize,
                         FB_BYTES);
    flash_mma<<<dim3(SEQN / 128, HEADS), 256, FB_BYTES>>>(Qh, Kh, Vth, O);

    // 5) output projection, written DIRECTLY in output layout [img|text|cond]
    proj_gemm3h<<<dim3(DIMN / 128, SEQN / 128, 1), 256>>>(
        O, O + (size_t)IMG_SEQ * DIMN,
        wo, wo_t, out,
        wo, wo_t, out,
        wo, wo_t, out,
        part, q_up, k_up, v_up,
        IMG_SEQ, DIMN, DIMN, 0, 1);

    // 6) post-projection LoRA on cond region of out (down -> fused-sum up)
    down_gemm_h<<<dim3(1, CONDN / 128, 8), 256>>>(out_cond,
                                                  p_down, p_down, p_down,
                                                  part, CONDN, 64, DIMN);
    up_sum_gemm_acc_h<<<dim3(DIMN / 128, CONDN / 128), 256>>>(part, p_up,
                                                              out_cond, DIMN);
}

// round 10
// speedup vs baseline: 8.8512x; 1.0566x over previous
#include <cuda_runtime.h>
#include <cuda_fp16.h>
#include <math.h>
#include <stdint.h>

// ---------------- problem constants ----------------
#define DIMN 2048
#define HEADS 16
#define HD 128
#define RANKN 64
#define IMG_SEQ 2048
#define TXT_SEQ 128
#define SEQN 2176          // IMG_SEQ + TXT_SEQ
#define CONDN 1024
#define BLOCKN 1024        // IMG_SEQ - COND
#define SBSN 1152          // SEQ - COND
#define EPSV 1e-5f

// ---------------- device scratch (no allocation allowed) ----------------
__device__ float g_Q[SEQN * DIMN];
__device__ float g_K[SEQN * DIMN];
__device__ float g_V[SEQN * DIMN];
__device__ float g_O[SEQN * DIMN];
__device__ float g_part[8 * CONDN * 192];
__device__ __half g_Qh[SEQN * DIMN];
__device__ __half g_Kh[SEQN * DIMN];
__device__ __half g_Vth[DIMN * SEQN];   // per head: [d=128][seq] fp16

// ---------------- helpers ----------------
__device__ __forceinline__ uint32_t pack_h2(float x, float y) {
    __half2 h = __floats2half2_rn(x, y);
    return *(uint32_t*)&h;
}

__device__ __forceinline__ void mma_f16(float c[4], const uint32_t a[4],
                                        uint32_t b0, uint32_t b1) {
    asm volatile(
        "mma.sync.aligned.m16n8k16.row.col.f32.f16.f16.f32 "
        "{%0,%1,%2,%3}, {%4,%5,%6,%7}, {%8,%9}, {%0,%1,%2,%3};"
        : "+f"(c[0]), "+f"(c[1]), "+f"(c[2]), "+f"(c[3])
        : "r"(a[0]), "r"(a[1]), "r"(a[2]), "r"(a[3]),
          "r"(b0), "r"(b1));
}

__device__ __forceinline__ void ldsm4(uint32_t& r0, uint32_t& r1,
                                      uint32_t& r2, uint32_t& r3, uint32_t addr) {
    asm volatile("ldmatrix.sync.aligned.m8n8.x4.shared.b16 {%0,%1,%2,%3}, [%4];"
                 : "=r"(r0), "=r"(r1), "=r"(r2), "=r"(r3) : "r"(addr));
}

__device__ __forceinline__ void cp_async16(uint32_t dst_smem, const void* src) {
    asm volatile("cp.async.cg.shared.global [%0], [%1], 16;"
                 :: "r"(dst_smem), "l"(src));
}
__device__ __forceinline__ void cp_commit() {
    asm volatile("cp.async.commit_group;" ::: "memory");
}
template <int N>
__device__ __forceinline__ void cp_wait() {
    asm volatile("cp.async.wait_group %0;" :: "n"(N) : "memory");
}

#define HLD 40   // halves per smem row (20 words -> conflict-free ldmatrix)

// ===== fp16 projection GEMM + fused LoRA-up =================================
// C[remap(r)] = A_sel(r) @ W_sel(r,z)^T  (+ LoRA-up for cond rows if lora!=0)
__global__ __launch_bounds__(256, 2) void proj_gemm3h(
    const float* __restrict__ A1, const float* __restrict__ A2,
    const float* __restrict__ Wa0, const float* __restrict__ Wb0, float* __restrict__ C0,
    const float* __restrict__ Wa1, const float* __restrict__ Wb1, float* __restrict__ C1,
    const float* __restrict__ Wa2, const float* __restrict__ Wb2, float* __restrict__ C2,
    const float* __restrict__ part,
    const float* __restrict__ up0, const float* __restrict__ up1,
    const float* __restrict__ up2,
    int Msplit, int N, int K, int lora, int remap) {
    __shared__ __half As[128 * HLD];
    __shared__ __half Bs[128 * HLD];

    const int tid = threadIdx.x;
    const int lane = tid & 31;
    const int warp = tid >> 5;
    const int wm = warp & 3;
    const int wn = warp >> 2;
    const int lrow = lane >> 2;
    const int lcol = lane & 3;
    const int row0 = blockIdx.y * 128;
    const int col0 = blockIdx.x * 128;
    const int z = blockIdx.z;

    const float* A = (row0 < Msplit) ? A1 + (size_t)row0 * K
                                     : A2 + (size_t)(row0 - Msplit) * K;
    const float* W;
    float* C;
    const float* up;
    if (z == 0)      { W = (row0 < Msplit) ? Wa0 : Wb0; C = C0; up = up0; }
    else if (z == 1) { W = (row0 < Msplit) ? Wa1 : Wb1; C = C1; up = up1; }
    else             { W = (row0 < Msplit) ? Wa2 : Wb2; C = C2; up = up2; }

    int row_out0 = row0;
    if (remap) {
        if (row0 >= IMG_SEQ)      row_out0 = row0 - CONDN;
        else if (row0 >= BLOCKN)  row_out0 = row0 + TXT_SEQ;
    }

    float c[2][8][4];
#pragma unroll
    for (int i = 0; i < 2; i++)
#pragma unroll
        for (int j = 0; j < 8; j++)
#pragma unroll
            for (int r = 0; r < 4; r++) c[i][j][r] = 0.f;

    // ldmatrix lane-address invariants (byte offsets)
    const uint32_t a_base = (uint32_t)__cvta_generic_to_shared(As);
    const uint32_t b_base = (uint32_t)__cvta_generic_to_shared(Bs);
    const int al_row = wm * 32 + (lane & 15);
    const int al_k   = 8 * (lane >> 4);
    const int bl_tile = lane >> 4;         // 0/1: which ntile of the pair
    const int bl_row  = lane & 7;
    const int bl_k    = 8 * ((lane >> 3) & 1);

    auto compute_block = [&]() {
#pragma unroll
        for (int ks = 0; ks < 2; ks++) {
            const int kb = ks * 16;
            uint32_t a[2][4];
#pragma unroll
            for (int mi = 0; mi < 2; mi++) {
                uint32_t addr = a_base +
                    (uint32_t)(((al_row + mi * 16) * HLD) + kb + al_k) * 2;
                ldsm4(a[mi][0], a[mi][1], a[mi][2], a[mi][3], addr);
            }
            uint32_t b[8][2];
#pragma unroll
            for (int j = 0; j < 4; j++) {
                int brow = wn * 64 + (2 * j + bl_tile) * 8 + bl_row;
                uint32_t addr = b_base + (uint32_t)(brow * HLD + kb + bl_k) * 2;
                ldsm4(b[2 * j][0], b[2 * j][1], b[2 * j + 1][0], b[2 * j + 1][1], addr);
            }
#pragma unroll
            for (int mi = 0; mi < 2; mi++)
#pragma unroll
                for (int ni = 0; ni < 8; ni++)
                    mma_f16(c[mi][ni], a[mi], b[ni][0], b[ni][1]);
        }
    };

    for (int k0 = 0; k0 < K; k0 += 32) {
#pragma unroll
        for (int f = 0; f < 4; f++) {
            int id = tid + f * 256;
            int r = id >> 3;
            int kq = (id & 7) << 2;
            float4 va = *(const float4*)&A[(size_t)r * K + k0 + kq];
            *(uint2*)&As[r * HLD + kq] =
                make_uint2(pack_h2(va.x, va.y), pack_h2(va.z, va.w));
            float4 vb = *(const float4*)&W[(size_t)(col0 + r) * K + k0 + kq];
            *(uint2*)&Bs[r * HLD + kq] =
                make_uint2(pack_h2(vb.x, vb.y), pack_h2(vb.z, vb.w));
        }
        __syncthreads();
        compute_block();
        __syncthreads();
    }

    // ---- fused LoRA-up: 2 extra BK=32 iterations (K=64) for cond rows ----
    if (lora && row0 >= BLOCKN && row0 < IMG_SEQ) {
        const int arow0 = row0 - BLOCKN;
#pragma unroll
        for (int e = 0; e < 2; e++) {
            const int k0 = e * 32;
#pragma unroll
            for (int f = 0; f < 4; f++) {
                int id = tid + f * 256;
                int r = id >> 3;
                int kq = (id & 7) << 2;
                const float* pa = part + (size_t)(arow0 + r) * 192 + z * 64 + k0 + kq;
                float4 va = *(const float4*)pa;
#pragma unroll
                for (int s = 1; s < 8; s++) {
                    float4 t = *(const float4*)(pa + (size_t)s * CONDN * 192);
                    va.x += t.x; va.y += t.y; va.z += t.z; va.w += t.w;
                }
                *(uint2*)&As[r * HLD + kq] =
                    make_uint2(pack_h2(va.x, va.y), pack_h2(va.z, va.w));
                float4 vb = *(const float4*)&up[(size_t)(col0 + r) * 64 + k0 + kq];
                *(uint2*)&Bs[r * HLD + kq] =
                    make_uint2(pack_h2(vb.x, vb.y), pack_h2(vb.z, vb.w));
            }
            __syncthreads();
            compute_block();
            __syncthreads();
        }
    }

#pragma unroll
    for (int mi = 0; mi < 2; mi++)
#pragma unroll
        for (int ni = 0; ni < 8; ni++) {
            int gr = row_out0 + wm * 32 + mi * 16 + lrow;
            int gc = col0 + wn * 64 + ni * 8 + lcol * 2;
            *(float2*)&C[(size_t)gr * N + gc] =
                make_float2(c[mi][ni][0], c[mi][ni][1]);
            *(float2*)&C[(size_t)(gr + 8) * N + gc] =
                make_float2(c[mi][ni][2], c[mi][ni][3]);
        }
}

// ===== fp16 LoRA up-projection with inline 8-way partial sum ================
__global__ __launch_bounds__(256) void up_sum_gemm_acc_h(
    const float* __restrict__ part,
    const float* __restrict__ W,
    float* __restrict__ C, int N) {
    __shared__ __half As[128 * HLD];
    __shared__ __half Bs[128 * HLD];

    const int tid = threadIdx.x;
    const int lane = tid & 31;
    const int warp = tid >> 5;
    const int wm = warp & 3;
    const int wn = warp >> 2;
    const int lrow = lane >> 2;
    const int lcol = lane & 3;
    const int row0 = blockIdx.y * 128;
    const int col0 = blockIdx.x * 128;

    float c[2][8][4];
#pragma unroll
    for (int i = 0; i < 2; i++)
#pragma unroll
        for (int j = 0; j < 8; j++)
#pragma unroll
            for (int r = 0; r < 4; r++) c[i][j][r] = 0.f;

    for (int k0 = 0; k0 < 64; k0 += 32) {
#pragma unroll
        for (int f = 0; f < 4; f++) {
            int id = tid + f * 256;
            int r = id >> 3;
            int kq = (id & 7) << 2;
            const float* pa = part + (size_t)(row0 + r) * 64 + k0 + kq;
            float4 va = *(const float4*)pa;
#pragma unroll
            for (int s = 1; s < 8; s++) {
                float4 t = *(const float4*)(pa + (size_t)s * CONDN * 64);
                va.x += t.x; va.y += t.y; va.z += t.z; va.w += t.w;
            }
            *(uint2*)&As[r * HLD + kq] =
                make_uint2(pack_h2(va.x, va.y), pack_h2(va.z, va.w));
            float4 vb = *(const float4*)&W[(size_t)(col0 + r) * 64 + k0 + kq];
            *(uint2*)&Bs[r * HLD + kq] =
                make_uint2(pack_h2(vb.x, vb.y), pack_h2(vb.z, vb.w));
        }
        __syncthreads();

#pragma unroll
        for (int ks = 0; ks < 2; ks++) {
            const int kb = ks * 16 + 2 * lcol;
            uint32_t a[2][4];
#pragma unroll
            for (int mi = 0; mi < 2; mi++) {
                int ar = wm * 32 + mi * 16 + lrow;
                a[mi][0] = *(const uint32_t*)&As[ar * HLD + kb];
                a[mi][1] = *(const uint32_t*)&As[(ar + 8) * HLD + kb];
                a[mi][2] = *(const uint32_t*)&As[ar * HLD + kb + 8];
                a[mi][3] = *(const uint32_t*)&As[(ar + 8) * HLD + kb + 8];
            }
            uint32_t b[8][2];
#pragma unroll
            for (int ni = 0; ni < 8; ni++) {
                int br = wn * 64 + ni * 8 + lrow;
                b[ni][0] = *(const uint32_t*)&Bs[br * HLD + kb];
                b[ni][1] = *(const uint32_t*)&Bs[br * HLD + kb + 8];
            }
#pragma unroll
            for (int mi = 0; mi < 2; mi++)
#pragma unroll
                for (int ni = 0; ni < 8; ni++)
                    mma_f16(c[mi][ni], a[mi], b[ni][0], b[ni][1]);
        }
        __syncthreads();
    }

#pragma unroll
    for (int mi = 0; mi < 2; mi++)
#pragma unroll
        for (int ni = 0; ni < 8; ni++) {
            int gr = row0 + wm * 32 + mi * 16 + lrow;
            int gc = col0 + wn * 64 + ni * 8 + lcol * 2;
            float2* p0 = (float2*)&C[(size_t)gr * N + gc];
            float2* p1 = (float2*)&C[(size_t)(gr + 8) * N + gc];
            float2 o0 = *p0, o1 = *p1;
            o0.x += c[mi][ni][0]; o0.y += c[mi][ni][1];
            o1.x += c[mi][ni][2]; o1.y += c[mi][ni][3];
            *p0 = o0; *p1 = o1;
        }
}

// ===== fp16 split-K LoRA down-projection (up to 3 fused weights) =============
__global__ __launch_bounds__(256) void down_gemm_h(const float* __restrict__ A,
                                                   const float* __restrict__ w0,
                                                   const float* __restrict__ w1,
                                                   const float* __restrict__ w2,
                                                   float* __restrict__ part,
                                                   int M, int Ntot, int Kfull) {
    __shared__ __half As[128 * HLD];
    __shared__ __half Ws[64 * HLD];

    const int cb = blockIdx.x, mb = blockIdx.y, sp = blockIdx.z;
    const int Kc = Kfull >> 3;
    const int kbase = sp * Kc;
    const float* W = (cb == 0) ? w0 : (cb == 1 ? w1 : w2);

    const int tid = threadIdx.x;
    const int lane = tid & 31;
    const int warp = tid >> 5;
    const int wm = warp & 3;
    const int wn = warp >> 2;
    const int lrow = lane >> 2;
    const int lcol = lane & 3;

    float c[2][4][4];
#pragma unroll
    for (int i = 0; i < 2; i++)
#pragma unroll
        for (int j = 0; j < 4; j++)
#pragma unroll
            for (int r = 0; r < 4; r++) c[i][j][r] = 0.f;

    for (int k0 = 0; k0 < Kc; k0 += 32) {
#pragma unroll
        for (int f = 0; f < 4; f++) {
            int id = tid + f * 256;
            int r = id >> 3;
            int kq = (id & 7) << 2;
            float4 va = *(const float4*)&A[(size_t)(mb * 128 + r) * Kfull + kbase + k0 + kq];
            *(uint2*)&As[r * HLD + kq] =
                make_uint2(pack_h2(va.x, va.y), pack_h2(va.z, va.w));
        }
#pragma unroll
        for (int f = 0; f < 2; f++) {
            int id = tid + f * 256;
            int r = id >> 3;
            int kq = (id & 7) << 2;
            float4 vb = *(const float4*)&W[(size_t)r * Kfull + kbase + k0 + kq];
            *(uint2*)&Ws[r * HLD + kq] =
                make_uint2(pack_h2(vb.x, vb.y), pack_h2(vb.z, vb.w));
        }
        __syncthreads();

#pragma unroll
        for (int ks = 0; ks < 2; ks++) {
            const int kb = ks * 16 + 2 * lcol;
            uint32_t a[2][4];
#pragma unroll
            for (int mi = 0; mi < 2; mi++) {
                int ar = wm * 32 + mi * 16 + lrow;
                a[mi][0] = *(const uint32_t*)&As[ar * HLD + kb];
                a[mi][1] = *(const uint32_t*)&As[(ar + 8) * HLD + kb];
                a[mi][2] = *(const uint32_t*)&As[ar * HLD + kb + 8];
                a[mi][3] = *(const uint32_t*)&As[(ar + 8) * HLD + kb + 8];
            }
            uint32_t b[4][2];
#pragma unroll
            for (int ni = 0; ni < 4; ni++) {
                int br = wn * 32 + ni * 8 + lrow;
                b[ni][0] = *(const uint32_t*)&Ws[br * HLD + kb];
                b[ni][1] = *(const uint32_t*)&Ws[br * HLD + kb + 8];
            }
#pragma unroll
            for (int mi = 0; mi < 2; mi++)
#pragma unroll
                for (int ni = 0; ni < 4; ni++)
                    mma_f16(c[mi][ni], a[mi], b[ni][0], b[ni][1]);
        }
        __syncthreads();
    }

    float* basep = part + (size_t)sp * M * Ntot;
#pragma unroll
    for (int mi = 0; mi < 2; mi++)
#pragma unroll
        for (int ni = 0; ni < 4; ni++) {
            int gr = mb * 128 + wm * 32 + mi * 16 + lrow;
            int gc = cb * 64 + wn * 32 + ni * 8 + lcol * 2;
            *(float2*)&basep[(size_t)gr * Ntot + gc] =
                make_float2(c[mi][ni][0], c[mi][ni][1]);
            *(float2*)&basep[(size_t)(gr + 8) * Ntot + gc] =
                make_float2(c[mi][ni][2], c[mi][ni][3]);
        }
}

// ---------------- fused RMS + rope -> fp16 Qh (pre-scaled), Kh --------------
__global__ __launch_bounds__(256) void rmsrope_kernel(
    const float* __restrict__ Q, const float* __restrict__ K,
    __half* __restrict__ Qh, __half* __restrict__ Kh,
    const float* __restrict__ rope,
    const float* __restrict__ gq, const float* __restrict__ gk,
    const float* __restrict__ gqt, const float* __restrict__ gkt) {
    const int row = blockIdx.x;
    const int tid = threadIdx.x;
    __shared__ float sbuf[18];

    const float* qrow = Q + (size_t)row * DIMN;
    const float* krow = K + (size_t)row * DIMN;
    __half* qh = Qh + (size_t)row * DIMN;
    __half* kh = Kh + (size_t)row * DIMN;

    float sq = 0.f, sk = 0.f;
    for (int c4 = tid; c4 < DIMN / 4; c4 += 256) {
        float4 q = *(const float4*)&qrow[c4 * 4];
        sq += q.x * q.x + q.y * q.y + q.z * q.z + q.w * q.w;
        float4 kk = *(const float4*)&krow[c4 * 4];
        sk += kk.x * kk.x + kk.y * kk.y + kk.z * kk.z + kk.w * kk.w;
    }
#pragma unroll
    for (int o = 16; o > 0; o >>= 1) {
        sq += __shfl_xor_sync(0xffffffffu, sq, o);
        sk += __shfl_xor_sync(0xffffffffu, sk, o);
    }
    int w = tid >> 5;
    if ((tid & 31) == 0) { sbuf[w] = sq; sbuf[8 + w] = sk; }
    __syncthreads();
    if (tid == 0) {
        float a = 0.f, b = 0.f;
        for (int i = 0; i < 8; i++) { a += sbuf[i]; b += sbuf[8 + i]; }
        sbuf[16] = a; sbuf[17] = b;
    }
    __syncthreads();
    const float scale = 0.08838834764831844f;
    const float invq = rsqrtf(sbuf[16] / (float)DIMN + EPSV);
    const float invk = rsqrtf(sbuf[17] / (float)DIMN + EPSV);
    const float* gQ = (row < IMG_SEQ) ? gq : gqt;
    const float* gK = (row < IMG_SEQ) ? gk : gkt;
    const float* rp = rope + (size_t)row * 256;

    for (int pi = tid; pi < DIMN / 2; pi += 256) {
        int c0 = pi * 2;
        int j = pi & 63;
        float4 r = *(const float4*)&rp[j * 4];
        float x0 = qrow[c0] * invq * gQ[c0];
        float x1 = qrow[c0 + 1] * invq * gQ[c0 + 1];
        *(uint32_t*)&qh[c0] = pack_h2(scale * (r.x * x0 + r.y * x1),
                                      scale * (r.z * x0 + r.w * x1));
        float y0 = krow[c0] * invk * gK[c0];
        float y1 = krow[c0 + 1] * invk * gK[c0 + 1];
        *(uint32_t*)&kh[c0] = pack_h2(r.x * y0 + r.y * y1,
                                      r.z * y0 + r.w * y1);
    }
}

// ---------------- V transpose+convert: V[j][h*128+d] -> Vth[h][d][j] --------
__global__ __launch_bounds__(256) void vtrans_kernel(const float* __restrict__ V,
                                                     __half* __restrict__ Vth) {
    __shared__ float ts[64][65];
    const int jb = blockIdx.x * 64;
    const int db = blockIdx.y * 64;
    const int tid = threadIdx.x;
#pragma unroll
    for (int f = 0; f < 16; f++) {
        int idx = tid + f * 256;
        int j = idx >> 6, d = idx & 63;
        ts[j][d] = V[(size_t)(jb + j) * DIMN + db + d];
    }
    __syncthreads();
    const int head = db >> 7;
    const int dh = db & 127;
#pragma unroll
    for (int f = 0; f < 16; f++) {
        int idx = tid + f * 256;
        int d = idx >> 6, j = idx & 63;
        Vth[(size_t)head * 128 * SEQN + (size_t)(dh + d) * SEQN + jb + j] =
            __float2half_rn(ts[j][d]);
    }
}

// ---------------- flash attention: fp16 mma + cp.async + ldmatrix -----------
// Br=128 (8 warps x 16 rows), Bc=64.
#define KLD 136
#define VLD 72
#define PLD 72
#define FB_KS0 0
#define FB_KS1 17408
#define FB_VT0 34816
#define FB_VT1 53248
#define FB_PS  71680
#define FB_BYTES 90112

__global__ __launch_bounds__(256) void flash_mma(const __half* __restrict__ Qh,
                                                 const __half* __restrict__ Kh,
                                                 const __half* __restrict__ Vth,
                                                 float* __restrict__ O) {
    extern __shared__ char smc[];
    const uint32_t sbase = (uint32_t)__cvta_generic_to_shared(smc);
    __half* Ps = (__half*)(smc + FB_PS);
    const uint32_t ps_base = sbase + FB_PS;

    const int tid = threadIdx.x;
    const int lane = tid & 31;
    const int warp = tid >> 5;
    const int lrow = lane >> 2;
    const int lcol = lane & 3;
    const int qrow0 = blockIdx.x * 128;
    const int head = blockIdx.y;
    const size_t hoff = (size_t)head * HD;
    const __half* Vh = Vth + (size_t)head * 128 * SEQN;

    // ldmatrix lane invariants
    const int bl_tile = lane >> 4;
    const int bl_row  = lane & 7;
    const int bl_k    = 8 * ((lane >> 3) & 1);
    const int al_row  = lane & 15;
    const int al_k    = 8 * (lane >> 4);

    // Q fragments (already scaled+roped fp16 in Qh)
    uint32_t qa[8][4];
    {
        const __half* qb = Qh + (size_t)(qrow0 + warp * 16) * DIMN + hoff;
#pragma unroll
        for (int ks = 0; ks < 8; ks++) {
            int kb = ks * 16 + 2 * lcol;
            qa[ks][0] = *(const uint32_t*)&qb[(size_t)lrow * DIMN + kb];
            qa[ks][1] = *(const uint32_t*)&qb[(size_t)(lrow + 8) * DIMN + kb];
            qa[ks][2] = *(const uint32_t*)&qb[(size_t)lrow * DIMN + kb + 8];
            qa[ks][3] = *(const uint32_t*)&qb[(size_t)(lrow + 8) * DIMN + kb + 8];
        }
    }

    float o[16][4];
#pragma unroll
    for (int ni = 0; ni < 16; ni++)
#pragma unroll
        for (int r = 0; r < 4; r++) o[ni][r] = 0.f;
    float m0 = -INFINITY, m1 = -INFINITY, l0 = 0.f, l1 = 0.f;

    const int kt0 = (qrow0 >= SBSN) ? (SBSN / 64) : 0;
    const int ktN = SEQN / 64;

    auto issue_tile = [&](int kt, int stg) {
        const int kr0 = kt * 64;
        const __half* ksrc = Kh + (size_t)kr0 * DIMN + hoff;
        const uint32_t kdst = sbase + (stg ? FB_KS1 : FB_KS0);
#pragma unroll
        for (int f = 0; f < 4; f++) {
            int id = tid + f * 256;
            int r = id >> 4;
            int cc = id & 15;
            cp_async16(kdst + (uint32_t)(r * KLD + cc * 8) * 2,
                       ksrc + (size_t)r * DIMN + cc * 8);
        }
        const __half* vsrc = Vh + kr0;
        const uint32_t vdst = sbase + (stg ? FB_VT1 : FB_VT0);
#pragma unroll
        for (int f = 0; f < 4; f++) {
            int id = tid + f * 256;
            int d = id >> 3;
            int cc = id & 7;
            cp_async16(vdst + (uint32_t)(d * VLD + cc * 8) * 2,
                       vsrc + (size_t)d * SEQN + cc * 8);
        }
        cp_commit();
    };

    issue_tile(kt0, kt0 & 1);

    for (int kt = kt0; kt < ktN; kt++) {
        const int stg = kt & 1;
        if (kt + 1 < ktN) {
            issue_tile(kt + 1, stg ^ 1);
            cp_wait<1>();
        } else {
            cp_wait<0>();
        }
        __syncthreads();
        const uint32_t ks_base = sbase + (stg ? FB_KS1 : FB_KS0);
        const uint32_t vt_base = sbase + (stg ? FB_VT1 : FB_VT0);

        // S = Q @ K^T (B frags via ldmatrix.x4)
        float s[8][4];
#pragma unroll
        for (int ni = 0; ni < 8; ni++)
#pragma unroll
            for (int r = 0; r < 4; r++) s[ni][r] = 0.f;
#pragma unroll
        for (int ks = 0; ks < 8; ks++) {
            const int kb = ks * 16;
            uint32_t b[8][2];
#pragma unroll
            for (int j = 0; j < 4; j++) {
                int brow = (2 * j + bl_tile) * 8 + bl_row;
                uint32_t addr = ks_base + (uint32_t)(brow * KLD + kb + bl_k) * 2;
                ldsm4(b[2 * j][0], b[2 * j][1], b[2 * j + 1][0], b[2 * j + 1][1], addr);
            }
#pragma unroll
            for (int ni = 0; ni < 8; ni++)
                mma_f16(s[ni], qa[ks], b[ni][0], b[ni][1]);
        }

        // online softmax (warp-local)
        float mt0 = -INFINITY, mt1 = -INFINITY;
#pragma unroll
        for (int ni = 0; ni < 8; ni++) {
            mt0 = fmaxf(mt0, fmaxf(s[ni][0], s[ni][1]));
            mt1 = fmaxf(mt1, fmaxf(s[ni][2], s[ni][3]));
        }
#pragma unroll
        for (int off = 1; off <= 2; off <<= 1) {
            mt0 = fmaxf(mt0, __shfl_xor_sync(0xffffffffu, mt0, off));
            mt1 = fmaxf(mt1, __shfl_xor_sync(0xffffffffu, mt1, off));
        }
        float mn0 = fmaxf(m0, mt0), mn1 = fmaxf(m1, mt1);
        float corr0 = __expf(m0 - mn0), corr1 = __expf(m1 - mn1);
        m0 = mn0; m1 = mn1;

        float ps0 = 0.f, ps1 = 0.f;
#pragma unroll
        for (int ni = 0; ni < 8; ni++) {
            __half2 h01 = __floats2half2_rn(__expf(s[ni][0] - mn0),
                                            __expf(s[ni][1] - mn0));
            __half2 h23 = __floats2half2_rn(__expf(s[ni][2] - mn1),
                                            __expf(s[ni][3] - mn1));
            ps0 += __low2float(h01) + __high2float(h01);
            ps1 += __low2float(h23) + __high2float(h23);
            int col = ni * 8 + 2 * lcol;
            *(uint32_t*)&Ps[(warp * 16 + lrow) * PLD + col] = *(uint32_t*)&h01;
            *(uint32_t*)&Ps[(warp * 16 + lrow + 8) * PLD + col] = *(uint32_t*)&h23;
        }
#pragma unroll
        for (int off = 1; off <= 2; off <<= 1) {
            ps0 += __shfl_xor_sync(0xffffffffu, ps0, off);
            ps1 += __shfl_xor_sync(0xffffffffu, ps1, off);
        }
        l0 = l0 * corr0 + ps0;
        l1 = l1 * corr1 + ps1;
#pragma unroll
        for (int ni = 0; ni < 16; ni++) {
            o[ni][0] *= corr0; o[ni][1] *= corr0;
            o[ni][2] *= corr1; o[ni][3] *= corr1;
        }
        __syncwarp();

        // O += P @ V (A and B frags via ldmatrix.x4)
#pragma unroll
        for (int ks = 0; ks < 4; ks++) {
            const int kb = ks * 16;
            uint32_t a[4];
            {
                uint32_t addr = ps_base +
                    (uint32_t)((warp * 16 + al_row) * PLD + kb + al_k) * 2;
                ldsm4(a[0], a[1], a[2], a[3], addr);
            }
#pragma unroll
            for (int j = 0; j < 8; j++) {
                int brow = (2 * j + bl_tile) * 8 + bl_row;
                uint32_t addr = vt_base + (uint32_t)(brow * VLD + kb + bl_k) * 2;
                uint32_t b0, b1, b2, b3;
                ldsm4(b0, b1, b2, b3, addr);
                mma_f16(o[2 * j], a, b0, b1);
                mma_f16(o[2 * j + 1], a, b2, b3);
            }
        }
        __syncthreads();
    }

    const float inv0 = 1.f / l0, inv1 = 1.f / l1;
    const int gr0 = qrow0 + warp * 16 + lrow;
#pragma unroll
    for (int ni = 0; ni < 16; ni++) {
        int gc = ni * 8 + lcol * 2;
        *(float2*)&O[(size_t)gr0 * DIMN + hoff + gc] =
            make_float2(o[ni][0] * inv0, o[ni][1] * inv0);
        *(float2*)&O[(size_t)(gr0 + 8) * DIMN + hoff + gc] =
            make_float2(o[ni][2] * inv1, o[ni][3] * inv1);
    }
}

// ---------------- launch ----------------
extern "C" void kernel_launch(void* const* d_in, const int* in_sizes, int n_in,
                              void* d_out, int out_size) {
    const float* img  = (const float*)d_in[0];
    const float* txt  = (const float*)d_in[1];
    const float* rope = (const float*)d_in[2];
    const float* wq   = (const float*)d_in[3];
    const float* wk   = (const float*)d_in[4];
    const float* wv   = (const float*)d_in[5];
    const float* wo   = (const float*)d_in[6];
    const float* wq_t = (const float*)d_in[7];
    const float* wk_t = (const float*)d_in[8];
    const float* wv_t = (const float*)d_in[9];
    const float* wo_t = (const float*)d_in[10];
    const float* gq   = (const float*)d_in[11];
    const float* gk   = (const float*)d_in[12];
    const float* gqt  = (const float*)d_in[13];
    const float* gkt  = (const float*)d_in[14];
    const float* q_down = (const float*)d_in[15];
    const float* q_up   = (const float*)d_in[16];
    const float* k_down = (const float*)d_in[17];
    const float* k_up   = (const float*)d_in[18];
    const float* v_down = (const float*)d_in[19];
    const float* v_up   = (const float*)d_in[20];
    const float* p_down = (const float*)d_in[21];
    const float* p_up   = (const float*)d_in[22];
    float* out = (float*)d_out;

    float *Q, *K, *V, *O, *part;
    __half *Qh, *Kh, *Vth;
    cudaGetSymbolAddress((void**)&Q,    g_Q);
    cudaGetSymbolAddress((void**)&K,    g_K);
    cudaGetSymbolAddress((void**)&V,    g_V);
    cudaGetSymbolAddress((void**)&O,    g_O);
    cudaGetSymbolAddress((void**)&part, g_part);
    cudaGetSymbolAddress((void**)&Qh,   g_Qh);
    cudaGetSymbolAddress((void**)&Kh,   g_Kh);
    cudaGetSymbolAddress((void**)&Vth,  g_Vth);

    const float* img_cond = img + (size_t)BLOCKN * DIMN;
    float* out_cond = out + (size_t)SBSN * DIMN;

    // 1) fused LoRA down-projections (q/k/v), split-K 8-way -> partials
    down_gemm_h<<<dim3(3, CONDN / 128, 8), 256>>>(img_cond, q_down, k_down, v_down,
                                                  part, CONDN, 192, DIMN);

    // 2) QKV projections in ONE launch, LoRA-up FUSED into cond-row epilogue
    proj_gemm3h<<<dim3(DIMN / 128, SEQN / 128, 3), 256>>>(
        img, txt,
        wq, wq_t, Q,
        wk, wk_t, K,
        wv, wv_t, V,
        part, q_up, k_up, v_up,
        IMG_SEQ, DIMN, DIMN, 1, 0);

    // 3) RMS + rope -> fp16 Qh (pre-scaled), Kh ; V -> transposed fp16 Vth
    rmsrope_kernel<<<SEQN, 256>>>(Q, K, Qh, Kh, rope, gq, gk, gqt, gkt);
    vtrans_kernel<<<dim3(SEQN / 64, DIMN / 64), 256>>>(V, Vth);

    // 4) flash attention (fp16 mma + cp.async + ldmatrix)
    cudaFuncSetAttribute(flash_mma, cudaFuncAttributeMaxDynamicSharedMemorySize,
                         FB_BYTES);
    flash_mma<<<dim3(SEQN / 128, HEADS), 256, FB_BYTES>>>(Qh, Kh, Vth, O);

    // 5) output projection, written DIRECTLY in output layout [img|text|cond]
    proj_gemm3h<<<dim3(DIMN / 128, SEQN / 128, 1), 256>>>(
        O, O + (size_t)IMG_SEQ * DIMN,
        wo, wo_t, out,
        wo, wo_t, out,
        wo, wo_t, out,
        part, q_up, k_up, v_up,
        IMG_SEQ, DIMN, DIMN, 0, 1);

    // 6) post-projection LoRA on cond region of out (down -> fused-sum up)
    down_gemm_h<<<dim3(1, CONDN / 128, 8), 256>>>(out_cond,
                                                  p_down, p_down, p_down,
                                                  part, CONDN, 64, DIMN);
    up_sum_gemm_acc_h<<<dim3(DIMN / 128, CONDN / 128), 256>>>(part, p_up,
                                                              out_cond, DIMN);
}

// round 11
// speedup vs baseline: 10.0982x; 1.1409x over previous
#include <cuda_runtime.h>
#include <cuda_fp16.h>
#include <math.h>
#include <stdint.h>

// ---------------- problem constants ----------------
#define DIMN 2048
#define HEADS 16
#define HD 128
#define RANKN 64
#define IMG_SEQ 2048
#define TXT_SEQ 128
#define SEQN 2176          // IMG_SEQ + TXT_SEQ
#define CONDN 1024
#define BLOCKN 1024        // IMG_SEQ - COND
#define SBSN 1152          // SEQ - COND
#define EPSV 1e-5f

// ---------------- device scratch (no allocation allowed) ----------------
__device__ float g_Q[SEQN * DIMN];
__device__ float g_K[SEQN * DIMN];
__device__ float g_V[SEQN * DIMN];
__device__ float g_part[8 * CONDN * 192];
__device__ __half g_Ah[SEQN * DIMN];    // fp16 [img; txt] activations
__device__ __half g_Oh[SEQN * DIMN];    // fp16 attention output
__device__ __half g_Qh[SEQN * DIMN];
__device__ __half g_Kh[SEQN * DIMN];
__device__ __half g_Vth[DIMN * SEQN];   // per head: [d=128][seq] fp16

// ---------------- helpers ----------------
__device__ __forceinline__ uint32_t pack_h2(float x, float y) {
    __half2 h = __floats2half2_rn(x, y);
    return *(uint32_t*)&h;
}

__device__ __forceinline__ void mma_f16(float c[4], const uint32_t a[4],
                                        uint32_t b0, uint32_t b1) {
    asm volatile(
        "mma.sync.aligned.m16n8k16.row.col.f32.f16.f16.f32 "
        "{%0,%1,%2,%3}, {%4,%5,%6,%7}, {%8,%9}, {%0,%1,%2,%3};"
        : "+f"(c[0]), "+f"(c[1]), "+f"(c[2]), "+f"(c[3])
        : "r"(a[0]), "r"(a[1]), "r"(a[2]), "r"(a[3]),
          "r"(b0), "r"(b1));
}

__device__ __forceinline__ void ldsm4(uint32_t& r0, uint32_t& r1,
                                      uint32_t& r2, uint32_t& r3, uint32_t addr) {
    asm volatile("ldmatrix.sync.aligned.m8n8.x4.shared.b16 {%0,%1,%2,%3}, [%4];"
                 : "=r"(r0), "=r"(r1), "=r"(r2), "=r"(r3) : "r"(addr));
}

__device__ __forceinline__ void cp_async16(uint32_t dst_smem, const void* src) {
    asm volatile("cp.async.cg.shared.global [%0], [%1], 16;"
                 :: "r"(dst_smem), "l"(src));
}
__device__ __forceinline__ void cp_commit() {
    asm volatile("cp.async.commit_group;" ::: "memory");
}
template <int N>
__device__ __forceinline__ void cp_wait() {
    asm volatile("cp.async.wait_group %0;" :: "n"(N) : "memory");
}

#define HLD 40   // halves per smem row (20 words -> conflict-free ldmatrix)

// ---------------- fp32 -> fp16 streaming convert (img ++ txt) ---------------
__global__ __launch_bounds__(256) void tofp16_kernel(const float* __restrict__ a,
                                                     const float* __restrict__ b,
                                                     int na4, int tot4,
                                                     __half* __restrict__ dst) {
    int i = blockIdx.x * blockDim.x + threadIdx.x;
    if (i >= tot4) return;
    const float* src = (i < na4) ? &a[(size_t)i * 4] : &b[(size_t)(i - na4) * 4];
    float4 v = *(const float4*)src;
    *(uint2*)&dst[(size_t)i * 4] = make_uint2(pack_h2(v.x, v.y), pack_h2(v.z, v.w));
}

// ===== async fp16 projection GEMM + fused LoRA-up ============================
// C[remap(r)] = Ain[r] @ Wsel(r,z)^T  (+ LoRA-up for cond rows if lora!=0)
// Ain: fp16 [M,K]; W: fp32 (cp.async staged + converted). 128x128 tile, 8 warps.
#define PJ_AS0 0
#define PJ_AS1 10240
#define PJ_BS  20480
#define PJ_BST0 30720
#define PJ_BST1 47104
#define PJ_BYTES 63488

__global__ __launch_bounds__(256, 2) void proj_gemm3h(
    const __half* __restrict__ Ain,
    const float* __restrict__ Wa0, const float* __restrict__ Wb0, float* __restrict__ C0,
    const float* __restrict__ Wa1, const float* __restrict__ Wb1, float* __restrict__ C1,
    const float* __restrict__ Wa2, const float* __restrict__ Wb2, float* __restrict__ C2,
    const float* __restrict__ part,
    const float* __restrict__ up0, const float* __restrict__ up1,
    const float* __restrict__ up2,
    int Msplit, int N, int K, int lora, int remap) {
    extern __shared__ char smc[];
    const uint32_t sbase = (uint32_t)__cvta_generic_to_shared(smc);
    __half* Bs = (__half*)(smc + PJ_BS);
    const uint32_t bs_base = sbase + PJ_BS;

    const int tid = threadIdx.x;
    const int lane = tid & 31;
    const int warp = tid >> 5;
    const int wm = warp & 3;
    const int wn = warp >> 2;
    const int lrow = lane >> 2;
    const int lcol = lane & 3;
    const int row0 = blockIdx.y * 128;
    const int col0 = blockIdx.x * 128;
    const int z = blockIdx.z;

    const float* W;
    float* C;
    const float* up;
    if (z == 0)      { W = (row0 < Msplit) ? Wa0 : Wb0; C = C0; up = up0; }
    else if (z == 1) { W = (row0 < Msplit) ? Wa1 : Wb1; C = C1; up = up1; }
    else             { W = (row0 < Msplit) ? Wa2 : Wb2; C = C2; up = up2; }

    int row_out0 = row0;
    if (remap) {
        if (row0 >= IMG_SEQ)      row_out0 = row0 - CONDN;
        else if (row0 >= BLOCKN)  row_out0 = row0 + TXT_SEQ;
    }

    float c[2][8][4];
#pragma unroll
    for (int i = 0; i < 2; i++)
#pragma unroll
        for (int j = 0; j < 8; j++)
#pragma unroll
            for (int r = 0; r < 4; r++) c[i][j][r] = 0.f;

    // ldmatrix lane invariants
    const int al_row = wm * 32 + (lane & 15);
    const int al_k   = 8 * (lane >> 4);
    const int bl_tile = lane >> 4;
    const int bl_row  = lane & 7;
    const int bl_k    = 8 * ((lane >> 3) & 1);

    auto compute_block = [&](uint32_t a_base) {
#pragma unroll
        for (int ks = 0; ks < 2; ks++) {
            const int kb = ks * 16;
            uint32_t a[2][4];
#pragma unroll
            for (int mi = 0; mi < 2; mi++) {
                uint32_t addr = a_base +
                    (uint32_t)(((al_row + mi * 16) * HLD) + kb + al_k) * 2;
                ldsm4(a[mi][0], a[mi][1], a[mi][2], a[mi][3], addr);
            }
            uint32_t b[8][2];
#pragma unroll
            for (int j = 0; j < 4; j++) {
                int brow = wn * 64 + (2 * j + bl_tile) * 8 + bl_row;
                uint32_t addr = bs_base + (uint32_t)(brow * HLD + kb + bl_k) * 2;
                ldsm4(b[2 * j][0], b[2 * j][1], b[2 * j + 1][0], b[2 * j + 1][1], addr);
            }
#pragma unroll
            for (int mi = 0; mi < 2; mi++)
#pragma unroll
                for (int ni = 0; ni < 8; ni++)
                    mma_f16(c[mi][ni], a[mi], b[ni][0], b[ni][1]);
        }
    };

    // async tile issue: A fp16 (128x32 halves), W fp32 (128x32 floats staged)
    auto issue_tile = [&](int kt, int stg) {
        const int k0 = kt * 32;
        const __half* asrc = Ain + (size_t)row0 * K + k0;
        const uint32_t adst = sbase + (stg ? PJ_AS1 : PJ_AS0);
#pragma unroll
        for (int f = 0; f < 2; f++) {
            int id = tid + f * 256;       // 0..511
            int r = id >> 2;              // 0..127
            int cc = id & 3;              // 4 x 16B chunks per row
            cp_async16(adst + (uint32_t)(r * 80 + cc * 16),
                       asrc + (size_t)r * K + cc * 8);
        }
        const float* wsrc = W + (size_t)col0 * K + k0;
        const uint32_t bdst = sbase + (stg ? PJ_BST1 : PJ_BST0);
#pragma unroll
        for (int f = 0; f < 4; f++) {
            int id = tid + f * 256;       // 0..1023
            int r = id >> 3;              // 0..127
            int cc = id & 7;              // 8 x 16B chunks per row
            cp_async16(bdst + (uint32_t)(r * 128 + cc * 16),
                       wsrc + (size_t)r * K + cc * 4);
        }
        cp_commit();
    };

    // convert own staged W chunks to fp16 operand buffer (no barrier needed)
    auto convert_B = [&](int stg) {
        const float* bst = (const float*)(smc + (stg ? PJ_BST1 : PJ_BST0));
#pragma unroll
        for (int f = 0; f < 4; f++) {
            int id = tid + f * 256;
            int r = id >> 3;
            int kq = (id & 7) << 2;
            float4 v = *(const float4*)&bst[r * 32 + kq];
            *(uint2*)&Bs[r * HLD + kq] =
                make_uint2(pack_h2(v.x, v.y), pack_h2(v.z, v.w));
        }
    };

    const int iters = K / 32;
    issue_tile(0, 0);

    for (int it = 0; it < iters; it++) {
        const int stg = it & 1;
        if (it + 1 < iters) {
            issue_tile(it + 1, stg ^ 1);
            cp_wait<1>();
        } else {
            cp_wait<0>();
        }
        convert_B(stg);
        __syncthreads();
        compute_block(sbase + (stg ? PJ_AS1 : PJ_AS0));
        __syncthreads();
    }

    // ---- fused LoRA-up: 2 extra BK=32 iterations (K=64) for cond rows ----
    if (lora && row0 >= BLOCKN && row0 < IMG_SEQ) {
        __half* As0 = (__half*)(smc + PJ_AS0);
        const int arow0 = row0 - BLOCKN;
#pragma unroll
        for (int e = 0; e < 2; e++) {
            const int k0 = e * 32;
#pragma unroll
            for (int f = 0; f < 4; f++) {
                int id = tid + f * 256;
                int r = id >> 3;
                int kq = (id & 7) << 2;
                const float* pa = part + (size_t)(arow0 + r) * 192 + z * 64 + k0 + kq;
                float4 va = *(const float4*)pa;
#pragma unroll
                for (int s = 1; s < 8; s++) {
                    float4 t = *(const float4*)(pa + (size_t)s * CONDN * 192);
                    va.x += t.x; va.y += t.y; va.z += t.z; va.w += t.w;
                }
                *(uint2*)&As0[r * HLD + kq] =
                    make_uint2(pack_h2(va.x, va.y), pack_h2(va.z, va.w));
                float4 vb = *(const float4*)&up[(size_t)(col0 + r) * 64 + k0 + kq];
                *(uint2*)&Bs[r * HLD + kq] =
                    make_uint2(pack_h2(vb.x, vb.y), pack_h2(vb.z, vb.w));
            }
            __syncthreads();
            compute_block(sbase + PJ_AS0);
            __syncthreads();
        }
    }

#pragma unroll
    for (int mi = 0; mi < 2; mi++)
#pragma unroll
        for (int ni = 0; ni < 8; ni++) {
            int gr = row_out0 + wm * 32 + mi * 16 + lrow;
            int gc = col0 + wn * 64 + ni * 8 + lcol * 2;
            *(float2*)&C[(size_t)gr * N + gc] =
                make_float2(c[mi][ni][0], c[mi][ni][1]);
            *(float2*)&C[(size_t)(gr + 8) * N + gc] =
                make_float2(c[mi][ni][2], c[mi][ni][3]);
        }
}

// ===== fp16 LoRA up-projection with inline 8-way partial sum ================
__global__ __launch_bounds__(256) void up_sum_gemm_acc_h(
    const float* __restrict__ part,
    const float* __restrict__ W,
    float* __restrict__ C, int N) {
    __shared__ __half As[128 * HLD];
    __shared__ __half Bs[128 * HLD];

    const int tid = threadIdx.x;
    const int lane = tid & 31;
    const int warp = tid >> 5;
    const int wm = warp & 3;
    const int wn = warp >> 2;
    const int lrow = lane >> 2;
    const int lcol = lane & 3;
    const int row0 = blockIdx.y * 128;
    const int col0 = blockIdx.x * 128;

    float c[2][8][4];
#pragma unroll
    for (int i = 0; i < 2; i++)
#pragma unroll
        for (int j = 0; j < 8; j++)
#pragma unroll
            for (int r = 0; r < 4; r++) c[i][j][r] = 0.f;

    for (int k0 = 0; k0 < 64; k0 += 32) {
#pragma unroll
        for (int f = 0; f < 4; f++) {
            int id = tid + f * 256;
            int r = id >> 3;
            int kq = (id & 7) << 2;
            const float* pa = part + (size_t)(row0 + r) * 64 + k0 + kq;
            float4 va = *(const float4*)pa;
#pragma unroll
            for (int s = 1; s < 8; s++) {
                float4 t = *(const float4*)(pa + (size_t)s * CONDN * 64);
                va.x += t.x; va.y += t.y; va.z += t.z; va.w += t.w;
            }
            *(uint2*)&As[r * HLD + kq] =
                make_uint2(pack_h2(va.x, va.y), pack_h2(va.z, va.w));
            float4 vb = *(const float4*)&W[(size_t)(col0 + r) * 64 + k0 + kq];
            *(uint2*)&Bs[r * HLD + kq] =
                make_uint2(pack_h2(vb.x, vb.y), pack_h2(vb.z, vb.w));
        }
        __syncthreads();

#pragma unroll
        for (int ks = 0; ks < 2; ks++) {
            const int kb = ks * 16 + 2 * lcol;
            uint32_t a[2][4];
#pragma unroll
            for (int mi = 0; mi < 2; mi++) {
                int ar = wm * 32 + mi * 16 + lrow;
                a[mi][0] = *(const uint32_t*)&As[ar * HLD + kb];
                a[mi][1] = *(const uint32_t*)&As[(ar + 8) * HLD + kb];
                a[mi][2] = *(const uint32_t*)&As[ar * HLD + kb + 8];
                a[mi][3] = *(const uint32_t*)&As[(ar + 8) * HLD + kb + 8];
            }
            uint32_t b[8][2];
#pragma unroll
            for (int ni = 0; ni < 8; ni++) {
                int br = wn * 64 + ni * 8 + lrow;
                b[ni][0] = *(const uint32_t*)&Bs[br * HLD + kb];
                b[ni][1] = *(const uint32_t*)&Bs[br * HLD + kb + 8];
            }
#pragma unroll
            for (int mi = 0; mi < 2; mi++)
#pragma unroll
                for (int ni = 0; ni < 8; ni++)
                    mma_f16(c[mi][ni], a[mi], b[ni][0], b[ni][1]);
        }
        __syncthreads();
    }

#pragma unroll
    for (int mi = 0; mi < 2; mi++)
#pragma unroll
        for (int ni = 0; ni < 8; ni++) {
            int gr = row0 + wm * 32 + mi * 16 + lrow;
            int gc = col0 + wn * 64 + ni * 8 + lcol * 2;
            float2* p0 = (float2*)&C[(size_t)gr * N + gc];
            float2* p1 = (float2*)&C[(size_t)(gr + 8) * N + gc];
            float2 o0 = *p0, o1 = *p1;
            o0.x += c[mi][ni][0]; o0.y += c[mi][ni][1];
            o1.x += c[mi][ni][2]; o1.y += c[mi][ni][3];
            *p0 = o0; *p1 = o1;
        }
}

// ===== split-K LoRA down-projection, templated A type ========================
template <typename TA>
__global__ __launch_bounds__(256) void down_gemm_t(const TA* __restrict__ A,
                                                   const float* __restrict__ w0,
                                                   const float* __restrict__ w1,
                                                   const float* __restrict__ w2,
                                                   float* __restrict__ part,
                                                   int M, int Ntot, int Kfull) {
    __shared__ __half As[128 * HLD];
    __shared__ __half Ws[64 * HLD];

    const int cb = blockIdx.x, mb = blockIdx.y, sp = blockIdx.z;
    const int Kc = Kfull >> 3;
    const int kbase = sp * Kc;
    const float* W = (cb == 0) ? w0 : (cb == 1 ? w1 : w2);

    const int tid = threadIdx.x;
    const int lane = tid & 31;
    const int warp = tid >> 5;
    const int wm = warp & 3;
    const int wn = warp >> 2;
    const int lrow = lane >> 2;
    const int lcol = lane & 3;

    float c[2][4][4];
#pragma unroll
    for (int i = 0; i < 2; i++)
#pragma unroll
        for (int j = 0; j < 4; j++)
#pragma unroll
            for (int r = 0; r < 4; r++) c[i][j][r] = 0.f;

    for (int k0 = 0; k0 < Kc; k0 += 32) {
#pragma unroll
        for (int f = 0; f < 4; f++) {
            int id = tid + f * 256;
            int r = id >> 3;
            int kq = (id & 7) << 2;
            const TA* pa = &A[(size_t)(mb * 128 + r) * Kfull + kbase + k0 + kq];
            if (sizeof(TA) == 2) {
                *(uint2*)&As[r * HLD + kq] = *(const uint2*)pa;
            } else {
                float4 va = *(const float4*)pa;
                *(uint2*)&As[r * HLD + kq] =
                    make_uint2(pack_h2(va.x, va.y), pack_h2(va.z, va.w));
            }
        }
#pragma unroll
        for (int f = 0; f < 2; f++) {
            int id = tid + f * 256;
            int r = id >> 3;
            int kq = (id & 7) << 2;
            float4 vb = *(const float4*)&W[(size_t)r * Kfull + kbase + k0 + kq];
            *(uint2*)&Ws[r * HLD + kq] =
                make_uint2(pack_h2(vb.x, vb.y), pack_h2(vb.z, vb.w));
        }
        __syncthreads();

#pragma unroll
        for (int ks = 0; ks < 2; ks++) {
            const int kb = ks * 16 + 2 * lcol;
            uint32_t a[2][4];
#pragma unroll
            for (int mi = 0; mi < 2; mi++) {
                int ar = wm * 32 + mi * 16 + lrow;
                a[mi][0] = *(const uint32_t*)&As[ar * HLD + kb];
                a[mi][1] = *(const uint32_t*)&As[(ar + 8) * HLD + kb];
                a[mi][2] = *(const uint32_t*)&As[ar * HLD + kb + 8];
                a[mi][3] = *(const uint32_t*)&As[(ar + 8) * HLD + kb + 8];
            }
            uint32_t b[4][2];
#pragma unroll
            for (int ni = 0; ni < 4; ni++) {
                int br = wn * 32 + ni * 8 + lrow;
                b[ni][0] = *(const uint32_t*)&Ws[br * HLD + kb];
                b[ni][1] = *(const uint32_t*)&Ws[br * HLD + kb + 8];
            }
#pragma unroll
            for (int mi = 0; mi < 2; mi++)
#pragma unroll
                for (int ni = 0; ni < 4; ni++)
                    mma_f16(c[mi][ni], a[mi], b[ni][0], b[ni][1]);
        }
        __syncthreads();
    }

    float* basep = part + (size_t)sp * M * Ntot;
#pragma unroll
    for (int mi = 0; mi < 2; mi++)
#pragma unroll
        for (int ni = 0; ni < 4; ni++) {
            int gr = mb * 128 + wm * 32 + mi * 16 + lrow;
            int gc = cb * 64 + wn * 32 + ni * 8 + lcol * 2;
            *(float2*)&basep[(size_t)gr * Ntot + gc] =
                make_float2(c[mi][ni][0], c[mi][ni][1]);
            *(float2*)&basep[(size_t)(gr + 8) * Ntot + gc] =
                make_float2(c[mi][ni][2], c[mi][ni][3]);
        }
}

// ---------------- fused RMS + rope -> fp16 Qh (pre-scaled), Kh --------------
__global__ __launch_bounds__(256) void rmsrope_kernel(
    const float* __restrict__ Q, const float* __restrict__ K,
    __half* __restrict__ Qh, __half* __restrict__ Kh,
    const float* __restrict__ rope,
    const float* __restrict__ gq, const float* __restrict__ gk,
    const float* __restrict__ gqt, const float* __restrict__ gkt) {
    const int row = blockIdx.x;
    const int tid = threadIdx.x;
    __shared__ float sbuf[18];

    const float* qrow = Q + (size_t)row * DIMN;
    const float* krow = K + (size_t)row * DIMN;
    __half* qh = Qh + (size_t)row * DIMN;
    __half* kh = Kh + (size_t)row * DIMN;

    float sq = 0.f, sk = 0.f;
    for (int c4 = tid; c4 < DIMN / 4; c4 += 256) {
        float4 q = *(const float4*)&qrow[c4 * 4];
        sq += q.x * q.x + q.y * q.y + q.z * q.z + q.w * q.w;
        float4 kk = *(const float4*)&krow[c4 * 4];
        sk += kk.x * kk.x + kk.y * kk.y + kk.z * kk.z + kk.w * kk.w;
    }
#pragma unroll
    for (int o = 16; o > 0; o >>= 1) {
        sq += __shfl_xor_sync(0xffffffffu, sq, o);
        sk += __shfl_xor_sync(0xffffffffu, sk, o);
    }
    int w = tid >> 5;
    if ((tid & 31) == 0) { sbuf[w] = sq; sbuf[8 + w] = sk; }
    __syncthreads();
    if (tid == 0) {
        float a = 0.f, b = 0.f;
        for (int i = 0; i < 8; i++) { a += sbuf[i]; b += sbuf[8 + i]; }
        sbuf[16] = a; sbuf[17] = b;
    }
    __syncthreads();
    const float scale = 0.08838834764831844f;
    const float invq = rsqrtf(sbuf[16] / (float)DIMN + EPSV);
    const float invk = rsqrtf(sbuf[17] / (float)DIMN + EPSV);
    const float* gQ = (row < IMG_SEQ) ? gq : gqt;
    const float* gK = (row < IMG_SEQ) ? gk : gkt;
    const float* rp = rope + (size_t)row * 256;

    for (int pi = tid; pi < DIMN / 2; pi += 256) {
        int c0 = pi * 2;
        int j = pi & 63;
        float4 r = *(const float4*)&rp[j * 4];
        float x0 = qrow[c0] * invq * gQ[c0];
        float x1 = qrow[c0 + 1] * invq * gQ[c0 + 1];
        *(uint32_t*)&qh[c0] = pack_h2(scale * (r.x * x0 + r.y * x1),
                                      scale * (r.z * x0 + r.w * x1));
        float y0 = krow[c0] * invk * gK[c0];
        float y1 = krow[c0 + 1] * invk * gK[c0 + 1];
        *(uint32_t*)&kh[c0] = pack_h2(r.x * y0 + r.y * y1,
                                      r.z * y0 + r.w * y1);
    }
}

// ---------------- V transpose+convert: V[j][h*128+d] -> Vth[h][d][j] --------
__global__ __launch_bounds__(256) void vtrans_kernel(const float* __restrict__ V,
                                                     __half* __restrict__ Vth) {
    __shared__ float ts[64][65];
    const int jb = blockIdx.x * 64;
    const int db = blockIdx.y * 64;
    const int tid = threadIdx.x;
#pragma unroll
    for (int f = 0; f < 16; f++) {
        int idx = tid + f * 256;
        int j = idx >> 6, d = idx & 63;
        ts[j][d] = V[(size_t)(jb + j) * DIMN + db + d];
    }
    __syncthreads();
    const int head = db >> 7;
    const int dh = db & 127;
#pragma unroll
    for (int f = 0; f < 16; f++) {
        int idx = tid + f * 256;
        int d = idx >> 6, j = idx & 63;
        Vth[(size_t)head * 128 * SEQN + (size_t)(dh + d) * SEQN + jb + j] =
            __float2half_rn(ts[j][d]);
    }
}

// ---------------- flash attention: fp16 mma + cp.async + ldmatrix -----------
#define KLD 136
#define VLD 72
#define PLD 72
#define FB_KS0 0
#define FB_KS1 17408
#define FB_VT0 34816
#define FB_VT1 53248
#define FB_PS  71680
#define FB_BYTES 90112

__global__ __launch_bounds__(256) void flash_mma(const __half* __restrict__ Qh,
                                                 const __half* __restrict__ Kh,
                                                 const __half* __restrict__ Vth,
                                                 __half* __restrict__ Oh) {
    extern __shared__ char smc[];
    const uint32_t sbase = (uint32_t)__cvta_generic_to_shared(smc);
    __half* Ps = (__half*)(smc + FB_PS);
    const uint32_t ps_base = sbase + FB_PS;

    const int tid = threadIdx.x;
    const int lane = tid & 31;
    const int warp = tid >> 5;
    const int lrow = lane >> 2;
    const int lcol = lane & 3;
    const int qrow0 = blockIdx.x * 128;
    const int head = blockIdx.y;
    const size_t hoff = (size_t)head * HD;
    const __half* Vh = Vth + (size_t)head * 128 * SEQN;

    const int bl_tile = lane >> 4;
    const int bl_row  = lane & 7;
    const int bl_k    = 8 * ((lane >> 3) & 1);
    const int al_row  = lane & 15;
    const int al_k    = 8 * (lane >> 4);

    uint32_t qa[8][4];
    {
        const __half* qb = Qh + (size_t)(qrow0 + warp * 16) * DIMN + hoff;
#pragma unroll
        for (int ks = 0; ks < 8; ks++) {
            int kb = ks * 16 + 2 * lcol;
            qa[ks][0] = *(const uint32_t*)&qb[(size_t)lrow * DIMN + kb];
            qa[ks][1] = *(const uint32_t*)&qb[(size_t)(lrow + 8) * DIMN + kb];
            qa[ks][2] = *(const uint32_t*)&qb[(size_t)lrow * DIMN + kb + 8];
            qa[ks][3] = *(const uint32_t*)&qb[(size_t)(lrow + 8) * DIMN + kb + 8];
        }
    }

    float o[16][4];
#pragma unroll
    for (int ni = 0; ni < 16; ni++)
#pragma unroll
        for (int r = 0; r < 4; r++) o[ni][r] = 0.f;
    float m0 = -INFINITY, m1 = -INFINITY, l0 = 0.f, l1 = 0.f;

    const int kt0 = (qrow0 >= SBSN) ? (SBSN / 64) : 0;
    const int ktN = SEQN / 64;

    auto issue_tile = [&](int kt, int stg) {
        const int kr0 = kt * 64;
        const __half* ksrc = Kh + (size_t)kr0 * DIMN + hoff;
        const uint32_t kdst = sbase + (stg ? FB_KS1 : FB_KS0);
#pragma unroll
        for (int f = 0; f < 4; f++) {
            int id = tid + f * 256;
            int r = id >> 4;
            int cc = id & 15;
            cp_async16(kdst + (uint32_t)(r * KLD + cc * 8) * 2,
                       ksrc + (size_t)r * DIMN + cc * 8);
        }
        const __half* vsrc = Vh + kr0;
        const uint32_t vdst = sbase + (stg ? FB_VT1 : FB_VT0);
#pragma unroll
        for (int f = 0; f < 4; f++) {
            int id = tid + f * 256;
            int d = id >> 3;
            int cc = id & 7;
            cp_async16(vdst + (uint32_t)(d * VLD + cc * 8) * 2,
                       vsrc + (size_t)d * SEQN + cc * 8);
        }
        cp_commit();
    };

    issue_tile(kt0, kt0 & 1);

    for (int kt = kt0; kt < ktN; kt++) {
        const int stg = kt & 1;
        if (kt + 1 < ktN) {
            issue_tile(kt + 1, stg ^ 1);
            cp_wait<1>();
        } else {
            cp_wait<0>();
        }
        __syncthreads();
        const uint32_t ks_base = sbase + (stg ? FB_KS1 : FB_KS0);
        const uint32_t vt_base = sbase + (stg ? FB_VT1 : FB_VT0);

        float s[8][4];
#pragma unroll
        for (int ni = 0; ni < 8; ni++)
#pragma unroll
            for (int r = 0; r < 4; r++) s[ni][r] = 0.f;
#pragma unroll
        for (int ks = 0; ks < 8; ks++) {
            const int kb = ks * 16;
            uint32_t b[8][2];
#pragma unroll
            for (int j = 0; j < 4; j++) {
                int brow = (2 * j + bl_tile) * 8 + bl_row;
                uint32_t addr = ks_base + (uint32_t)(brow * KLD + kb + bl_k) * 2;
                ldsm4(b[2 * j][0], b[2 * j][1], b[2 * j + 1][0], b[2 * j + 1][1], addr);
            }
#pragma unroll
            for (int ni = 0; ni < 8; ni++)
                mma_f16(s[ni], qa[ks], b[ni][0], b[ni][1]);
        }

        float mt0 = -INFINITY, mt1 = -INFINITY;
#pragma unroll
        for (int ni = 0; ni < 8; ni++) {
            mt0 = fmaxf(mt0, fmaxf(s[ni][0], s[ni][1]));
            mt1 = fmaxf(mt1, fmaxf(s[ni][2], s[ni][3]));
        }
#pragma unroll
        for (int off = 1; off <= 2; off <<= 1) {
            mt0 = fmaxf(mt0, __shfl_xor_sync(0xffffffffu, mt0, off));
            mt1 = fmaxf(mt1, __shfl_xor_sync(0xffffffffu, mt1, off));
        }
        float mn0 = fmaxf(m0, mt0), mn1 = fmaxf(m1, mt1);
        float corr0 = __expf(m0 - mn0), corr1 = __expf(m1 - mn1);
        m0 = mn0; m1 = mn1;

        float ps0 = 0.f, ps1 = 0.f;
#pragma unroll
        for (int ni = 0; ni < 8; ni++) {
            __half2 h01 = __floats2half2_rn(__expf(s[ni][0] - mn0),
                                            __expf(s[ni][1] - mn0));
            __half2 h23 = __floats2half2_rn(__expf(s[ni][2] - mn1),
                                            __expf(s[ni][3] - mn1));
            ps0 += __low2float(h01) + __high2float(h01);
            ps1 += __low2float(h23) + __high2float(h23);
            int col = ni * 8 + 2 * lcol;
            *(uint32_t*)&Ps[(warp * 16 + lrow) * PLD + col] = *(uint32_t*)&h01;
            *(uint32_t*)&Ps[(warp * 16 + lrow + 8) * PLD + col] = *(uint32_t*)&h23;
        }
#pragma unroll
        for (int off = 1; off <= 2; off <<= 1) {
            ps0 += __shfl_xor_sync(0xffffffffu, ps0, off);
            ps1 += __shfl_xor_sync(0xffffffffu, ps1, off);
        }
        l0 = l0 * corr0 + ps0;
        l1 = l1 * corr1 + ps1;
#pragma unroll
        for (int ni = 0; ni < 16; ni++) {
            o[ni][0] *= corr0; o[ni][1] *= corr0;
            o[ni][2] *= corr1; o[ni][3] *= corr1;
        }
        __syncwarp();

#pragma unroll
        for (int ks = 0; ks < 4; ks++) {
            const int kb = ks * 16;
            uint32_t a[4];
            {
                uint32_t addr = ps_base +
                    (uint32_t)((warp * 16 + al_row) * PLD + kb + al_k) * 2;
                ldsm4(a[0], a[1], a[2], a[3], addr);
            }
#pragma unroll
            for (int j = 0; j < 8; j++) {
                int brow = (2 * j + bl_tile) * 8 + bl_row;
                uint32_t addr = vt_base + (uint32_t)(brow * VLD + kb + bl_k) * 2;
                uint32_t b0, b1, b2, b3;
                ldsm4(b0, b1, b2, b3, addr);
                mma_f16(o[2 * j], a, b0, b1);
                mma_f16(o[2 * j + 1], a, b2, b3);
            }
        }
        __syncthreads();
    }

    const float inv0 = 1.f / l0, inv1 = 1.f / l1;
    const int gr0 = qrow0 + warp * 16 + lrow;
#pragma unroll
    for (int ni = 0; ni < 16; ni++) {
        int gc = ni * 8 + lcol * 2;
        *(uint32_t*)&Oh[(size_t)gr0 * DIMN + hoff + gc] =
            pack_h2(o[ni][0] * inv0, o[ni][1] * inv0);
        *(uint32_t*)&Oh[(size_t)(gr0 + 8) * DIMN + hoff + gc] =
            pack_h2(o[ni][2] * inv1, o[ni][3] * inv1);
    }
}

// ---------------- launch ----------------
extern "C" void kernel_launch(void* const* d_in, const int* in_sizes, int n_in,
                              void* d_out, int out_size) {
    const float* img  = (const float*)d_in[0];
    const float* txt  = (const float*)d_in[1];
    const float* rope = (const float*)d_in[2];
    const float* wq   = (const float*)d_in[3];
    const float* wk   = (const float*)d_in[4];
    const float* wv   = (const float*)d_in[5];
    const float* wo   = (const float*)d_in[6];
    const float* wq_t = (const float*)d_in[7];
    const float* wk_t = (const float*)d_in[8];
    const float* wv_t = (const float*)d_in[9];
    const float* wo_t = (const float*)d_in[10];
    const float* gq   = (const float*)d_in[11];
    const float* gk   = (const float*)d_in[12];
    const float* gqt  = (const float*)d_in[13];
    const float* gkt  = (const float*)d_in[14];
    const float* q_down = (const float*)d_in[15];
    const float* q_up   = (const float*)d_in[16];
    const float* k_down = (const float*)d_in[17];
    const float* k_up   = (const float*)d_in[18];
    const float* v_down = (const float*)d_in[19];
    const float* v_up   = (const float*)d_in[20];
    const float* p_down = (const float*)d_in[21];
    const float* p_up   = (const float*)d_in[22];
    float* out = (float*)d_out;

    float *Q, *K, *V, *part;
    __half *Ah, *Oh, *Qh, *Kh, *Vth;
    cudaGetSymbolAddress((void**)&Q,    g_Q);
    cudaGetSymbolAddress((void**)&K,    g_K);
    cudaGetSymbolAddress((void**)&V,    g_V);
    cudaGetSymbolAddress((void**)&part, g_part);
    cudaGetSymbolAddress((void**)&Ah,   g_Ah);
    cudaGetSymbolAddress((void**)&Oh,   g_Oh);
    cudaGetSymbolAddress((void**)&Qh,   g_Qh);
    cudaGetSymbolAddress((void**)&Kh,   g_Kh);
    cudaGetSymbolAddress((void**)&Vth,  g_Vth);

    float* out_cond = out + (size_t)SBSN * DIMN;

    cudaFuncSetAttribute(proj_gemm3h, cudaFuncAttributeMaxDynamicSharedMemorySize,
                         PJ_BYTES);
    cudaFuncSetAttribute(flash_mma, cudaFuncAttributeMaxDynamicSharedMemorySize,
                         FB_BYTES);

    // 0) activations -> fp16 [img; txt]
    {
        int na4 = IMG_SEQ * DIMN / 4;
        int tot4 = SEQN * DIMN / 4;
        tofp16_kernel<<<(tot4 + 255) / 256, 256>>>(img, txt, na4, tot4, Ah);
    }

    // 1) fused LoRA down-projections (q/k/v), split-K 8-way -> partials
    down_gemm_t<__half><<<dim3(3, CONDN / 128, 8), 256>>>(
        Ah + (size_t)BLOCKN * DIMN, q_down, k_down, v_down,
        part, CONDN, 192, DIMN);

    // 2) QKV projections in ONE launch, LoRA-up FUSED into cond-row epilogue
    proj_gemm3h<<<dim3(DIMN / 128, SEQN / 128, 3), 256, PJ_BYTES>>>(
        Ah,
        wq, wq_t, Q,
        wk, wk_t, K,
        wv, wv_t, V,
        part, q_up, k_up, v_up,
        IMG_SEQ, DIMN, DIMN, 1, 0);

    // 3) RMS + rope -> fp16 Qh (pre-scaled), Kh ; V -> transposed fp16 Vth
    rmsrope_kernel<<<SEQN, 256>>>(Q, K, Qh, Kh, rope, gq, gk, gqt, gkt);
    vtrans_kernel<<<dim3(SEQN / 64, DIMN / 64), 256>>>(V, Vth);

    // 4) flash attention -> fp16 Oh
    flash_mma<<<dim3(SEQN / 128, HEADS), 256, FB_BYTES>>>(Qh, Kh, Vth, Oh);

    // 5) output projection, written DIRECTLY in output layout [img|text|cond]
    proj_gemm3h<<<dim3(DIMN / 128, SEQN / 128, 1), 256, PJ_BYTES>>>(
        Oh,
        wo, wo_t, out,
        wo, wo_t, out,
        wo, wo_t, out,
        part, q_up, k_up, v_up,
        IMG_SEQ, DIMN, DIMN, 0, 1);

    // 6) post-projection LoRA on cond region of out (down -> fused-sum up)
    down_gemm_t<float><<<dim3(1, CONDN / 128, 8), 256>>>(
        out_cond, p_down, p_down, p_down, part, CONDN, 64, DIMN);
    up_sum_gemm_acc_h<<<dim3(DIMN / 128, CONDN / 128), 256>>>(part, p_up,
                                                              out_cond, DIMN);
}